// round 6
// baseline (speedup 1.0000x reference)
#include <cuda_runtime.h>
#include <cuda_bf16.h>
#include <cstdint>
#include <math.h>

#define NN 50000
#define EE 400000
#define ETOT (EE + NN)
#define DD 256
#define HEADS 4
#define HIDC 64
#define GG 64
#define NEG_SLOPE 0.2f

// ---------------- static device scratch ----------------
__device__ __nv_bfloat162 g_hb[NN * 128];   // GEMM output h as bf16 pairs
__device__ float g_o[NN * DD];              // post agg+LN features (layer 2)
__device__ __nv_bfloat16 g_ahi[NN * DD];
__device__ __nv_bfloat16 g_alo[NN * DD];
__device__ __nv_bfloat16 g_w1hi[DD * DD], g_w1lo[DD * DD];
__device__ __nv_bfloat16 g_w2hi[DD * DD], g_w2lo[DD * DD];
__device__ float g_asrc[NN * HEADS];
__device__ float g_adst[NN * HEADS];
__device__ int   g_deg[NN];
__device__ int   g_rowptr[NN + 1];
__device__ int   g_cursor[NN];
__device__ int   g_csrsrc[ETOT];
__device__ int   g_gstart[GG + 1];
__device__ float g_pooled[GG * DD];
#define SNB 98
__device__ int   g_bsum[SNB];
__device__ int   g_boff[SNB];

// ---------------- helpers ----------------
__device__ __forceinline__ uint32_t su32(const void* p) {
    uint32_t a;
    asm("{ .reg .u64 t; cvta.to.shared.u64 t, %1; cvt.u32.u64 %0, t; }" : "=r"(a) : "l"(p));
    return a;
}
__device__ __forceinline__ uint32_t swz(uint32_t off) {
    return off ^ ((off >> 3) & 0x70);
}
__device__ __forceinline__ void ldsm_x4(uint32_t* r, uint32_t addr) {
    asm volatile("ldmatrix.sync.aligned.m8n8.x4.shared.b16 {%0,%1,%2,%3}, [%4];"
                 : "=r"(r[0]), "=r"(r[1]), "=r"(r[2]), "=r"(r[3]) : "r"(addr));
}
__device__ __forceinline__ void mma_bf16(float* c, const uint32_t* a, const uint32_t* b) {
    asm volatile("mma.sync.aligned.m16n8k16.row.col.f32.bf16.bf16.f32 "
                 "{%0,%1,%2,%3}, {%4,%5,%6,%7}, {%8,%9}, {%0,%1,%2,%3};"
                 : "+f"(c[0]), "+f"(c[1]), "+f"(c[2]), "+f"(c[3])
                 : "r"(a[0]), "r"(a[1]), "r"(a[2]), "r"(a[3]), "r"(b[0]), "r"(b[1]));
}
__device__ __forceinline__ void cp16(uint32_t dst, const void* src, uint32_t sz) {
    asm volatile("cp.async.cg.shared.global [%0], [%1], 16, %2;" :: "r"(dst), "l"(src), "r"(sz));
}
__device__ __forceinline__ void cp16f(uint32_t dst, const void* src) {
    asm volatile("cp.async.cg.shared.global [%0], [%1], 16;" :: "r"(dst), "l"(src));
}
#define CP_COMMIT() asm volatile("cp.async.commit_group;" ::: "memory")
#define CP_WAIT(n)  asm volatile("cp.async.wait_group %0;" :: "n"(n) : "memory")

// ---------------- CSR build ----------------
__global__ void k_zero_deg() {
    int i = blockIdx.x * blockDim.x + threadIdx.x;
    if (i < NN) g_deg[i] = 0;
}
__global__ void k_hist_edges(const int* __restrict__ ei) {
    int i = blockIdx.x * blockDim.x + threadIdx.x;
    if (i < EE) atomicAdd(&g_deg[ei[EE + i]], 1);
    else if (i < ETOT) atomicAdd(&g_deg[i - EE], 1);
}
__global__ void k_scan_part() {
    __shared__ int sh[512];
    int i = blockIdx.x * 512 + threadIdx.x;
    int v = (i < NN) ? g_deg[i] : 0;
    sh[threadIdx.x] = v;
    __syncthreads();
    #pragma unroll
    for (int off = 1; off < 512; off <<= 1) {
        int t = (threadIdx.x >= off) ? sh[threadIdx.x - off] : 0;
        __syncthreads();
        sh[threadIdx.x] += t;
        __syncthreads();
    }
    if (i < NN) g_rowptr[i] = sh[threadIdx.x] - v;
    if (threadIdx.x == 511) g_bsum[blockIdx.x] = sh[511];
}
__global__ void k_scan_boff() {
    int c = 0;
    for (int b = 0; b < SNB; b++) { g_boff[b] = c; c += g_bsum[b]; }
}
__global__ void k_scan_add() {
    int i = blockIdx.x * blockDim.x + threadIdx.x;
    if (i < NN) {
        int val = g_rowptr[i] + g_boff[i >> 9];
        g_rowptr[i] = val;
        g_cursor[i] = val;
    }
    if (i == 0) g_rowptr[NN] = ETOT;
}
__global__ void k_scatter_edges(const int* __restrict__ ei) {
    int i = blockIdx.x * blockDim.x + threadIdx.x;
    int src, dst;
    if (i < EE)        { src = ei[i]; dst = ei[EE + i]; }
    else if (i < ETOT) { src = i - EE; dst = i - EE; }
    else return;
    int pos = atomicAdd(&g_cursor[dst], 1);
    g_csrsrc[pos] = src;
}
// sorted batch -> graph boundary detection (no atomics, no scan)
__global__ void k_gbounds(const int* __restrict__ batch) {
    int i = blockIdx.x * blockDim.x + threadIdx.x;
    if (i >= NN) return;
    int b = batch[i];
    int prev = (i == 0) ? -1 : batch[i - 1];
    for (int g = prev + 1; g <= b; g++) g_gstart[g] = i;
    if (i == NN - 1)
        for (int g = b + 1; g <= GG; g++) g_gstart[g] = NN;
}

// ---------------- fp32 -> bf16 hi/lo splits ----------------
__global__ void k_split_x(const float* __restrict__ x,
                          __nv_bfloat16* __restrict__ hi, __nv_bfloat16* __restrict__ lo) {
    int i = blockIdx.x * 256 + threadIdx.x;
    float v = x[i];
    __nv_bfloat16 h = __float2bfloat16(v);
    hi[i] = h;
    lo[i] = __float2bfloat16(v - __bfloat162float(h));
}
// both weight matrices, transposed + split, one launch
__global__ void k_split_w(const float* __restrict__ W1, const float* __restrict__ W2) {
    int i = blockIdx.x * 256 + threadIdx.x;   // 0..131071
    int which = i >> 16;
    int j = i & 65535;
    int n = j >> 8, k = j & 255;
    const float* W = which ? W2 : W1;
    float v = W[k * 256 + n];
    __nv_bfloat16 h = __float2bfloat16(v);
    float r = v - __bfloat162float(h);
    if (which) { g_w2hi[j] = h; g_w2lo[j] = __float2bfloat16(r); }
    else       { g_w1hi[j] = h; g_w1lo[j] = __float2bfloat16(r); }
}

// ---------------- GEMM: h[M,256] = A @ Wt^T  (bf16 out) + fused att-coef epilogue ----------------
#define STG   98304
#define OA_HI 0
#define OA_LO 16384
#define OB_HI 32768
#define OB_LO 65536
#define SMEM_TOT (2 * STG)

__global__ void __launch_bounds__(256) k_gemm_att(
    const __nv_bfloat16* __restrict__ Ahi, const __nv_bfloat16* __restrict__ Alo,
    const __nv_bfloat16* __restrict__ Bhi, const __nv_bfloat16* __restrict__ Blo,
    __nv_bfloat162* __restrict__ Hout,
    const float* __restrict__ as, const float* __restrict__ ad,
    int M)
{
    extern __shared__ char smem[];
    uint32_t sb = su32(smem);
    const int tid = threadIdx.x, wid = tid >> 5, lane = tid & 31;
    const int row0 = blockIdx.x * 128;
    const int wm = wid & 3;
    const int wn = wid >> 2;

    float acc[2][16][4];
    #pragma unroll
    for (int a = 0; a < 2; a++)
        #pragma unroll
        for (int b = 0; b < 16; b++)
            #pragma unroll
            for (int q = 0; q < 4; q++) acc[a][b][q] = 0.f;

    auto load_chunk = [&](int c, int stage) {
        uint32_t base = sb + stage * STG;
        #pragma unroll
        for (int it = 0; it < 4; it++) {
            int u = tid + it * 256;
            int r = u >> 3, j = u & 7;
            uint32_t sw = swz(r * 128 + j * 16);
            int m = row0 + r;
            int mc = m < M ? m : (M - 1);
            uint32_t sz = (m < M) ? 16u : 0u;
            size_t gi = (size_t)mc * 256 + c * 64 + j * 8;
            cp16(base + OA_HI + sw, Ahi + gi, sz);
            cp16(base + OA_LO + sw, Alo + gi, sz);
        }
        #pragma unroll
        for (int it = 0; it < 8; it++) {
            int u = tid + it * 256;
            int r = u >> 3, j = u & 7;
            uint32_t sw = swz(r * 128 + j * 16);
            size_t gi = (size_t)r * 256 + c * 64 + j * 8;
            cp16f(base + OB_HI + sw, Bhi + gi);
            cp16f(base + OB_LO + sw, Blo + gi);
        }
    };

    load_chunk(0, 0);
    CP_COMMIT();

    const int lrow = lane & 15;
    const int lcol = (lane >> 4) * 8;
    const int cb = wn * 128;

    for (int c = 0; c < 4; c++) {
        int stage = c & 1;
        if (c < 3) { load_chunk(c + 1, stage ^ 1); CP_COMMIT(); CP_WAIT(1); }
        else       { CP_WAIT(0); }
        __syncthreads();
        uint32_t base = sb + stage * STG;

        #pragma unroll
        for (int kk = 0; kk < 4; kk++) {
            uint32_t ah[2][4], al[2][4];
            #pragma unroll
            for (int mt = 0; mt < 2; mt++) {
                uint32_t off = swz((wm * 32 + mt * 16 + lrow) * 128 + (kk * 16 + lcol) * 2);
                ldsm_x4(ah[mt], base + OA_HI + off);
                ldsm_x4(al[mt], base + OA_LO + off);
            }
            #pragma unroll
            for (int ntp = 0; ntp < 8; ntp++) {
                int q = lane >> 3;
                int nrow = cb + ntp * 16 + (q >> 1) * 8 + (lane & 7);
                int kcol = kk * 16 + (q & 1) * 8;
                uint32_t boff = swz(nrow * 128 + kcol * 2);
                uint32_t bh[4], bl[4];
                ldsm_x4(bh, base + OB_HI + boff);
                ldsm_x4(bl, base + OB_LO + boff);
                #pragma unroll
                for (int sub = 0; sub < 2; sub++) {
                    int nt = ntp * 2 + sub;
                    #pragma unroll
                    for (int mt = 0; mt < 2; mt++) {
                        mma_bf16(acc[mt][nt], ah[mt], bh + sub * 2);
                        mma_bf16(acc[mt][nt], ah[mt], bl + sub * 2);
                        mma_bf16(acc[mt][nt], al[mt], bh + sub * 2);
                    }
                }
            }
        }
        __syncthreads();
    }

    // ---- epilogue: attention coefficients (fp32) + bf16 h store ----
    float sa[4][2], sd[4][2];
    #pragma unroll
    for (int i = 0; i < 4; i++) { sa[i][0] = sa[i][1] = 0.f; sd[i][0] = sd[i][1] = 0.f; }

    #pragma unroll
    for (int nt = 0; nt < 16; nt++) {
        int c0 = cb + nt * 8 + (lane & 3) * 2;
        float w0 = __ldg(as + c0), w1 = __ldg(as + c0 + 1);
        float v0 = __ldg(ad + c0), v1 = __ldg(ad + c0 + 1);
        int hl = nt >> 3;
        #pragma unroll
        for (int mt = 0; mt < 2; mt++) {
            sa[mt * 2 + 0][hl] += acc[mt][nt][0] * w0 + acc[mt][nt][1] * w1;
            sa[mt * 2 + 1][hl] += acc[mt][nt][2] * w0 + acc[mt][nt][3] * w1;
            sd[mt * 2 + 0][hl] += acc[mt][nt][0] * v0 + acc[mt][nt][1] * v1;
            sd[mt * 2 + 1][hl] += acc[mt][nt][2] * v0 + acc[mt][nt][3] * v1;
        }
    }
    #pragma unroll
    for (int i = 0; i < 4; i++)
        #pragma unroll
        for (int hl = 0; hl < 2; hl++) {
            sa[i][hl] += __shfl_xor_sync(0xffffffff, sa[i][hl], 1);
            sa[i][hl] += __shfl_xor_sync(0xffffffff, sa[i][hl], 2);
            sd[i][hl] += __shfl_xor_sync(0xffffffff, sd[i][hl], 1);
            sd[i][hl] += __shfl_xor_sync(0xffffffff, sd[i][hl], 2);
        }
    if ((lane & 3) == 0) {
        #pragma unroll
        for (int mt = 0; mt < 2; mt++)
            #pragma unroll
            for (int rh = 0; rh < 2; rh++) {
                int r = row0 + wm * 32 + mt * 16 + (lane >> 2) + rh * 8;
                if (r < M) {
                    #pragma unroll
                    for (int hl = 0; hl < 2; hl++) {
                        g_asrc[r * 4 + wn * 2 + hl] = sa[mt * 2 + rh][hl];
                        g_adst[r * 4 + wn * 2 + hl] = sd[mt * 2 + rh][hl];
                    }
                }
            }
    }

    #pragma unroll
    for (int mt = 0; mt < 2; mt++) {
        int r0 = row0 + wm * 32 + mt * 16 + (lane >> 2);
        int r1 = r0 + 8;
        #pragma unroll
        for (int nt = 0; nt < 16; nt++) {
            int cc2 = (cb >> 1) + nt * 4 + (lane & 3);
            if (r0 < M) Hout[(size_t)r0 * 128 + cc2] = __floats2bfloat162_rn(acc[mt][nt][0], acc[mt][nt][1]);
            if (r1 < M) Hout[(size_t)r1 * 128 + cc2] = __floats2bfloat162_rn(acc[mt][nt][2], acc[mt][nt][3]);
        }
    }
}

// ---------------- fused GAT aggregation (bf16 gather, 4-way ILP) + bias + LN + ReLU ----------------
__global__ void __launch_bounds__(128) k_agg_ln(
    const __nv_bfloat162* __restrict__ hb, const float* __restrict__ bias,
    const float* __restrict__ gamma, const float* __restrict__ beta,
    float* __restrict__ outf, __nv_bfloat162* __restrict__ ohi, __nv_bfloat162* __restrict__ olo)
{
    int n = blockIdx.x;
    int t = threadIdx.x >> 5, lane = threadIdx.x & 31;
    __shared__ float red[8];
    int beg = g_rowptr[n], end = g_rowptr[n + 1];
    float adst = g_adst[n * HEADS + t];

    float acc0 = 0.f, acc1 = 0.f, den = 0.f;
    const __nv_bfloat162* hp = hb + t * 32 + lane;
    int k = beg;
    for (; k + 3 < end; k += 4) {
        // batch indices first (broadcast loads), then 8 independent gathers
        int s0 = __ldg(g_csrsrc + k),     s1 = __ldg(g_csrsrc + k + 1);
        int s2 = __ldg(g_csrsrc + k + 2), s3 = __ldg(g_csrsrc + k + 3);
        float e0 = __ldg(g_asrc + s0 * HEADS + t);
        float e1 = __ldg(g_asrc + s1 * HEADS + t);
        float e2 = __ldg(g_asrc + s2 * HEADS + t);
        float e3 = __ldg(g_asrc + s3 * HEADS + t);
        __nv_bfloat162 v0 = __ldg(hp + (size_t)s0 * 128);
        __nv_bfloat162 v1 = __ldg(hp + (size_t)s1 * 128);
        __nv_bfloat162 v2 = __ldg(hp + (size_t)s2 * 128);
        __nv_bfloat162 v3 = __ldg(hp + (size_t)s3 * 128);
        e0 += adst; e1 += adst; e2 += adst; e3 += adst;
        e0 = (e0 > 0.f) ? e0 : NEG_SLOPE * e0;
        e1 = (e1 > 0.f) ? e1 : NEG_SLOPE * e1;
        e2 = (e2 > 0.f) ? e2 : NEG_SLOPE * e2;
        e3 = (e3 > 0.f) ? e3 : NEG_SLOPE * e3;
        float w0 = __expf(e0), w1 = __expf(e1), w2 = __expf(e2), w3 = __expf(e3);
        float2 f0 = __bfloat1622float2(v0);
        float2 f1 = __bfloat1622float2(v1);
        float2 f2 = __bfloat1622float2(v2);
        float2 f3 = __bfloat1622float2(v3);
        den += (w0 + w1) + (w2 + w3);
        acc0 = fmaf(w0, f0.x, fmaf(w1, f1.x, fmaf(w2, f2.x, fmaf(w3, f3.x, acc0))));
        acc1 = fmaf(w0, f0.y, fmaf(w1, f1.y, fmaf(w2, f2.y, fmaf(w3, f3.y, acc1))));
    }
    for (; k < end; k++) {
        int s0 = __ldg(g_csrsrc + k);
        float e0 = __ldg(g_asrc + s0 * HEADS + t) + adst;
        __nv_bfloat162 v0 = __ldg(hp + (size_t)s0 * 128);
        e0 = (e0 > 0.f) ? e0 : NEG_SLOPE * e0;
        float w0 = __expf(e0);
        float2 f0 = __bfloat1622float2(v0);
        den += w0;
        acc0 = fmaf(w0, f0.x, acc0);
        acc1 = fmaf(w0, f0.y, acc1);
    }
    float inv = 1.0f / den;
    int c0 = 2 * threadIdx.x, c1 = c0 + 1;
    float m0 = acc0 * inv + bias[c0];
    float m1 = acc1 * inv + bias[c1];

    float s = m0 + m1;
    #pragma unroll
    for (int off = 16; off > 0; off >>= 1) s += __shfl_xor_sync(0xffffffff, s, off);
    if (lane == 0) red[t] = s;
    __syncthreads();
    float mu = (red[0] + red[1] + red[2] + red[3]) * (1.0f / 256.0f);
    float d0 = m0 - mu, d1 = m1 - mu;
    float q = d0 * d0 + d1 * d1;
    #pragma unroll
    for (int off = 16; off > 0; off >>= 1) q += __shfl_xor_sync(0xffffffff, q, off);
    if (lane == 0) red[4 + t] = q;
    __syncthreads();
    float invs = rsqrtf((red[4] + red[5] + red[6] + red[7]) * (1.0f / 256.0f) + 1e-5f);

    float y0 = fmaxf(d0 * invs * gamma[c0] + beta[c0], 0.f);
    float y1 = fmaxf(d1 * invs * gamma[c1] + beta[c1], 0.f);
    size_t o = (size_t)n * 128 + threadIdx.x;
    if (outf) {
        *(float2*)(outf + 2 * o) = make_float2(y0, y1);
    }
    if (ohi) {
        __nv_bfloat16 h0 = __float2bfloat16(y0);
        __nv_bfloat16 h1 = __float2bfloat16(y1);
        ohi[o] = __nv_bfloat162(h0, h1);
        olo[o] = __nv_bfloat162(__float2bfloat16(y0 - __bfloat162float(h0)),
                                __float2bfloat16(y1 - __bfloat162float(h1)));
    }
}

// ---------------- global mean pool (float2) ----------------
__global__ void k_pool(const float* __restrict__ h) {
    int g = blockIdx.x;
    int col2 = threadIdx.x;   // 128 float2 columns
    int s = g_gstart[g], e = g_gstart[g + 1];
    float sum0 = 0.f, sum1 = 0.f;
    const float2* p = (const float2*)h + col2;
    for (int i = s; i < e; i++) {
        float2 v = __ldg(p + (size_t)i * 128);
        sum0 += v.x; sum1 += v.y;
    }
    float invc = 1.0f / (float)max(e - s, 1);
    g_pooled[g * DD + 2 * col2]     = sum0 * invc;
    g_pooled[g * DD + 2 * col2 + 1] = sum1 * invc;
}

// ---------------- final MLP ----------------
__global__ void k_mlp(const float* __restrict__ lw1, const float* __restrict__ lb1,
                      const float* __restrict__ lw2, const float* __restrict__ lb2,
                      float* __restrict__ out) {
    __shared__ float p[DD];
    __shared__ float hid[HIDC];
    int g = blockIdx.x, tid = threadIdx.x;
    for (int i = tid; i < DD; i += 64) p[i] = g_pooled[g * DD + i];
    __syncthreads();
    float s = lb1[tid];
    #pragma unroll 8
    for (int k = 0; k < DD; k++) s = fmaf(p[k], lw1[k * HIDC + tid], s);
    hid[tid] = fmaxf(s, 0.f);
    __syncthreads();
    if (tid < 2) {
        float o = lb2[tid];
        #pragma unroll
        for (int k = 0; k < HIDC; k++) o = fmaf(hid[k], lw2[k * 2 + tid], o);
        out[g * 2 + tid] = o;
    }
}

// ---------------- host launcher ----------------
extern "C" void kernel_launch(void* const* d_in, const int* in_sizes, int n_in,
                              void* d_out, int out_size) {
    const float* x   = (const float*)d_in[0];
    const int*   ei  = (const int*)d_in[1];
    const int*   bat = (const int*)d_in[2];
    const float* W1  = (const float*)d_in[3];
    const float* as1 = (const float*)d_in[4];
    const float* ad1 = (const float*)d_in[5];
    const float* b1  = (const float*)d_in[6];
    const float* g1  = (const float*)d_in[7];
    const float* be1 = (const float*)d_in[8];
    const float* W2  = (const float*)d_in[9];
    const float* as2 = (const float*)d_in[10];
    const float* ad2 = (const float*)d_in[11];
    const float* b2  = (const float*)d_in[12];
    const float* g2  = (const float*)d_in[13];
    const float* be2 = (const float*)d_in[14];
    const float* lw1 = (const float*)d_in[15];
    const float* lb1 = (const float*)d_in[16];
    const float* lw2 = (const float*)d_in[17];
    const float* lb2 = (const float*)d_in[18];
    float* out = (float*)d_out;

    cudaFuncSetAttribute(k_gemm_att, cudaFuncAttributeMaxDynamicSharedMemorySize, SMEM_TOT);

    float *bo;
    __nv_bfloat162 *hb;
    __nv_bfloat16 *ahi, *alo, *w1h, *w1l, *w2h, *w2l;
    cudaGetSymbolAddress((void**)&hb, g_hb);
    cudaGetSymbolAddress((void**)&bo, g_o);
    cudaGetSymbolAddress((void**)&ahi, g_ahi);
    cudaGetSymbolAddress((void**)&alo, g_alo);
    cudaGetSymbolAddress((void**)&w1h, g_w1hi);
    cudaGetSymbolAddress((void**)&w1l, g_w1lo);
    cudaGetSymbolAddress((void**)&w2h, g_w2hi);
    cudaGetSymbolAddress((void**)&w2l, g_w2lo);

    // CSR + batch ranges + splits
    k_zero_deg<<<(NN + 255) / 256, 256>>>();
    k_hist_edges<<<(ETOT + 255) / 256, 256>>>(ei);
    k_scan_part<<<SNB, 512>>>();
    k_scan_boff<<<1, 1>>>();
    k_scan_add<<<(NN + 255) / 256, 256>>>();
    k_scatter_edges<<<(ETOT + 255) / 256, 256>>>(ei);
    k_gbounds<<<(NN + 255) / 256, 256>>>(bat);
    k_split_x<<<NN * DD / 256, 256>>>(x, ahi, alo);
    k_split_w<<<2 * DD * DD / 256, 256>>>(W1, W2);

    int gemm_blocks = (NN + 127) / 128;

    // ---- layer 1 ----
    k_gemm_att<<<gemm_blocks, 256, SMEM_TOT>>>(ahi, alo, w1h, w1l, hb, as1, ad1, NN);
    k_agg_ln<<<NN, 128>>>(hb, b1, g1, be1, nullptr, (__nv_bfloat162*)ahi, (__nv_bfloat162*)alo);

    // ---- layer 2 ----
    k_gemm_att<<<gemm_blocks, 256, SMEM_TOT>>>(ahi, alo, w2h, w2l, hb, as2, ad2, NN);
    k_agg_ln<<<NN, 128>>>(hb, b2, g2, be2, bo, nullptr, nullptr);

    // ---- pool + MLP ----
    k_pool<<<GG, 128>>>(bo);
    k_mlp<<<GG, 64>>>(lw1, lb1, lw2, lb2, out);
}

// round 7
// speedup vs baseline: 1.0092x; 1.0092x over previous
#include <cuda_runtime.h>
#include <cuda_bf16.h>
#include <cstdint>
#include <math.h>

#define NN 50000
#define EE 400000
#define ETOT (EE + NN)
#define DD 256
#define HEADS 4
#define HIDC 64
#define GG 64
#define NEG_SLOPE 0.2f

// ---------------- static device scratch ----------------
__device__ __nv_bfloat162 g_hb[NN * 128];
__device__ float g_o[NN * DD];
__device__ __nv_bfloat16 g_ahi[NN * DD];
__device__ __nv_bfloat16 g_alo[NN * DD];
__device__ __nv_bfloat16 g_w1hi[DD * DD], g_w1lo[DD * DD];
__device__ __nv_bfloat16 g_w2hi[DD * DD], g_w2lo[DD * DD];
__device__ float g_asrc[NN * HEADS];
__device__ float g_adst[NN * HEADS];
__device__ int   g_deg[NN];
__device__ int   g_rowptr[NN + 1];
__device__ int   g_cursor[NN];
__device__ int   g_csrsrc[ETOT];
__device__ int   g_gstart[GG + 1];
__device__ float g_pooled[GG * DD];
#define SNB 98
__device__ int   g_bsum[SNB];
__device__ int   g_boff[SNB];

// ---------------- helpers ----------------
__device__ __forceinline__ uint32_t su32(const void* p) {
    uint32_t a;
    asm("{ .reg .u64 t; cvta.to.shared.u64 t, %1; cvt.u32.u64 %0, t; }" : "=r"(a) : "l"(p));
    return a;
}
__device__ __forceinline__ uint32_t swz(uint32_t off) {
    return off ^ ((off >> 3) & 0x70);
}
__device__ __forceinline__ void ldsm_x4(uint32_t* r, uint32_t addr) {
    asm volatile("ldmatrix.sync.aligned.m8n8.x4.shared.b16 {%0,%1,%2,%3}, [%4];"
                 : "=r"(r[0]), "=r"(r[1]), "=r"(r[2]), "=r"(r[3]) : "r"(addr));
}
__device__ __forceinline__ void mma_bf16(float* c, const uint32_t* a, const uint32_t* b) {
    asm volatile("mma.sync.aligned.m16n8k16.row.col.f32.bf16.bf16.f32 "
                 "{%0,%1,%2,%3}, {%4,%5,%6,%7}, {%8,%9}, {%0,%1,%2,%3};"
                 : "+f"(c[0]), "+f"(c[1]), "+f"(c[2]), "+f"(c[3])
                 : "r"(a[0]), "r"(a[1]), "r"(a[2]), "r"(a[3]), "r"(b[0]), "r"(b[1]));
}
__device__ __forceinline__ void cp16(uint32_t dst, const void* src, uint32_t sz) {
    asm volatile("cp.async.cg.shared.global [%0], [%1], 16, %2;" :: "r"(dst), "l"(src), "r"(sz));
}
__device__ __forceinline__ void cp16f(uint32_t dst, const void* src) {
    asm volatile("cp.async.cg.shared.global [%0], [%1], 16;" :: "r"(dst), "l"(src));
}
#define CP_COMMIT() asm volatile("cp.async.commit_group;" ::: "memory")
#define CP_WAIT(n)  asm volatile("cp.async.wait_group %0;" :: "n"(n) : "memory")

// ---------------- CSR build ----------------
__global__ void k_zero_deg() {
    int i = blockIdx.x * blockDim.x + threadIdx.x;
    if (i < NN) g_deg[i] = 0;
}
__global__ void k_hist_edges(const int* __restrict__ ei) {
    int i = blockIdx.x * blockDim.x + threadIdx.x;
    if (i < EE) atomicAdd(&g_deg[ei[EE + i]], 1);
    else if (i < ETOT) atomicAdd(&g_deg[i - EE], 1);
}
__global__ void k_scan_part() {
    __shared__ int sh[512];
    int i = blockIdx.x * 512 + threadIdx.x;
    int v = (i < NN) ? g_deg[i] : 0;
    sh[threadIdx.x] = v;
    __syncthreads();
    #pragma unroll
    for (int off = 1; off < 512; off <<= 1) {
        int t = (threadIdx.x >= off) ? sh[threadIdx.x - off] : 0;
        __syncthreads();
        sh[threadIdx.x] += t;
        __syncthreads();
    }
    if (i < NN) g_rowptr[i] = sh[threadIdx.x] - v;
    if (threadIdx.x == 511) g_bsum[blockIdx.x] = sh[511];
}
// parallel 98-element exclusive scan (1 block, 128 threads)
__global__ void k_scan_boff() {
    __shared__ int sh[128];
    int i = threadIdx.x;
    int v = (i < SNB) ? g_bsum[i] : 0;
    sh[i] = v;
    __syncthreads();
    #pragma unroll
    for (int off = 1; off < 128; off <<= 1) {
        int t = (i >= off) ? sh[i - off] : 0;
        __syncthreads();
        sh[i] += t;
        __syncthreads();
    }
    if (i < SNB) g_boff[i] = sh[i] - v;
}
__global__ void k_scan_add() {
    int i = blockIdx.x * blockDim.x + threadIdx.x;
    if (i < NN) {
        int val = g_rowptr[i] + g_boff[i >> 9];
        g_rowptr[i] = val;
        g_cursor[i] = val;
    }
    if (i == 0) g_rowptr[NN] = ETOT;
}
__global__ void k_scatter_edges(const int* __restrict__ ei) {
    int i = blockIdx.x * blockDim.x + threadIdx.x;
    int src, dst;
    if (i < EE)        { src = ei[i]; dst = ei[EE + i]; }
    else if (i < ETOT) { src = i - EE; dst = i - EE; }
    else return;
    int pos = atomicAdd(&g_cursor[dst], 1);
    g_csrsrc[pos] = src;
}
__global__ void k_gbounds(const int* __restrict__ batch) {
    int i = blockIdx.x * blockDim.x + threadIdx.x;
    if (i >= NN) return;
    int b = batch[i];
    int prev = (i == 0) ? -1 : batch[i - 1];
    for (int g = prev + 1; g <= b; g++) g_gstart[g] = i;
    if (i == NN - 1)
        for (int g = b + 1; g <= GG; g++) g_gstart[g] = NN;
}

// ---------------- fp32 -> bf16 hi/lo splits ----------------
__global__ void k_split_x(const float* __restrict__ x,
                          __nv_bfloat16* __restrict__ hi, __nv_bfloat16* __restrict__ lo) {
    int i = blockIdx.x * 256 + threadIdx.x;
    float v = x[i];
    __nv_bfloat16 h = __float2bfloat16(v);
    hi[i] = h;
    lo[i] = __float2bfloat16(v - __bfloat162float(h));
}
__global__ void k_split_w(const float* __restrict__ W1, const float* __restrict__ W2) {
    int i = blockIdx.x * 256 + threadIdx.x;
    int which = i >> 16;
    int j = i & 65535;
    int n = j >> 8, k = j & 255;
    const float* W = which ? W2 : W1;
    float v = W[k * 256 + n];
    __nv_bfloat16 h = __float2bfloat16(v);
    float r = v - __bfloat162float(h);
    if (which) { g_w2hi[j] = h; g_w2lo[j] = __float2bfloat16(r); }
    else       { g_w1hi[j] = h; g_w1lo[j] = __float2bfloat16(r); }
}

// ---------------- GEMM: h[M,256] = A @ Wt^T (bf16 out) + fused att-coef epilogue ----------------
#define STG   98304
#define OA_HI 0
#define OA_LO 16384
#define OB_HI 32768
#define OB_LO 65536
#define SMEM_TOT (2 * STG)

__global__ void __launch_bounds__(256) k_gemm_att(
    const __nv_bfloat16* __restrict__ Ahi, const __nv_bfloat16* __restrict__ Alo,
    const __nv_bfloat16* __restrict__ Bhi, const __nv_bfloat16* __restrict__ Blo,
    __nv_bfloat162* __restrict__ Hout,
    const float* __restrict__ as, const float* __restrict__ ad,
    int M)
{
    extern __shared__ char smem[];
    uint32_t sb = su32(smem);
    const int tid = threadIdx.x, wid = tid >> 5, lane = tid & 31;
    const int row0 = blockIdx.x * 128;
    const int wm = wid & 3;
    const int wn = wid >> 2;

    float acc[2][16][4];
    #pragma unroll
    for (int a = 0; a < 2; a++)
        #pragma unroll
        for (int b = 0; b < 16; b++)
            #pragma unroll
            for (int q = 0; q < 4; q++) acc[a][b][q] = 0.f;

    auto load_chunk = [&](int c, int stage) {
        uint32_t base = sb + stage * STG;
        #pragma unroll
        for (int it = 0; it < 4; it++) {
            int u = tid + it * 256;
            int r = u >> 3, j = u & 7;
            uint32_t sw = swz(r * 128 + j * 16);
            int m = row0 + r;
            int mc = m < M ? m : (M - 1);
            uint32_t sz = (m < M) ? 16u : 0u;
            size_t gi = (size_t)mc * 256 + c * 64 + j * 8;
            cp16(base + OA_HI + sw, Ahi + gi, sz);
            cp16(base + OA_LO + sw, Alo + gi, sz);
        }
        #pragma unroll
        for (int it = 0; it < 8; it++) {
            int u = tid + it * 256;
            int r = u >> 3, j = u & 7;
            uint32_t sw = swz(r * 128 + j * 16);
            size_t gi = (size_t)r * 256 + c * 64 + j * 8;
            cp16f(base + OB_HI + sw, Bhi + gi);
            cp16f(base + OB_LO + sw, Blo + gi);
        }
    };

    load_chunk(0, 0);
    CP_COMMIT();

    const int lrow = lane & 15;
    const int lcol = (lane >> 4) * 8;
    const int cb = wn * 128;

    for (int c = 0; c < 4; c++) {
        int stage = c & 1;
        if (c < 3) { load_chunk(c + 1, stage ^ 1); CP_COMMIT(); CP_WAIT(1); }
        else       { CP_WAIT(0); }
        __syncthreads();
        uint32_t base = sb + stage * STG;

        #pragma unroll
        for (int kk = 0; kk < 4; kk++) {
            uint32_t ah[2][4], al[2][4];
            #pragma unroll
            for (int mt = 0; mt < 2; mt++) {
                uint32_t off = swz((wm * 32 + mt * 16 + lrow) * 128 + (kk * 16 + lcol) * 2);
                ldsm_x4(ah[mt], base + OA_HI + off);
                ldsm_x4(al[mt], base + OA_LO + off);
            }
            #pragma unroll
            for (int ntp = 0; ntp < 8; ntp++) {
                int q = lane >> 3;
                int nrow = cb + ntp * 16 + (q >> 1) * 8 + (lane & 7);
                int kcol = kk * 16 + (q & 1) * 8;
                uint32_t boff = swz(nrow * 128 + kcol * 2);
                uint32_t bh[4], bl[4];
                ldsm_x4(bh, base + OB_HI + boff);
                ldsm_x4(bl, base + OB_LO + boff);
                #pragma unroll
                for (int sub = 0; sub < 2; sub++) {
                    int nt = ntp * 2 + sub;
                    #pragma unroll
                    for (int mt = 0; mt < 2; mt++) {
                        mma_bf16(acc[mt][nt], ah[mt], bh + sub * 2);
                        mma_bf16(acc[mt][nt], ah[mt], bl + sub * 2);
                        mma_bf16(acc[mt][nt], al[mt], bh + sub * 2);
                    }
                }
            }
        }
        __syncthreads();
    }

    // ---- epilogue: attention coefficients + bf16 h store ----
    float sa[4][2], sd[4][2];
    #pragma unroll
    for (int i = 0; i < 4; i++) { sa[i][0] = sa[i][1] = 0.f; sd[i][0] = sd[i][1] = 0.f; }

    #pragma unroll
    for (int nt = 0; nt < 16; nt++) {
        int c0 = cb + nt * 8 + (lane & 3) * 2;
        float w0 = __ldg(as + c0), w1 = __ldg(as + c0 + 1);
        float v0 = __ldg(ad + c0), v1 = __ldg(ad + c0 + 1);
        int hl = nt >> 3;
        #pragma unroll
        for (int mt = 0; mt < 2; mt++) {
            sa[mt * 2 + 0][hl] += acc[mt][nt][0] * w0 + acc[mt][nt][1] * w1;
            sa[mt * 2 + 1][hl] += acc[mt][nt][2] * w0 + acc[mt][nt][3] * w1;
            sd[mt * 2 + 0][hl] += acc[mt][nt][0] * v0 + acc[mt][nt][1] * v1;
            sd[mt * 2 + 1][hl] += acc[mt][nt][2] * v0 + acc[mt][nt][3] * v1;
        }
    }
    #pragma unroll
    for (int i = 0; i < 4; i++)
        #pragma unroll
        for (int hl = 0; hl < 2; hl++) {
            sa[i][hl] += __shfl_xor_sync(0xffffffff, sa[i][hl], 1);
            sa[i][hl] += __shfl_xor_sync(0xffffffff, sa[i][hl], 2);
            sd[i][hl] += __shfl_xor_sync(0xffffffff, sd[i][hl], 1);
            sd[i][hl] += __shfl_xor_sync(0xffffffff, sd[i][hl], 2);
        }
    if ((lane & 3) == 0) {
        #pragma unroll
        for (int mt = 0; mt < 2; mt++)
            #pragma unroll
            for (int rh = 0; rh < 2; rh++) {
                int r = row0 + wm * 32 + mt * 16 + (lane >> 2) + rh * 8;
                if (r < M) {
                    #pragma unroll
                    for (int hl = 0; hl < 2; hl++) {
                        g_asrc[r * 4 + wn * 2 + hl] = sa[mt * 2 + rh][hl];
                        g_adst[r * 4 + wn * 2 + hl] = sd[mt * 2 + rh][hl];
                    }
                }
            }
    }

    #pragma unroll
    for (int mt = 0; mt < 2; mt++) {
        int r0 = row0 + wm * 32 + mt * 16 + (lane >> 2);
        int r1 = r0 + 8;
        #pragma unroll
        for (int nt = 0; nt < 16; nt++) {
            int cc2 = (cb >> 1) + nt * 4 + (lane & 3);
            if (r0 < M) Hout[(size_t)r0 * 128 + cc2] = __floats2bfloat162_rn(acc[mt][nt][0], acc[mt][nt][1]);
            if (r1 < M) Hout[(size_t)r1 * 128 + cc2] = __floats2bfloat162_rn(acc[mt][nt][2], acc[mt][nt][3]);
        }
    }
}

// ---------------- fused GAT aggregation (bf16 gather) + bias + LN + ReLU ----------------
__global__ void __launch_bounds__(128) k_agg_ln(
    const __nv_bfloat162* __restrict__ hb, const float* __restrict__ bias,
    const float* __restrict__ gamma, const float* __restrict__ beta,
    float* __restrict__ outf, __nv_bfloat162* __restrict__ ohi, __nv_bfloat162* __restrict__ olo)
{
    int n = blockIdx.x;
    int t = threadIdx.x >> 5, lane = threadIdx.x & 31;
    __shared__ float red[8];
    int beg = g_rowptr[n], end = g_rowptr[n + 1];
    float adst = g_adst[n * HEADS + t];

    float acc0 = 0.f, acc1 = 0.f, den = 0.f;
    const __nv_bfloat162* hp = hb + t * 32 + lane;
    int k = beg;
    for (; k + 1 < end; k += 2) {
        int s0 = g_csrsrc[k], s1 = g_csrsrc[k + 1];
        __nv_bfloat162 v0 = hp[(size_t)s0 * 128];
        __nv_bfloat162 v1 = hp[(size_t)s1 * 128];
        float e0 = g_asrc[s0 * HEADS + t] + adst;
        float e1 = g_asrc[s1 * HEADS + t] + adst;
        e0 = (e0 > 0.f) ? e0 : NEG_SLOPE * e0;
        e1 = (e1 > 0.f) ? e1 : NEG_SLOPE * e1;
        float w0 = __expf(e0), w1 = __expf(e1);
        float2 f0 = __bfloat1622float2(v0);
        float2 f1 = __bfloat1622float2(v1);
        den += w0 + w1;
        acc0 = fmaf(w0, f0.x, fmaf(w1, f1.x, acc0));
        acc1 = fmaf(w0, f0.y, fmaf(w1, f1.y, acc1));
    }
    if (k < end) {
        int s0 = g_csrsrc[k];
        __nv_bfloat162 v0 = hp[(size_t)s0 * 128];
        float e0 = g_asrc[s0 * HEADS + t] + adst;
        e0 = (e0 > 0.f) ? e0 : NEG_SLOPE * e0;
        float w0 = __expf(e0);
        float2 f0 = __bfloat1622float2(v0);
        den += w0;
        acc0 = fmaf(w0, f0.x, acc0);
        acc1 = fmaf(w0, f0.y, acc1);
    }
    float inv = 1.0f / den;
    int c0 = 2 * threadIdx.x, c1 = c0 + 1;
    float m0 = acc0 * inv + bias[c0];
    float m1 = acc1 * inv + bias[c1];

    float s = m0 + m1;
    #pragma unroll
    for (int off = 16; off > 0; off >>= 1) s += __shfl_xor_sync(0xffffffff, s, off);
    if (lane == 0) red[t] = s;
    __syncthreads();
    float mu = (red[0] + red[1] + red[2] + red[3]) * (1.0f / 256.0f);
    float d0 = m0 - mu, d1 = m1 - mu;
    float q = d0 * d0 + d1 * d1;
    #pragma unroll
    for (int off = 16; off > 0; off >>= 1) q += __shfl_xor_sync(0xffffffff, q, off);
    if (lane == 0) red[4 + t] = q;
    __syncthreads();
    float invs = rsqrtf((red[4] + red[5] + red[6] + red[7]) * (1.0f / 256.0f) + 1e-5f);

    float y0 = fmaxf(d0 * invs * gamma[c0] + beta[c0], 0.f);
    float y1 = fmaxf(d1 * invs * gamma[c1] + beta[c1], 0.f);
    size_t o = (size_t)n * 128 + threadIdx.x;
    if (outf) {
        *(float2*)(outf + 2 * o) = make_float2(y0, y1);
    }
    if (ohi) {
        __nv_bfloat16 h0 = __float2bfloat16(y0);
        __nv_bfloat16 h1 = __float2bfloat16(y1);
        ohi[o] = __nv_bfloat162(h0, h1);
        olo[o] = __nv_bfloat162(__float2bfloat16(y0 - __bfloat162float(h0)),
                                __float2bfloat16(y1 - __bfloat162float(h1)));
    }
}

// ---------------- global mean pool (float2) ----------------
__global__ void k_pool(const float* __restrict__ h) {
    int g = blockIdx.x;
    int col2 = threadIdx.x;
    int s = g_gstart[g], e = g_gstart[g + 1];
    float sum0 = 0.f, sum1 = 0.f;
    const float2* p = (const float2*)h + col2;
    for (int i = s; i < e; i++) {
        float2 v = __ldg(p + (size_t)i * 128);
        sum0 += v.x; sum1 += v.y;
    }
    float invc = 1.0f / (float)max(e - s, 1);
    g_pooled[g * DD + 2 * col2]     = sum0 * invc;
    g_pooled[g * DD + 2 * col2 + 1] = sum1 * invc;
}

// ---------------- final MLP ----------------
__global__ void k_mlp(const float* __restrict__ lw1, const float* __restrict__ lb1,
                      const float* __restrict__ lw2, const float* __restrict__ lb2,
                      float* __restrict__ out) {
    __shared__ float p[DD];
    __shared__ float hid[HIDC];
    int g = blockIdx.x, tid = threadIdx.x;
    for (int i = tid; i < DD; i += 64) p[i] = g_pooled[g * DD + i];
    __syncthreads();
    float s = lb1[tid];
    #pragma unroll 8
    for (int k = 0; k < DD; k++) s = fmaf(p[k], lw1[k * HIDC + tid], s);
    hid[tid] = fmaxf(s, 0.f);
    __syncthreads();
    if (tid < 2) {
        float o = lb2[tid];
        #pragma unroll
        for (int k = 0; k < HIDC; k++) o = fmaf(hid[k], lw2[k * 2 + tid], o);
        out[g * 2 + tid] = o;
    }
}

// ---------------- host launcher ----------------
extern "C" void kernel_launch(void* const* d_in, const int* in_sizes, int n_in,
                              void* d_out, int out_size) {
    const float* x   = (const float*)d_in[0];
    const int*   ei  = (const int*)d_in[1];
    const int*   bat = (const int*)d_in[2];
    const float* W1  = (const float*)d_in[3];
    const float* as1 = (const float*)d_in[4];
    const float* ad1 = (const float*)d_in[5];
    const float* b1  = (const float*)d_in[6];
    const float* g1  = (const float*)d_in[7];
    const float* be1 = (const float*)d_in[8];
    const float* W2  = (const float*)d_in[9];
    const float* as2 = (const float*)d_in[10];
    const float* ad2 = (const float*)d_in[11];
    const float* b2  = (const float*)d_in[12];
    const float* g2  = (const float*)d_in[13];
    const float* be2 = (const float*)d_in[14];
    const float* lw1 = (const float*)d_in[15];
    const float* lb1 = (const float*)d_in[16];
    const float* lw2 = (const float*)d_in[17];
    const float* lb2 = (const float*)d_in[18];
    float* out = (float*)d_out;

    cudaFuncSetAttribute(k_gemm_att, cudaFuncAttributeMaxDynamicSharedMemorySize, SMEM_TOT);

    float *bo;
    __nv_bfloat162 *hb;
    __nv_bfloat16 *ahi, *alo, *w1h, *w1l, *w2h, *w2l;
    cudaGetSymbolAddress((void**)&hb, g_hb);
    cudaGetSymbolAddress((void**)&bo, g_o);
    cudaGetSymbolAddress((void**)&ahi, g_ahi);
    cudaGetSymbolAddress((void**)&alo, g_alo);
    cudaGetSymbolAddress((void**)&w1h, g_w1hi);
    cudaGetSymbolAddress((void**)&w1l, g_w1lo);
    cudaGetSymbolAddress((void**)&w2h, g_w2hi);
    cudaGetSymbolAddress((void**)&w2l, g_w2lo);

    int gemm_blocks = (NN + 127) / 128;

    // independent prework first so k_gemm_att is launch #4 (ncu capture slot)
    k_split_x<<<NN * DD / 256, 256>>>(x, ahi, alo);                 // 1
    k_split_w<<<2 * DD * DD / 256, 256>>>(W1, W2);                  // 2
    k_gbounds<<<(NN + 255) / 256, 256>>>(bat);                      // 3
    k_gemm_att<<<gemm_blocks, 256, SMEM_TOT>>>(ahi, alo, w1h, w1l, hb, as1, ad1, NN);  // 4

    // CSR build (must finish before agg1)
    k_zero_deg<<<(NN + 255) / 256, 256>>>();                        // 5
    k_hist_edges<<<(ETOT + 255) / 256, 256>>>(ei);                  // 6
    k_scan_part<<<SNB, 512>>>();                                    // 7
    k_scan_boff<<<1, 128>>>();                                      // 8
    k_scan_add<<<(NN + 255) / 256, 256>>>();                        // 9
    k_scatter_edges<<<(ETOT + 255) / 256, 256>>>(ei);               // 10

    // ---- layer 1 agg ----
    k_agg_ln<<<NN, 128>>>(hb, b1, g1, be1, nullptr, (__nv_bfloat162*)ahi, (__nv_bfloat162*)alo);

    // ---- layer 2 ----
    k_gemm_att<<<gemm_blocks, 256, SMEM_TOT>>>(ahi, alo, w2h, w2l, hb, as2, ad2, NN);
    k_agg_ln<<<NN, 128>>>(hb, b2, g2, be2, bo, nullptr, nullptr);

    // ---- pool + MLP ----
    k_pool<<<GG, 128>>>(bo);
    k_mlp<<<GG, 64>>>(lw1, lb1, lw2, lb2, out);
}

// round 8
// speedup vs baseline: 1.1503x; 1.1399x over previous
#include <cuda_runtime.h>
#include <cuda_bf16.h>
#include <cstdint>
#include <math.h>

#define NN 50000
#define EE 400000
#define ETOT (EE + NN)
#define DD 256
#define HEADS 4
#define HIDC 64
#define GG 64
#define NEG_SLOPE 0.2f

// ---------------- static device scratch ----------------
__device__ __nv_bfloat162 g_hb[NN * 128];
__device__ float g_o[NN * DD];
__device__ __nv_bfloat16 g_ahi[NN * DD];
__device__ __nv_bfloat16 g_alo[NN * DD];
__device__ __nv_bfloat16 g_w1hi[DD * DD], g_w1lo[DD * DD];
__device__ __nv_bfloat16 g_w2hi[DD * DD], g_w2lo[DD * DD];
__device__ float g_asrc[NN * HEADS];
__device__ float g_adst[NN * HEADS];
__device__ int   g_deg[NN];
__device__ int   g_rowptr[NN + 1];
__device__ int   g_cursor[NN];
__device__ int   g_csrsrc[ETOT];
__device__ int   g_gstart[GG + 1];
__device__ float g_pooled[GG * DD];
#define SNB 98
__device__ int   g_bsum[SNB];
__device__ int   g_boff[SNB];

// ---------------- helpers ----------------
__device__ __forceinline__ uint32_t su32(const void* p) {
    uint32_t a;
    asm("{ .reg .u64 t; cvta.to.shared.u64 t, %1; cvt.u32.u64 %0, t; }" : "=r"(a) : "l"(p));
    return a;
}
__device__ __forceinline__ uint32_t swz(uint32_t off) {
    return off ^ ((off >> 3) & 0x70);
}
__device__ __forceinline__ void ldsm_x4(uint32_t* r, uint32_t addr) {
    asm volatile("ldmatrix.sync.aligned.m8n8.x4.shared.b16 {%0,%1,%2,%3}, [%4];"
                 : "=r"(r[0]), "=r"(r[1]), "=r"(r[2]), "=r"(r[3]) : "r"(addr));
}
__device__ __forceinline__ void mma_bf16(float* c, const uint32_t* a, const uint32_t* b) {
    asm volatile("mma.sync.aligned.m16n8k16.row.col.f32.bf16.bf16.f32 "
                 "{%0,%1,%2,%3}, {%4,%5,%6,%7}, {%8,%9}, {%0,%1,%2,%3};"
                 : "+f"(c[0]), "+f"(c[1]), "+f"(c[2]), "+f"(c[3])
                 : "r"(a[0]), "r"(a[1]), "r"(a[2]), "r"(a[3]), "r"(b[0]), "r"(b[1]));
}
__device__ __forceinline__ void cp16(uint32_t dst, const void* src, uint32_t sz) {
    asm volatile("cp.async.cg.shared.global [%0], [%1], 16, %2;" :: "r"(dst), "l"(src), "r"(sz));
}
__device__ __forceinline__ void cp16f(uint32_t dst, const void* src) {
    asm volatile("cp.async.cg.shared.global [%0], [%1], 16;" :: "r"(dst), "l"(src));
}
#define CP_COMMIT() asm volatile("cp.async.commit_group;" ::: "memory")
#define CP_WAIT(n)  asm volatile("cp.async.wait_group %0;" :: "n"(n) : "memory")

// ---------------- CSR build ----------------
__global__ void k_zero_deg() {
    int i = blockIdx.x * blockDim.x + threadIdx.x;
    if (i < NN) g_deg[i] = 0;
}
__global__ void k_hist_edges(const int* __restrict__ ei) {
    int i = blockIdx.x * blockDim.x + threadIdx.x;
    if (i < EE) atomicAdd(&g_deg[ei[EE + i]], 1);
    else if (i < ETOT) atomicAdd(&g_deg[i - EE], 1);
}
__global__ void k_scan_part() {
    __shared__ int sh[512];
    int i = blockIdx.x * 512 + threadIdx.x;
    int v = (i < NN) ? g_deg[i] : 0;
    sh[threadIdx.x] = v;
    __syncthreads();
    #pragma unroll
    for (int off = 1; off < 512; off <<= 1) {
        int t = (threadIdx.x >= off) ? sh[threadIdx.x - off] : 0;
        __syncthreads();
        sh[threadIdx.x] += t;
        __syncthreads();
    }
    if (i < NN) g_rowptr[i] = sh[threadIdx.x] - v;
    if (threadIdx.x == 511) g_bsum[blockIdx.x] = sh[511];
}
__global__ void k_scan_boff() {
    __shared__ int sh[128];
    int i = threadIdx.x;
    int v = (i < SNB) ? g_bsum[i] : 0;
    sh[i] = v;
    __syncthreads();
    #pragma unroll
    for (int off = 1; off < 128; off <<= 1) {
        int t = (i >= off) ? sh[i - off] : 0;
        __syncthreads();
        sh[i] += t;
        __syncthreads();
    }
    if (i < SNB) g_boff[i] = sh[i] - v;
}
__global__ void k_scan_add() {
    int i = blockIdx.x * blockDim.x + threadIdx.x;
    if (i < NN) {
        int val = g_rowptr[i] + g_boff[i >> 9];
        g_rowptr[i] = val;
        g_cursor[i] = val;
    }
    if (i == 0) g_rowptr[NN] = ETOT;
}
__global__ void k_scatter_edges(const int* __restrict__ ei) {
    int i = blockIdx.x * blockDim.x + threadIdx.x;
    int src, dst;
    if (i < EE)        { src = ei[i]; dst = ei[EE + i]; }
    else if (i < ETOT) { src = i - EE; dst = i - EE; }
    else return;
    int pos = atomicAdd(&g_cursor[dst], 1);
    g_csrsrc[pos] = src;
}
__global__ void k_gbounds(const int* __restrict__ batch) {
    int i = blockIdx.x * blockDim.x + threadIdx.x;
    if (i >= NN) return;
    int b = batch[i];
    int prev = (i == 0) ? -1 : batch[i - 1];
    for (int g = prev + 1; g <= b; g++) g_gstart[g] = i;
    if (i == NN - 1)
        for (int g = b + 1; g <= GG; g++) g_gstart[g] = NN;
}

// ---------------- fp32 -> bf16 hi/lo splits ----------------
__global__ void k_split_x(const float* __restrict__ x,
                          __nv_bfloat16* __restrict__ hi, __nv_bfloat16* __restrict__ lo) {
    int i = blockIdx.x * 256 + threadIdx.x;
    float v = x[i];
    __nv_bfloat16 h = __float2bfloat16(v);
    hi[i] = h;
    lo[i] = __float2bfloat16(v - __bfloat162float(h));
}
__global__ void k_split_w(const float* __restrict__ W1, const float* __restrict__ W2) {
    int i = blockIdx.x * 256 + threadIdx.x;
    int which = i >> 16;
    int j = i & 65535;
    int n = j >> 8, k = j & 255;
    const float* W = which ? W2 : W1;
    float v = W[k * 256 + n];
    __nv_bfloat16 h = __float2bfloat16(v);
    float r = v - __bfloat162float(h);
    if (which) { g_w2hi[j] = h; g_w2lo[j] = __float2bfloat16(r); }
    else       { g_w1hi[j] = h; g_w1lo[j] = __float2bfloat16(r); }
}

// ---------------- GEMM: h[M,256] = A @ Wt^T (bf16 out) + fused att-coef epilogue ----------------
#define STG   98304
#define OA_HI 0
#define OA_LO 16384
#define OB_HI 32768
#define OB_LO 65536
#define SMEM_TOT (2 * STG)

__global__ void __launch_bounds__(256) k_gemm_att(
    const __nv_bfloat16* __restrict__ Ahi, const __nv_bfloat16* __restrict__ Alo,
    const __nv_bfloat16* __restrict__ Bhi, const __nv_bfloat16* __restrict__ Blo,
    __nv_bfloat162* __restrict__ Hout,
    const float* __restrict__ as, const float* __restrict__ ad,
    int M)
{
    extern __shared__ char smem[];
    uint32_t sb = su32(smem);
    const int tid = threadIdx.x, wid = tid >> 5, lane = tid & 31;
    const int row0 = blockIdx.x * 128;
    const int wm = wid & 3;
    const int wn = wid >> 2;

    float acc[2][16][4];
    #pragma unroll
    for (int a = 0; a < 2; a++)
        #pragma unroll
        for (int b = 0; b < 16; b++)
            #pragma unroll
            for (int q = 0; q < 4; q++) acc[a][b][q] = 0.f;

    auto load_chunk = [&](int c, int stage) {
        uint32_t base = sb + stage * STG;
        #pragma unroll
        for (int it = 0; it < 4; it++) {
            int u = tid + it * 256;
            int r = u >> 3, j = u & 7;
            uint32_t sw = swz(r * 128 + j * 16);
            int m = row0 + r;
            int mc = m < M ? m : (M - 1);
            uint32_t sz = (m < M) ? 16u : 0u;
            size_t gi = (size_t)mc * 256 + c * 64 + j * 8;
            cp16(base + OA_HI + sw, Ahi + gi, sz);
            cp16(base + OA_LO + sw, Alo + gi, sz);
        }
        #pragma unroll
        for (int it = 0; it < 8; it++) {
            int u = tid + it * 256;
            int r = u >> 3, j = u & 7;
            uint32_t sw = swz(r * 128 + j * 16);
            size_t gi = (size_t)r * 256 + c * 64 + j * 8;
            cp16f(base + OB_HI + sw, Bhi + gi);
            cp16f(base + OB_LO + sw, Blo + gi);
        }
    };

    load_chunk(0, 0);
    CP_COMMIT();

    const int lrow = lane & 15;
    const int lcol = (lane >> 4) * 8;
    const int cb = wn * 128;

    for (int c = 0; c < 4; c++) {
        int stage = c & 1;
        if (c < 3) { load_chunk(c + 1, stage ^ 1); CP_COMMIT(); CP_WAIT(1); }
        else       { CP_WAIT(0); }
        __syncthreads();
        uint32_t base = sb + stage * STG;

        #pragma unroll
        for (int kk = 0; kk < 4; kk++) {
            uint32_t ah[2][4], al[2][4];
            #pragma unroll
            for (int mt = 0; mt < 2; mt++) {
                uint32_t off = swz((wm * 32 + mt * 16 + lrow) * 128 + (kk * 16 + lcol) * 2);
                ldsm_x4(ah[mt], base + OA_HI + off);
                ldsm_x4(al[mt], base + OA_LO + off);
            }
            #pragma unroll
            for (int ntp = 0; ntp < 8; ntp++) {
                int q = lane >> 3;
                int nrow = cb + ntp * 16 + (q >> 1) * 8 + (lane & 7);
                int kcol = kk * 16 + (q & 1) * 8;
                uint32_t boff = swz(nrow * 128 + kcol * 2);
                uint32_t bh[4], bl[4];
                ldsm_x4(bh, base + OB_HI + boff);
                ldsm_x4(bl, base + OB_LO + boff);
                #pragma unroll
                for (int sub = 0; sub < 2; sub++) {
                    int nt = ntp * 2 + sub;
                    #pragma unroll
                    for (int mt = 0; mt < 2; mt++) {
                        mma_bf16(acc[mt][nt], ah[mt], bh + sub * 2);
                        mma_bf16(acc[mt][nt], ah[mt], bl + sub * 2);
                        mma_bf16(acc[mt][nt], al[mt], bh + sub * 2);
                    }
                }
            }
        }
        __syncthreads();
    }

    // ---- epilogue: attention coefficients + bf16 h store ----
    float sa[4][2], sd[4][2];
    #pragma unroll
    for (int i = 0; i < 4; i++) { sa[i][0] = sa[i][1] = 0.f; sd[i][0] = sd[i][1] = 0.f; }

    #pragma unroll
    for (int nt = 0; nt < 16; nt++) {
        int c0 = cb + nt * 8 + (lane & 3) * 2;
        float w0 = __ldg(as + c0), w1 = __ldg(as + c0 + 1);
        float v0 = __ldg(ad + c0), v1 = __ldg(ad + c0 + 1);
        int hl = nt >> 3;
        #pragma unroll
        for (int mt = 0; mt < 2; mt++) {
            sa[mt * 2 + 0][hl] += acc[mt][nt][0] * w0 + acc[mt][nt][1] * w1;
            sa[mt * 2 + 1][hl] += acc[mt][nt][2] * w0 + acc[mt][nt][3] * w1;
            sd[mt * 2 + 0][hl] += acc[mt][nt][0] * v0 + acc[mt][nt][1] * v1;
            sd[mt * 2 + 1][hl] += acc[mt][nt][2] * v0 + acc[mt][nt][3] * v1;
        }
    }
    #pragma unroll
    for (int i = 0; i < 4; i++)
        #pragma unroll
        for (int hl = 0; hl < 2; hl++) {
            sa[i][hl] += __shfl_xor_sync(0xffffffff, sa[i][hl], 1);
            sa[i][hl] += __shfl_xor_sync(0xffffffff, sa[i][hl], 2);
            sd[i][hl] += __shfl_xor_sync(0xffffffff, sd[i][hl], 1);
            sd[i][hl] += __shfl_xor_sync(0xffffffff, sd[i][hl], 2);
        }
    if ((lane & 3) == 0) {
        #pragma unroll
        for (int mt = 0; mt < 2; mt++)
            #pragma unroll
            for (int rh = 0; rh < 2; rh++) {
                int r = row0 + wm * 32 + mt * 16 + (lane >> 2) + rh * 8;
                if (r < M) {
                    #pragma unroll
                    for (int hl = 0; hl < 2; hl++) {
                        g_asrc[r * 4 + wn * 2 + hl] = sa[mt * 2 + rh][hl];
                        g_adst[r * 4 + wn * 2 + hl] = sd[mt * 2 + rh][hl];
                    }
                }
            }
    }

    #pragma unroll
    for (int mt = 0; mt < 2; mt++) {
        int r0 = row0 + wm * 32 + mt * 16 + (lane >> 2);
        int r1 = r0 + 8;
        #pragma unroll
        for (int nt = 0; nt < 16; nt++) {
            int cc2 = (cb >> 1) + nt * 4 + (lane & 3);
            if (r0 < M) Hout[(size_t)r0 * 128 + cc2] = __floats2bfloat162_rn(acc[mt][nt][0], acc[mt][nt][1]);
            if (r1 < M) Hout[(size_t)r1 * 128 + cc2] = __floats2bfloat162_rn(acc[mt][nt][2], acc[mt][nt][3]);
        }
    }
}

// ---------------- warp-per-node GAT aggregation (all heads) + bias + warp LN + ReLU ----------------
__global__ void __launch_bounds__(256) k_agg_ln(
    const __nv_bfloat162* __restrict__ hb, const float* __restrict__ bias,
    const float* __restrict__ gamma, const float* __restrict__ beta,
    float* __restrict__ outf, __nv_bfloat162* __restrict__ ohi, __nv_bfloat162* __restrict__ olo)
{
    int wid = threadIdx.x >> 5, lane = threadIdx.x & 31;
    int n = blockIdx.x * 8 + wid;
    if (n >= NN) return;
    int beg = g_rowptr[n], end = g_rowptr[n + 1];
    float4 ad4 = __ldg((const float4*)g_adst + n);

    float a0 = 0.f, a1 = 0.f, a2 = 0.f, a3 = 0.f, a4 = 0.f, a5 = 0.f, a6 = 0.f, a7 = 0.f;
    float dn0 = 0.f, dn1 = 0.f, dn2 = 0.f, dn3 = 0.f;
    const __nv_bfloat162* hp = hb + lane;

    for (int k = beg; k < end; k++) {
        int s = __ldg(g_csrsrc + k);
        float4 av = __ldg((const float4*)g_asrc + s);
        const __nv_bfloat162* row = hp + (size_t)s * 128;
        __nv_bfloat162 v0 = __ldg(row);
        __nv_bfloat162 v1 = __ldg(row + 32);
        __nv_bfloat162 v2 = __ldg(row + 64);
        __nv_bfloat162 v3 = __ldg(row + 96);
        float e0 = av.x + ad4.x, e1 = av.y + ad4.y, e2 = av.z + ad4.z, e3 = av.w + ad4.w;
        e0 = (e0 > 0.f) ? e0 : NEG_SLOPE * e0;
        e1 = (e1 > 0.f) ? e1 : NEG_SLOPE * e1;
        e2 = (e2 > 0.f) ? e2 : NEG_SLOPE * e2;
        e3 = (e3 > 0.f) ? e3 : NEG_SLOPE * e3;
        float w0 = __expf(e0), w1 = __expf(e1), w2 = __expf(e2), w3 = __expf(e3);
        dn0 += w0; dn1 += w1; dn2 += w2; dn3 += w3;
        float2 f0 = __bfloat1622float2(v0);
        float2 f1 = __bfloat1622float2(v1);
        float2 f2 = __bfloat1622float2(v2);
        float2 f3 = __bfloat1622float2(v3);
        a0 = fmaf(w0, f0.x, a0); a1 = fmaf(w0, f0.y, a1);
        a2 = fmaf(w1, f1.x, a2); a3 = fmaf(w1, f1.y, a3);
        a4 = fmaf(w2, f2.x, a4); a5 = fmaf(w2, f2.y, a5);
        a6 = fmaf(w3, f3.x, a6); a7 = fmaf(w3, f3.y, a7);
    }
    float i0 = 1.f / dn0, i1 = 1.f / dn1, i2 = 1.f / dn2, i3 = 1.f / dn3;
    int c = 2 * lane;
    float m0 = a0 * i0 + __ldg(bias + c);
    float m1 = a1 * i0 + __ldg(bias + c + 1);
    float m2 = a2 * i1 + __ldg(bias + 64 + c);
    float m3 = a3 * i1 + __ldg(bias + 64 + c + 1);
    float m4 = a4 * i2 + __ldg(bias + 128 + c);
    float m5 = a5 * i2 + __ldg(bias + 128 + c + 1);
    float m6 = a6 * i3 + __ldg(bias + 192 + c);
    float m7 = a7 * i3 + __ldg(bias + 192 + c + 1);

    // warp-local LayerNorm over 256 channels
    float s = ((m0 + m1) + (m2 + m3)) + ((m4 + m5) + (m6 + m7));
    #pragma unroll
    for (int off = 16; off > 0; off >>= 1) s += __shfl_xor_sync(0xffffffff, s, off);
    float mu = s * (1.0f / 256.0f);
    float d0 = m0 - mu, d1 = m1 - mu, d2 = m2 - mu, d3 = m3 - mu;
    float d4 = m4 - mu, d5 = m5 - mu, d6 = m6 - mu, d7 = m7 - mu;
    float q = ((d0 * d0 + d1 * d1) + (d2 * d2 + d3 * d3)) + ((d4 * d4 + d5 * d5) + (d6 * d6 + d7 * d7));
    #pragma unroll
    for (int off = 16; off > 0; off >>= 1) q += __shfl_xor_sync(0xffffffff, q, off);
    float invs = rsqrtf(q * (1.0f / 256.0f) + 1e-5f);

    float y0 = fmaxf(d0 * invs * __ldg(gamma + c)       + __ldg(beta + c), 0.f);
    float y1 = fmaxf(d1 * invs * __ldg(gamma + c + 1)   + __ldg(beta + c + 1), 0.f);
    float y2 = fmaxf(d2 * invs * __ldg(gamma + 64 + c)  + __ldg(beta + 64 + c), 0.f);
    float y3 = fmaxf(d3 * invs * __ldg(gamma + 64 + c + 1) + __ldg(beta + 64 + c + 1), 0.f);
    float y4 = fmaxf(d4 * invs * __ldg(gamma + 128 + c) + __ldg(beta + 128 + c), 0.f);
    float y5 = fmaxf(d5 * invs * __ldg(gamma + 128 + c + 1) + __ldg(beta + 128 + c + 1), 0.f);
    float y6 = fmaxf(d6 * invs * __ldg(gamma + 192 + c) + __ldg(beta + 192 + c), 0.f);
    float y7 = fmaxf(d7 * invs * __ldg(gamma + 192 + c + 1) + __ldg(beta + 192 + c + 1), 0.f);

    if (outf) {
        float* ob = outf + (size_t)n * DD;
        *(float2*)(ob + c)       = make_float2(y0, y1);
        *(float2*)(ob + 64 + c)  = make_float2(y2, y3);
        *(float2*)(ob + 128 + c) = make_float2(y4, y5);
        *(float2*)(ob + 192 + c) = make_float2(y6, y7);
    }
    if (ohi) {
        size_t o = (size_t)n * 128 + lane;
        __nv_bfloat16 h0 = __float2bfloat16(y0), h1 = __float2bfloat16(y1);
        __nv_bfloat16 h2 = __float2bfloat16(y2), h3 = __float2bfloat16(y3);
        __nv_bfloat16 h4 = __float2bfloat16(y4), h5 = __float2bfloat16(y5);
        __nv_bfloat16 h6 = __float2bfloat16(y6), h7 = __float2bfloat16(y7);
        ohi[o]      = __nv_bfloat162(h0, h1);
        ohi[o + 32] = __nv_bfloat162(h2, h3);
        ohi[o + 64] = __nv_bfloat162(h4, h5);
        ohi[o + 96] = __nv_bfloat162(h6, h7);
        olo[o]      = __nv_bfloat162(__float2bfloat16(y0 - __bfloat162float(h0)),
                                     __float2bfloat16(y1 - __bfloat162float(h1)));
        olo[o + 32] = __nv_bfloat162(__float2bfloat16(y2 - __bfloat162float(h2)),
                                     __float2bfloat16(y3 - __bfloat162float(h3)));
        olo[o + 64] = __nv_bfloat162(__float2bfloat16(y4 - __bfloat162float(h4)),
                                     __float2bfloat16(y5 - __bfloat162float(h5)));
        olo[o + 96] = __nv_bfloat162(__float2bfloat16(y6 - __bfloat162float(h6)),
                                     __float2bfloat16(y7 - __bfloat162float(h7)));
    }
}

// ---------------- global mean pool (float2) ----------------
__global__ void k_pool(const float* __restrict__ h) {
    int g = blockIdx.x;
    int col2 = threadIdx.x;
    int s = g_gstart[g], e = g_gstart[g + 1];
    float sum0 = 0.f, sum1 = 0.f;
    const float2* p = (const float2*)h + col2;
    for (int i = s; i < e; i++) {
        float2 v = __ldg(p + (size_t)i * 128);
        sum0 += v.x; sum1 += v.y;
    }
    float invc = 1.0f / (float)max(e - s, 1);
    g_pooled[g * DD + 2 * col2]     = sum0 * invc;
    g_pooled[g * DD + 2 * col2 + 1] = sum1 * invc;
}

// ---------------- final MLP ----------------
__global__ void k_mlp(const float* __restrict__ lw1, const float* __restrict__ lb1,
                      const float* __restrict__ lw2, const float* __restrict__ lb2,
                      float* __restrict__ out) {
    __shared__ float p[DD];
    __shared__ float hid[HIDC];
    int g = blockIdx.x, tid = threadIdx.x;
    for (int i = tid; i < DD; i += 64) p[i] = g_pooled[g * DD + i];
    __syncthreads();
    float s = lb1[tid];
    #pragma unroll 8
    for (int k = 0; k < DD; k++) s = fmaf(p[k], lw1[k * HIDC + tid], s);
    hid[tid] = fmaxf(s, 0.f);
    __syncthreads();
    if (tid < 2) {
        float o = lb2[tid];
        #pragma unroll
        for (int k = 0; k < HIDC; k++) o = fmaf(hid[k], lw2[k * 2 + tid], o);
        out[g * 2 + tid] = o;
    }
}

// ---------------- host launcher ----------------
extern "C" void kernel_launch(void* const* d_in, const int* in_sizes, int n_in,
                              void* d_out, int out_size) {
    const float* x   = (const float*)d_in[0];
    const int*   ei  = (const int*)d_in[1];
    const int*   bat = (const int*)d_in[2];
    const float* W1  = (const float*)d_in[3];
    const float* as1 = (const float*)d_in[4];
    const float* ad1 = (const float*)d_in[5];
    const float* b1  = (const float*)d_in[6];
    const float* g1  = (const float*)d_in[7];
    const float* be1 = (const float*)d_in[8];
    const float* W2  = (const float*)d_in[9];
    const float* as2 = (const float*)d_in[10];
    const float* ad2 = (const float*)d_in[11];
    const float* b2  = (const float*)d_in[12];
    const float* g2  = (const float*)d_in[13];
    const float* be2 = (const float*)d_in[14];
    const float* lw1 = (const float*)d_in[15];
    const float* lb1 = (const float*)d_in[16];
    const float* lw2 = (const float*)d_in[17];
    const float* lb2 = (const float*)d_in[18];
    float* out = (float*)d_out;

    cudaFuncSetAttribute(k_gemm_att, cudaFuncAttributeMaxDynamicSharedMemorySize, SMEM_TOT);

    float *bo;
    __nv_bfloat162 *hb;
    __nv_bfloat16 *ahi, *alo, *w1h, *w1l, *w2h, *w2l;
    cudaGetSymbolAddress((void**)&hb, g_hb);
    cudaGetSymbolAddress((void**)&bo, g_o);
    cudaGetSymbolAddress((void**)&ahi, g_ahi);
    cudaGetSymbolAddress((void**)&alo, g_alo);
    cudaGetSymbolAddress((void**)&w1h, g_w1hi);
    cudaGetSymbolAddress((void**)&w1l, g_w1lo);
    cudaGetSymbolAddress((void**)&w2h, g_w2hi);
    cudaGetSymbolAddress((void**)&w2l, g_w2lo);

    int gemm_blocks = (NN + 127) / 128;
    int agg_blocks = (NN + 7) / 8;

    // independent prework first so k_gemm_att lands near the ncu capture slot
    k_split_x<<<NN * DD / 256, 256>>>(x, ahi, alo);                 // 1
    k_split_w<<<2 * DD * DD / 256, 256>>>(W1, W2);                  // 2
    k_gbounds<<<(NN + 255) / 256, 256>>>(bat);                      // 3
    k_gemm_att<<<gemm_blocks, 256, SMEM_TOT>>>(ahi, alo, w1h, w1l, hb, as1, ad1, NN);  // 4

    // CSR build (must finish before agg1)
    k_zero_deg<<<(NN + 255) / 256, 256>>>();                        // 5
    k_hist_edges<<<(ETOT + 255) / 256, 256>>>(ei);                  // 6
    k_scan_part<<<SNB, 512>>>();                                    // 7
    k_scan_boff<<<1, 128>>>();                                      // 8
    k_scan_add<<<(NN + 255) / 256, 256>>>();                        // 9
    k_scatter_edges<<<(ETOT + 255) / 256, 256>>>(ei);               // 10

    // ---- layer 1 agg ----
    k_agg_ln<<<agg_blocks, 256>>>(hb, b1, g1, be1, nullptr, (__nv_bfloat162*)ahi, (__nv_bfloat162*)alo);

    // ---- layer 2 ----
    k_gemm_att<<<gemm_blocks, 256, SMEM_TOT>>>(ahi, alo, w2h, w2l, hb, as2, ad2, NN);
    k_agg_ln<<<agg_blocks, 256>>>(hb, b2, g2, be2, bo, nullptr, nullptr);

    // ---- pool + MLP ----
    k_pool<<<GG, 128>>>(bo);
    k_mlp<<<GG, 64>>>(lw1, lb1, lw2, lb2, out);
}

// round 9
// speedup vs baseline: 1.2326x; 1.0715x over previous
#include <cuda_runtime.h>
#include <cuda_bf16.h>
#include <cstdint>
#include <math.h>

#define NN 50000
#define EE 400000
#define ETOT (EE + NN)
#define DD 256
#define HEADS 4
#define HIDC 64
#define GG 64
#define NEG_SLOPE 0.2f

// ---------------- static device scratch ----------------
__device__ __nv_bfloat162 g_hb[NN * 128];
__device__ float g_o[NN * DD];
__device__ __nv_bfloat16 g_ahi[NN * DD];
__device__ __nv_bfloat16 g_w1hi[DD * DD], g_w1lo[DD * DD];
__device__ __nv_bfloat16 g_w2hi[DD * DD], g_w2lo[DD * DD];
__device__ float g_asrc[NN * HEADS];
__device__ float g_adst[NN * HEADS];
__device__ int   g_deg[NN];
__device__ int   g_rowptr[NN + 1];
__device__ int   g_cursor[NN];
__device__ int   g_csrsrc[ETOT];
__device__ int   g_gstart[GG + 1];
__device__ float g_pooled[GG * DD];
#define SNB 98
__device__ int   g_bsum[SNB];
__device__ int   g_boff[SNB];

// ---------------- helpers ----------------
__device__ __forceinline__ uint32_t su32(const void* p) {
    uint32_t a;
    asm("{ .reg .u64 t; cvta.to.shared.u64 t, %1; cvt.u32.u64 %0, t; }" : "=r"(a) : "l"(p));
    return a;
}
__device__ __forceinline__ uint32_t swz(uint32_t off) {
    return off ^ ((off >> 3) & 0x70);
}
__device__ __forceinline__ void ldsm_x4(uint32_t* r, uint32_t addr) {
    asm volatile("ldmatrix.sync.aligned.m8n8.x4.shared.b16 {%0,%1,%2,%3}, [%4];"
                 : "=r"(r[0]), "=r"(r[1]), "=r"(r[2]), "=r"(r[3]) : "r"(addr));
}
__device__ __forceinline__ void mma_bf16(float* c, const uint32_t* a, const uint32_t* b) {
    asm volatile("mma.sync.aligned.m16n8k16.row.col.f32.bf16.bf16.f32 "
                 "{%0,%1,%2,%3}, {%4,%5,%6,%7}, {%8,%9}, {%0,%1,%2,%3};"
                 : "+f"(c[0]), "+f"(c[1]), "+f"(c[2]), "+f"(c[3])
                 : "r"(a[0]), "r"(a[1]), "r"(a[2]), "r"(a[3]), "r"(b[0]), "r"(b[1]));
}
__device__ __forceinline__ void cp16(uint32_t dst, const void* src, uint32_t sz) {
    asm volatile("cp.async.cg.shared.global [%0], [%1], 16, %2;" :: "r"(dst), "l"(src), "r"(sz));
}
__device__ __forceinline__ void cp16f(uint32_t dst, const void* src) {
    asm volatile("cp.async.cg.shared.global [%0], [%1], 16;" :: "r"(dst), "l"(src));
}
#define CP_COMMIT() asm volatile("cp.async.commit_group;" ::: "memory")
#define CP_WAIT(n)  asm volatile("cp.async.wait_group %0;" :: "n"(n) : "memory")

// ---------------- CSR build ----------------
__global__ void k_zero_deg() {
    int i = blockIdx.x * blockDim.x + threadIdx.x;
    if (i < NN) g_deg[i] = 0;
}
__global__ void k_hist_edges(const int* __restrict__ ei) {
    int i = blockIdx.x * blockDim.x + threadIdx.x;
    if (i < EE) atomicAdd(&g_deg[ei[EE + i]], 1);
    else if (i < ETOT) atomicAdd(&g_deg[i - EE], 1);
}
__global__ void k_scan_part() {
    __shared__ int sh[512];
    int i = blockIdx.x * 512 + threadIdx.x;
    int v = (i < NN) ? g_deg[i] : 0;
    sh[threadIdx.x] = v;
    __syncthreads();
    #pragma unroll
    for (int off = 1; off < 512; off <<= 1) {
        int t = (threadIdx.x >= off) ? sh[threadIdx.x - off] : 0;
        __syncthreads();
        sh[threadIdx.x] += t;
        __syncthreads();
    }
    if (i < NN) g_rowptr[i] = sh[threadIdx.x] - v;
    if (threadIdx.x == 511) g_bsum[blockIdx.x] = sh[511];
}
__global__ void k_scan_boff() {
    __shared__ int sh[128];
    int i = threadIdx.x;
    int v = (i < SNB) ? g_bsum[i] : 0;
    sh[i] = v;
    __syncthreads();
    #pragma unroll
    for (int off = 1; off < 128; off <<= 1) {
        int t = (i >= off) ? sh[i - off] : 0;
        __syncthreads();
        sh[i] += t;
        __syncthreads();
    }
    if (i < SNB) g_boff[i] = sh[i] - v;
}
__global__ void k_scan_add() {
    int i = blockIdx.x * blockDim.x + threadIdx.x;
    if (i < NN) {
        int val = g_rowptr[i] + g_boff[i >> 9];
        g_rowptr[i] = val;
        g_cursor[i] = val;
    }
    if (i == 0) g_rowptr[NN] = ETOT;
}
__global__ void k_scatter_edges(const int* __restrict__ ei) {
    int i = blockIdx.x * blockDim.x + threadIdx.x;
    int src, dst;
    if (i < EE)        { src = ei[i]; dst = ei[EE + i]; }
    else if (i < ETOT) { src = i - EE; dst = i - EE; }
    else return;
    int pos = atomicAdd(&g_cursor[dst], 1);
    g_csrsrc[pos] = src;
}
__global__ void k_gbounds(const int* __restrict__ batch) {
    int i = blockIdx.x * blockDim.x + threadIdx.x;
    if (i >= NN) return;
    int b = batch[i];
    int prev = (i == 0) ? -1 : batch[i - 1];
    for (int g = prev + 1; g <= b; g++) g_gstart[g] = i;
    if (i == NN - 1)
        for (int g = b + 1; g <= GG; g++) g_gstart[g] = NN;
}

// ---------------- fp32 -> bf16 ----------------
__global__ void k_split_x(const float* __restrict__ x, __nv_bfloat16* __restrict__ hi) {
    int i = blockIdx.x * 256 + threadIdx.x;
    hi[i] = __float2bfloat16(x[i]);
}
__global__ void k_split_w(const float* __restrict__ W1, const float* __restrict__ W2) {
    int i = blockIdx.x * 256 + threadIdx.x;
    int which = i >> 16;
    int j = i & 65535;
    int n = j >> 8, k = j & 255;
    const float* W = which ? W2 : W1;
    float v = W[k * 256 + n];
    __nv_bfloat16 h = __float2bfloat16(v);
    float r = v - __bfloat162float(h);
    if (which) { g_w2hi[j] = h; g_w2lo[j] = __float2bfloat16(r); }
    else       { g_w1hi[j] = h; g_w1lo[j] = __float2bfloat16(r); }
}

// ---------------- GEMM: h[M,256] = A(bf16) @ [Whi+Wlo]^T + fused att epilogue ----------------
#define STG   81920
#define OA_HI 0
#define OB_HI 16384
#define OB_LO 49152
#define SMEM_TOT (2 * STG)

__global__ void __launch_bounds__(256) k_gemm_att(
    const __nv_bfloat16* __restrict__ Ahi,
    const __nv_bfloat16* __restrict__ Bhi, const __nv_bfloat16* __restrict__ Blo,
    __nv_bfloat162* __restrict__ Hout,
    const float* __restrict__ as, const float* __restrict__ ad,
    int M)
{
    extern __shared__ char smem[];
    uint32_t sb = su32(smem);
    const int tid = threadIdx.x, wid = tid >> 5, lane = tid & 31;
    const int row0 = blockIdx.x * 128;
    const int wm = wid & 3;
    const int wn = wid >> 2;

    float acc[2][16][4];
    #pragma unroll
    for (int a = 0; a < 2; a++)
        #pragma unroll
        for (int b = 0; b < 16; b++)
            #pragma unroll
            for (int q = 0; q < 4; q++) acc[a][b][q] = 0.f;

    auto load_chunk = [&](int c, int stage) {
        uint32_t base = sb + stage * STG;
        #pragma unroll
        for (int it = 0; it < 4; it++) {          // A: 1024 16B slots
            int u = tid + it * 256;
            int r = u >> 3, j = u & 7;
            uint32_t sw = swz(r * 128 + j * 16);
            int m = row0 + r;
            int mc = m < M ? m : (M - 1);
            uint32_t sz = (m < M) ? 16u : 0u;
            size_t gi = (size_t)mc * 256 + c * 64 + j * 8;
            cp16(base + OA_HI + sw, Ahi + gi, sz);
        }
        #pragma unroll
        for (int it = 0; it < 8; it++) {          // B: 2048 16B slots
            int u = tid + it * 256;
            int r = u >> 3, j = u & 7;
            uint32_t sw = swz(r * 128 + j * 16);
            size_t gi = (size_t)r * 256 + c * 64 + j * 8;
            cp16f(base + OB_HI + sw, Bhi + gi);
            cp16f(base + OB_LO + sw, Blo + gi);
        }
    };

    load_chunk(0, 0);
    CP_COMMIT();

    const int lrow = lane & 15;
    const int lcol = (lane >> 4) * 8;
    const int cb = wn * 128;

    for (int c = 0; c < 4; c++) {
        int stage = c & 1;
        if (c < 3) { load_chunk(c + 1, stage ^ 1); CP_COMMIT(); CP_WAIT(1); }
        else       { CP_WAIT(0); }
        __syncthreads();
        uint32_t base = sb + stage * STG;

        #pragma unroll
        for (int kk = 0; kk < 4; kk++) {
            uint32_t ah[2][4];
            #pragma unroll
            for (int mt = 0; mt < 2; mt++) {
                uint32_t off = swz((wm * 32 + mt * 16 + lrow) * 128 + (kk * 16 + lcol) * 2);
                ldsm_x4(ah[mt], base + OA_HI + off);
            }
            #pragma unroll
            for (int ntp = 0; ntp < 8; ntp++) {
                int q = lane >> 3;
                int nrow = cb + ntp * 16 + (q >> 1) * 8 + (lane & 7);
                int kcol = kk * 16 + (q & 1) * 8;
                uint32_t boff = swz(nrow * 128 + kcol * 2);
                uint32_t bh[4], bl[4];
                ldsm_x4(bh, base + OB_HI + boff);
                ldsm_x4(bl, base + OB_LO + boff);
                #pragma unroll
                for (int sub = 0; sub < 2; sub++) {
                    int nt = ntp * 2 + sub;
                    #pragma unroll
                    for (int mt = 0; mt < 2; mt++) {
                        mma_bf16(acc[mt][nt], ah[mt], bh + sub * 2);
                        mma_bf16(acc[mt][nt], ah[mt], bl + sub * 2);
                    }
                }
            }
        }
        __syncthreads();
    }

    // ---- epilogue: attention coefficients + bf16 h store ----
    float sa[4][2], sd[4][2];
    #pragma unroll
    for (int i = 0; i < 4; i++) { sa[i][0] = sa[i][1] = 0.f; sd[i][0] = sd[i][1] = 0.f; }

    #pragma unroll
    for (int nt = 0; nt < 16; nt++) {
        int c0 = cb + nt * 8 + (lane & 3) * 2;
        float w0 = __ldg(as + c0), w1 = __ldg(as + c0 + 1);
        float v0 = __ldg(ad + c0), v1 = __ldg(ad + c0 + 1);
        int hl = nt >> 3;
        #pragma unroll
        for (int mt = 0; mt < 2; mt++) {
            sa[mt * 2 + 0][hl] += acc[mt][nt][0] * w0 + acc[mt][nt][1] * w1;
            sa[mt * 2 + 1][hl] += acc[mt][nt][2] * w0 + acc[mt][nt][3] * w1;
            sd[mt * 2 + 0][hl] += acc[mt][nt][0] * v0 + acc[mt][nt][1] * v1;
            sd[mt * 2 + 1][hl] += acc[mt][nt][2] * v0 + acc[mt][nt][3] * v1;
        }
    }
    #pragma unroll
    for (int i = 0; i < 4; i++)
        #pragma unroll
        for (int hl = 0; hl < 2; hl++) {
            sa[i][hl] += __shfl_xor_sync(0xffffffff, sa[i][hl], 1);
            sa[i][hl] += __shfl_xor_sync(0xffffffff, sa[i][hl], 2);
            sd[i][hl] += __shfl_xor_sync(0xffffffff, sd[i][hl], 1);
            sd[i][hl] += __shfl_xor_sync(0xffffffff, sd[i][hl], 2);
        }
    if ((lane & 3) == 0) {
        #pragma unroll
        for (int mt = 0; mt < 2; mt++)
            #pragma unroll
            for (int rh = 0; rh < 2; rh++) {
                int r = row0 + wm * 32 + mt * 16 + (lane >> 2) + rh * 8;
                if (r < M) {
                    #pragma unroll
                    for (int hl = 0; hl < 2; hl++) {
                        g_asrc[r * 4 + wn * 2 + hl] = sa[mt * 2 + rh][hl];
                        g_adst[r * 4 + wn * 2 + hl] = sd[mt * 2 + rh][hl];
                    }
                }
            }
    }

    #pragma unroll
    for (int mt = 0; mt < 2; mt++) {
        int r0 = row0 + wm * 32 + mt * 16 + (lane >> 2);
        int r1 = r0 + 8;
        #pragma unroll
        for (int nt = 0; nt < 16; nt++) {
            int cc2 = (cb >> 1) + nt * 4 + (lane & 3);
            if (r0 < M) Hout[(size_t)r0 * 128 + cc2] = __floats2bfloat162_rn(acc[mt][nt][0], acc[mt][nt][1]);
            if (r1 < M) Hout[(size_t)r1 * 128 + cc2] = __floats2bfloat162_rn(acc[mt][nt][2], acc[mt][nt][3]);
        }
    }
}

// ---------------- warp-per-node GAT aggregation (idx-prefetch) + bias + warp LN + ReLU ----------------
__global__ void __launch_bounds__(256) k_agg_ln(
    const __nv_bfloat162* __restrict__ hb, const float* __restrict__ bias,
    const float* __restrict__ gamma, const float* __restrict__ beta,
    float* __restrict__ outf, __nv_bfloat162* __restrict__ ohi)
{
    int wid = threadIdx.x >> 5, lane = threadIdx.x & 31;
    int n = blockIdx.x * 8 + wid;
    if (n >= NN) return;
    int beg = g_rowptr[n], end = g_rowptr[n + 1];
    float4 ad4 = __ldg((const float4*)g_adst + n);

    float a0 = 0.f, a1 = 0.f, a2 = 0.f, a3 = 0.f, a4 = 0.f, a5 = 0.f, a6 = 0.f, a7 = 0.f;
    float dn0 = 0.f, dn1 = 0.f, dn2 = 0.f, dn3 = 0.f;
    const __nv_bfloat162* hp = hb + lane;

    int s = __ldg(g_csrsrc + beg);     // prefetch first index
    for (int k = beg; k < end; k++) {
        int sc = s;
        if (k + 1 < end) s = __ldg(g_csrsrc + k + 1);   // prefetch next index
        float4 av = __ldg((const float4*)g_asrc + sc);
        const __nv_bfloat162* row = hp + (size_t)sc * 128;
        __nv_bfloat162 v0 = __ldg(row);
        __nv_bfloat162 v1 = __ldg(row + 32);
        __nv_bfloat162 v2 = __ldg(row + 64);
        __nv_bfloat162 v3 = __ldg(row + 96);
        float e0 = av.x + ad4.x, e1 = av.y + ad4.y, e2 = av.z + ad4.z, e3 = av.w + ad4.w;
        e0 = (e0 > 0.f) ? e0 : NEG_SLOPE * e0;
        e1 = (e1 > 0.f) ? e1 : NEG_SLOPE * e1;
        e2 = (e2 > 0.f) ? e2 : NEG_SLOPE * e2;
        e3 = (e3 > 0.f) ? e3 : NEG_SLOPE * e3;
        float w0 = __expf(e0), w1 = __expf(e1), w2 = __expf(e2), w3 = __expf(e3);
        dn0 += w0; dn1 += w1; dn2 += w2; dn3 += w3;
        float2 f0 = __bfloat1622float2(v0);
        float2 f1 = __bfloat1622float2(v1);
        float2 f2 = __bfloat1622float2(v2);
        float2 f3 = __bfloat1622float2(v3);
        a0 = fmaf(w0, f0.x, a0); a1 = fmaf(w0, f0.y, a1);
        a2 = fmaf(w1, f1.x, a2); a3 = fmaf(w1, f1.y, a3);
        a4 = fmaf(w2, f2.x, a4); a5 = fmaf(w2, f2.y, a5);
        a6 = fmaf(w3, f3.x, a6); a7 = fmaf(w3, f3.y, a7);
    }
    float i0 = 1.f / dn0, i1 = 1.f / dn1, i2 = 1.f / dn2, i3 = 1.f / dn3;
    int c = 2 * lane;
    float m0 = a0 * i0 + __ldg(bias + c);
    float m1 = a1 * i0 + __ldg(bias + c + 1);
    float m2 = a2 * i1 + __ldg(bias + 64 + c);
    float m3 = a3 * i1 + __ldg(bias + 64 + c + 1);
    float m4 = a4 * i2 + __ldg(bias + 128 + c);
    float m5 = a5 * i2 + __ldg(bias + 128 + c + 1);
    float m6 = a6 * i3 + __ldg(bias + 192 + c);
    float m7 = a7 * i3 + __ldg(bias + 192 + c + 1);

    float s1 = ((m0 + m1) + (m2 + m3)) + ((m4 + m5) + (m6 + m7));
    #pragma unroll
    for (int off = 16; off > 0; off >>= 1) s1 += __shfl_xor_sync(0xffffffff, s1, off);
    float mu = s1 * (1.0f / 256.0f);
    float d0 = m0 - mu, d1 = m1 - mu, d2 = m2 - mu, d3 = m3 - mu;
    float d4 = m4 - mu, d5 = m5 - mu, d6 = m6 - mu, d7 = m7 - mu;
    float q = ((d0 * d0 + d1 * d1) + (d2 * d2 + d3 * d3)) + ((d4 * d4 + d5 * d5) + (d6 * d6 + d7 * d7));
    #pragma unroll
    for (int off = 16; off > 0; off >>= 1) q += __shfl_xor_sync(0xffffffff, q, off);
    float invs = rsqrtf(q * (1.0f / 256.0f) + 1e-5f);

    float y0 = fmaxf(d0 * invs * __ldg(gamma + c)       + __ldg(beta + c), 0.f);
    float y1 = fmaxf(d1 * invs * __ldg(gamma + c + 1)   + __ldg(beta + c + 1), 0.f);
    float y2 = fmaxf(d2 * invs * __ldg(gamma + 64 + c)  + __ldg(beta + 64 + c), 0.f);
    float y3 = fmaxf(d3 * invs * __ldg(gamma + 64 + c + 1) + __ldg(beta + 64 + c + 1), 0.f);
    float y4 = fmaxf(d4 * invs * __ldg(gamma + 128 + c) + __ldg(beta + 128 + c), 0.f);
    float y5 = fmaxf(d5 * invs * __ldg(gamma + 128 + c + 1) + __ldg(beta + 128 + c + 1), 0.f);
    float y6 = fmaxf(d6 * invs * __ldg(gamma + 192 + c) + __ldg(beta + 192 + c), 0.f);
    float y7 = fmaxf(d7 * invs * __ldg(gamma + 192 + c + 1) + __ldg(beta + 192 + c + 1), 0.f);

    if (outf) {
        float* ob = outf + (size_t)n * DD;
        *(float2*)(ob + c)       = make_float2(y0, y1);
        *(float2*)(ob + 64 + c)  = make_float2(y2, y3);
        *(float2*)(ob + 128 + c) = make_float2(y4, y5);
        *(float2*)(ob + 192 + c) = make_float2(y6, y7);
    }
    if (ohi) {
        size_t o = (size_t)n * 128 + lane;
        ohi[o]      = __floats2bfloat162_rn(y0, y1);
        ohi[o + 32] = __floats2bfloat162_rn(y2, y3);
        ohi[o + 64] = __floats2bfloat162_rn(y4, y5);
        ohi[o + 96] = __floats2bfloat162_rn(y6, y7);
    }
}

// ---------------- global mean pool (float2) ----------------
__global__ void k_pool(const float* __restrict__ h) {
    int g = blockIdx.x;
    int col2 = threadIdx.x;
    int s = g_gstart[g], e = g_gstart[g + 1];
    float sum0 = 0.f, sum1 = 0.f;
    const float2* p = (const float2*)h + col2;
    for (int i = s; i < e; i++) {
        float2 v = __ldg(p + (size_t)i * 128);
        sum0 += v.x; sum1 += v.y;
    }
    float invc = 1.0f / (float)max(e - s, 1);
    g_pooled[g * DD + 2 * col2]     = sum0 * invc;
    g_pooled[g * DD + 2 * col2 + 1] = sum1 * invc;
}

// ---------------- final MLP ----------------
__global__ void k_mlp(const float* __restrict__ lw1, const float* __restrict__ lb1,
                      const float* __restrict__ lw2, const float* __restrict__ lb2,
                      float* __restrict__ out) {
    __shared__ float p[DD];
    __shared__ float hid[HIDC];
    int g = blockIdx.x, tid = threadIdx.x;
    for (int i = tid; i < DD; i += 64) p[i] = g_pooled[g * DD + i];
    __syncthreads();
    float s = lb1[tid];
    #pragma unroll 8
    for (int k = 0; k < DD; k++) s = fmaf(p[k], lw1[k * HIDC + tid], s);
    hid[tid] = fmaxf(s, 0.f);
    __syncthreads();
    if (tid < 2) {
        float o = lb2[tid];
        #pragma unroll
        for (int k = 0; k < HIDC; k++) o = fmaf(hid[k], lw2[k * 2 + tid], o);
        out[g * 2 + tid] = o;
    }
}

// ---------------- host launcher ----------------
extern "C" void kernel_launch(void* const* d_in, const int* in_sizes, int n_in,
                              void* d_out, int out_size) {
    const float* x   = (const float*)d_in[0];
    const int*   ei  = (const int*)d_in[1];
    const int*   bat = (const int*)d_in[2];
    const float* W1  = (const float*)d_in[3];
    const float* as1 = (const float*)d_in[4];
    const float* ad1 = (const float*)d_in[5];
    const float* b1  = (const float*)d_in[6];
    const float* g1  = (const float*)d_in[7];
    const float* be1 = (const float*)d_in[8];
    const float* W2  = (const float*)d_in[9];
    const float* as2 = (const float*)d_in[10];
    const float* ad2 = (const float*)d_in[11];
    const float* b2  = (const float*)d_in[12];
    const float* g2  = (const float*)d_in[13];
    const float* be2 = (const float*)d_in[14];
    const float* lw1 = (const float*)d_in[15];
    const float* lb1 = (const float*)d_in[16];
    const float* lw2 = (const float*)d_in[17];
    const float* lb2 = (const float*)d_in[18];
    float* out = (float*)d_out;

    cudaFuncSetAttribute(k_gemm_att, cudaFuncAttributeMaxDynamicSharedMemorySize, SMEM_TOT);

    float *bo;
    __nv_bfloat162 *hb;
    __nv_bfloat16 *ahi, *w1h, *w1l, *w2h, *w2l;
    cudaGetSymbolAddress((void**)&hb, g_hb);
    cudaGetSymbolAddress((void**)&bo, g_o);
    cudaGetSymbolAddress((void**)&ahi, g_ahi);
    cudaGetSymbolAddress((void**)&w1h, g_w1hi);
    cudaGetSymbolAddress((void**)&w1l, g_w1lo);
    cudaGetSymbolAddress((void**)&w2h, g_w2hi);
    cudaGetSymbolAddress((void**)&w2l, g_w2lo);

    int gemm_blocks = (NN + 127) / 128;
    int agg_blocks = (NN + 7) / 8;

    // independent prework first so k_gemm_att lands at the ncu capture slot
    k_split_x<<<NN * DD / 256, 256>>>(x, ahi);                      // 1
    k_split_w<<<2 * DD * DD / 256, 256>>>(W1, W2);                  // 2
    k_gbounds<<<(NN + 255) / 256, 256>>>(bat);                      // 3
    k_gemm_att<<<gemm_blocks, 256, SMEM_TOT>>>(ahi, w1h, w1l, hb, as1, ad1, NN);  // 4

    // CSR build (must finish before agg1)
    k_zero_deg<<<(NN + 255) / 256, 256>>>();                        // 5
    k_hist_edges<<<(ETOT + 255) / 256, 256>>>(ei);                  // 6
    k_scan_part<<<SNB, 512>>>();                                    // 7
    k_scan_boff<<<1, 128>>>();                                      // 8
    k_scan_add<<<(NN + 255) / 256, 256>>>();                        // 9
    k_scatter_edges<<<(ETOT + 255) / 256, 256>>>(ei);               // 10

    // ---- layer 1 agg ----
    k_agg_ln<<<agg_blocks, 256>>>(hb, b1, g1, be1, nullptr, (__nv_bfloat162*)ahi);

    // ---- layer 2 ----
    k_gemm_att<<<gemm_blocks, 256, SMEM_TOT>>>(ahi, w2h, w2l, hb, as2, ad2, NN);
    k_agg_ln<<<agg_blocks, 256>>>(hb, b2, g2, be2, bo, nullptr);

    // ---- pool + MLP ----
    k_pool<<<GG, 128>>>(bo);
    k_mlp<<<GG, 64>>>(lw1, lb1, lw2, lb2, out);
}

// round 10
// speedup vs baseline: 1.3536x; 1.0982x over previous
#include <cuda_runtime.h>
#include <cuda_bf16.h>
#include <cstdint>
#include <math.h>

#define NN 50000
#define EE 400000
#define ETOT (EE + NN)
#define DD 256
#define HEADS 4
#define HIDC 64
#define GG 64
#define NEG_SLOPE 0.2f

// ---------------- static device scratch ----------------
__device__ __nv_bfloat162 g_hb[NN * 128];
__device__ float g_o[NN * DD];
__device__ __nv_bfloat16 g_ahi[NN * DD];
__device__ __nv_bfloat16 g_w1hi[DD * DD], g_w1lo[DD * DD];
__device__ __nv_bfloat16 g_w2hi[DD * DD], g_w2lo[DD * DD];
__device__ float g_asrc[NN * HEADS];
__device__ float g_adst[NN * HEADS];
__device__ int   g_deg[NN];
__device__ int   g_rowptr[NN + 1];
__device__ int   g_cursor[NN];
__device__ int   g_csrsrc[ETOT];
__device__ int   g_gstart[GG + 1];
__device__ float g_pooled[GG * DD];
#define SNB 98
__device__ int   g_bsum[SNB];
__device__ int   g_boff[SNB];

// ---------------- helpers ----------------
__device__ __forceinline__ uint32_t su32(const void* p) {
    uint32_t a;
    asm("{ .reg .u64 t; cvta.to.shared.u64 t, %1; cvt.u32.u64 %0, t; }" : "=r"(a) : "l"(p));
    return a;
}
__device__ __forceinline__ uint32_t swz(uint32_t off) {
    return off ^ ((off >> 3) & 0x70);
}
__device__ __forceinline__ void ldsm_x4(uint32_t* r, uint32_t addr) {
    asm volatile("ldmatrix.sync.aligned.m8n8.x4.shared.b16 {%0,%1,%2,%3}, [%4];"
                 : "=r"(r[0]), "=r"(r[1]), "=r"(r[2]), "=r"(r[3]) : "r"(addr));
}
__device__ __forceinline__ void mma_bf16(float* c, const uint32_t* a, const uint32_t* b) {
    asm volatile("mma.sync.aligned.m16n8k16.row.col.f32.bf16.bf16.f32 "
                 "{%0,%1,%2,%3}, {%4,%5,%6,%7}, {%8,%9}, {%0,%1,%2,%3};"
                 : "+f"(c[0]), "+f"(c[1]), "+f"(c[2]), "+f"(c[3])
                 : "r"(a[0]), "r"(a[1]), "r"(a[2]), "r"(a[3]), "r"(b[0]), "r"(b[1]));
}
__device__ __forceinline__ void cp16(uint32_t dst, const void* src, uint32_t sz) {
    asm volatile("cp.async.cg.shared.global [%0], [%1], 16, %2;" :: "r"(dst), "l"(src), "r"(sz));
}
__device__ __forceinline__ void cp16f(uint32_t dst, const void* src) {
    asm volatile("cp.async.cg.shared.global [%0], [%1], 16;" :: "r"(dst), "l"(src));
}
#define CP_COMMIT() asm volatile("cp.async.commit_group;" ::: "memory")
#define CP_WAIT(n)  asm volatile("cp.async.wait_group %0;" :: "n"(n) : "memory")

// ---------------- CSR build ----------------
__global__ void k_zero_deg() {
    int i = blockIdx.x * blockDim.x + threadIdx.x;
    if (i < NN) g_deg[i] = 0;
}
__global__ void k_hist_edges(const int* __restrict__ ei) {
    int i = blockIdx.x * blockDim.x + threadIdx.x;
    if (i < EE) atomicAdd(&g_deg[ei[EE + i]], 1);
    else if (i < ETOT) atomicAdd(&g_deg[i - EE], 1);
}
__global__ void k_scan_part() {
    __shared__ int sh[512];
    int i = blockIdx.x * 512 + threadIdx.x;
    int v = (i < NN) ? g_deg[i] : 0;
    sh[threadIdx.x] = v;
    __syncthreads();
    #pragma unroll
    for (int off = 1; off < 512; off <<= 1) {
        int t = (threadIdx.x >= off) ? sh[threadIdx.x - off] : 0;
        __syncthreads();
        sh[threadIdx.x] += t;
        __syncthreads();
    }
    if (i < NN) g_rowptr[i] = sh[threadIdx.x] - v;
    if (threadIdx.x == 511) g_bsum[blockIdx.x] = sh[511];
}
__global__ void k_scan_boff() {
    __shared__ int sh[128];
    int i = threadIdx.x;
    int v = (i < SNB) ? g_bsum[i] : 0;
    sh[i] = v;
    __syncthreads();
    #pragma unroll
    for (int off = 1; off < 128; off <<= 1) {
        int t = (i >= off) ? sh[i - off] : 0;
        __syncthreads();
        sh[i] += t;
        __syncthreads();
    }
    if (i < SNB) g_boff[i] = sh[i] - v;
}
__global__ void k_scan_add() {
    int i = blockIdx.x * blockDim.x + threadIdx.x;
    if (i < NN) {
        int val = g_rowptr[i] + g_boff[i >> 9];
        g_rowptr[i] = val;
        g_cursor[i] = val;
    }
    if (i == 0) g_rowptr[NN] = ETOT;
}
__global__ void k_scatter_edges(const int* __restrict__ ei) {
    int i = blockIdx.x * blockDim.x + threadIdx.x;
    int src, dst;
    if (i < EE)        { src = ei[i]; dst = ei[EE + i]; }
    else if (i < ETOT) { src = i - EE; dst = i - EE; }
    else return;
    int pos = atomicAdd(&g_cursor[dst], 1);
    g_csrsrc[pos] = src;
}
__global__ void k_gbounds(const int* __restrict__ batch) {
    int i = blockIdx.x * blockDim.x + threadIdx.x;
    if (i >= NN) return;
    int b = batch[i];
    int prev = (i == 0) ? -1 : batch[i - 1];
    for (int g = prev + 1; g <= b; g++) g_gstart[g] = i;
    if (i == NN - 1)
        for (int g = b + 1; g <= GG; g++) g_gstart[g] = NN;
}

// ---------------- fp32 -> bf16 ----------------
__global__ void k_split_x(const float* __restrict__ x, __nv_bfloat16* __restrict__ hi) {
    int i = blockIdx.x * 256 + threadIdx.x;
    hi[i] = __float2bfloat16(x[i]);
}
__global__ void k_split_w(const float* __restrict__ W1, const float* __restrict__ W2) {
    int i = blockIdx.x * 256 + threadIdx.x;
    int which = i >> 16;
    int j = i & 65535;
    int n = j >> 8, k = j & 255;
    const float* W = which ? W2 : W1;
    float v = W[k * 256 + n];
    __nv_bfloat16 h = __float2bfloat16(v);
    float r = v - __bfloat162float(h);
    if (which) { g_w2hi[j] = h; g_w2lo[j] = __float2bfloat16(r); }
    else       { g_w1hi[j] = h; g_w1lo[j] = __float2bfloat16(r); }
}

// ---------------- GEMM: h[M,256] = A(bf16) @ [Whi+Wlo]^T + fused att epilogue ----------------
#define STG   81920
#define OA_HI 0
#define OB_HI 16384
#define OB_LO 49152
#define SMEM_TOT (2 * STG)

__global__ void __launch_bounds__(256) k_gemm_att(
    const __nv_bfloat16* __restrict__ Ahi,
    const __nv_bfloat16* __restrict__ Bhi, const __nv_bfloat16* __restrict__ Blo,
    __nv_bfloat162* __restrict__ Hout,
    const float* __restrict__ as, const float* __restrict__ ad,
    int M)
{
    extern __shared__ char smem[];
    uint32_t sb = su32(smem);
    const int tid = threadIdx.x, wid = tid >> 5, lane = tid & 31;
    const int row0 = blockIdx.x * 128;
    const int wm = wid & 3;
    const int wn = wid >> 2;

    float acc[2][16][4];
    #pragma unroll
    for (int a = 0; a < 2; a++)
        #pragma unroll
        for (int b = 0; b < 16; b++)
            #pragma unroll
            for (int q = 0; q < 4; q++) acc[a][b][q] = 0.f;

    auto load_chunk = [&](int c, int stage) {
        uint32_t base = sb + stage * STG;
        #pragma unroll
        for (int it = 0; it < 4; it++) {
            int u = tid + it * 256;
            int r = u >> 3, j = u & 7;
            uint32_t sw = swz(r * 128 + j * 16);
            int m = row0 + r;
            int mc = m < M ? m : (M - 1);
            uint32_t sz = (m < M) ? 16u : 0u;
            size_t gi = (size_t)mc * 256 + c * 64 + j * 8;
            cp16(base + OA_HI + sw, Ahi + gi, sz);
        }
        #pragma unroll
        for (int it = 0; it < 8; it++) {
            int u = tid + it * 256;
            int r = u >> 3, j = u & 7;
            uint32_t sw = swz(r * 128 + j * 16);
            size_t gi = (size_t)r * 256 + c * 64 + j * 8;
            cp16f(base + OB_HI + sw, Bhi + gi);
            cp16f(base + OB_LO + sw, Blo + gi);
        }
    };

    load_chunk(0, 0);
    CP_COMMIT();

    const int lrow = lane & 15;
    const int lcol = (lane >> 4) * 8;
    const int cb = wn * 128;

    for (int c = 0; c < 4; c++) {
        int stage = c & 1;
        if (c < 3) { load_chunk(c + 1, stage ^ 1); CP_COMMIT(); CP_WAIT(1); }
        else       { CP_WAIT(0); }
        __syncthreads();
        uint32_t base = sb + stage * STG;

        #pragma unroll
        for (int kk = 0; kk < 4; kk++) {
            uint32_t ah[2][4];
            #pragma unroll
            for (int mt = 0; mt < 2; mt++) {
                uint32_t off = swz((wm * 32 + mt * 16 + lrow) * 128 + (kk * 16 + lcol) * 2);
                ldsm_x4(ah[mt], base + OA_HI + off);
            }
            #pragma unroll
            for (int ntp = 0; ntp < 8; ntp++) {
                int q = lane >> 3;
                int nrow = cb + ntp * 16 + (q >> 1) * 8 + (lane & 7);
                int kcol = kk * 16 + (q & 1) * 8;
                uint32_t boff = swz(nrow * 128 + kcol * 2);
                uint32_t bh[4], bl[4];
                ldsm_x4(bh, base + OB_HI + boff);
                ldsm_x4(bl, base + OB_LO + boff);
                #pragma unroll
                for (int sub = 0; sub < 2; sub++) {
                    int nt = ntp * 2 + sub;
                    #pragma unroll
                    for (int mt = 0; mt < 2; mt++) {
                        mma_bf16(acc[mt][nt], ah[mt], bh + sub * 2);
                        mma_bf16(acc[mt][nt], ah[mt], bl + sub * 2);
                    }
                }
            }
        }
        __syncthreads();
    }

    // ---- epilogue: attention coefficients + bf16 h store ----
    float sa[4][2], sd[4][2];
    #pragma unroll
    for (int i = 0; i < 4; i++) { sa[i][0] = sa[i][1] = 0.f; sd[i][0] = sd[i][1] = 0.f; }

    #pragma unroll
    for (int nt = 0; nt < 16; nt++) {
        int c0 = cb + nt * 8 + (lane & 3) * 2;
        float w0 = __ldg(as + c0), w1 = __ldg(as + c0 + 1);
        float v0 = __ldg(ad + c0), v1 = __ldg(ad + c0 + 1);
        int hl = nt >> 3;
        #pragma unroll
        for (int mt = 0; mt < 2; mt++) {
            sa[mt * 2 + 0][hl] += acc[mt][nt][0] * w0 + acc[mt][nt][1] * w1;
            sa[mt * 2 + 1][hl] += acc[mt][nt][2] * w0 + acc[mt][nt][3] * w1;
            sd[mt * 2 + 0][hl] += acc[mt][nt][0] * v0 + acc[mt][nt][1] * v1;
            sd[mt * 2 + 1][hl] += acc[mt][nt][2] * v0 + acc[mt][nt][3] * v1;
        }
    }
    #pragma unroll
    for (int i = 0; i < 4; i++)
        #pragma unroll
        for (int hl = 0; hl < 2; hl++) {
            sa[i][hl] += __shfl_xor_sync(0xffffffff, sa[i][hl], 1);
            sa[i][hl] += __shfl_xor_sync(0xffffffff, sa[i][hl], 2);
            sd[i][hl] += __shfl_xor_sync(0xffffffff, sd[i][hl], 1);
            sd[i][hl] += __shfl_xor_sync(0xffffffff, sd[i][hl], 2);
        }
    if ((lane & 3) == 0) {
        #pragma unroll
        for (int mt = 0; mt < 2; mt++)
            #pragma unroll
            for (int rh = 0; rh < 2; rh++) {
                int r = row0 + wm * 32 + mt * 16 + (lane >> 2) + rh * 8;
                if (r < M) {
                    #pragma unroll
                    for (int hl = 0; hl < 2; hl++) {
                        g_asrc[r * 4 + wn * 2 + hl] = sa[mt * 2 + rh][hl];
                        g_adst[r * 4 + wn * 2 + hl] = sd[mt * 2 + rh][hl];
                    }
                }
            }
    }

    #pragma unroll
    for (int mt = 0; mt < 2; mt++) {
        int r0 = row0 + wm * 32 + mt * 16 + (lane >> 2);
        int r1 = r0 + 8;
        #pragma unroll
        for (int nt = 0; nt < 16; nt++) {
            int cc2 = (cb >> 1) + nt * 4 + (lane & 3);
            if (r0 < M) Hout[(size_t)r0 * 128 + cc2] = __floats2bfloat162_rn(acc[mt][nt][0], acc[mt][nt][1]);
            if (r1 < M) Hout[(size_t)r1 * 128 + cc2] = __floats2bfloat162_rn(acc[mt][nt][2], acc[mt][nt][3]);
        }
    }
}

// ---------------- warp-per-node GAT aggregation: lane owns 8 consecutive channels ----------------
__global__ void __launch_bounds__(256) k_agg_ln(
    const __nv_bfloat162* __restrict__ hb, const float* __restrict__ bias,
    const float* __restrict__ gamma, const float* __restrict__ beta,
    float* __restrict__ outf, __nv_bfloat162* __restrict__ ohi)
{
    int wid = threadIdx.x >> 5, lane = threadIdx.x & 31;
    int n = blockIdx.x * 8 + wid;
    if (n >= NN) return;
    int beg = g_rowptr[n], end = g_rowptr[n + 1];
    int head = lane >> 3;                 // 0..3 : this lane's head
    float adh = __ldg(g_adst + 4 * n + head);

    float acc[8];
    #pragma unroll
    for (int j = 0; j < 8; j++) acc[j] = 0.f;
    float den = 0.f;

    const int4* hrow = (const int4*)hb;   // h row = 32 int4 (512B); lane loads int4 #lane

    int s = __ldg(g_csrsrc + beg);        // prefetch first index
    for (int k = beg; k < end; k++) {
        int sc = s;
        if (k + 1 < end) s = __ldg(g_csrsrc + k + 1);
        float av = __ldg(g_asrc + 4 * sc + head);
        int4 v = __ldg(hrow + (size_t)sc * 32 + lane);
        float e = av + adh;
        e = (e > 0.f) ? e : NEG_SLOPE * e;
        float w = __expf(e);
        den += w;
        const __nv_bfloat162* pv = (const __nv_bfloat162*)&v;
        #pragma unroll
        for (int j = 0; j < 4; j++) {
            float2 f = __bfloat1622float2(pv[j]);
            acc[2 * j]     = fmaf(w, f.x, acc[2 * j]);
            acc[2 * j + 1] = fmaf(w, f.y, acc[2 * j + 1]);
        }
    }

    float inv = 1.0f / den;
    int c0 = lane * 8;                    // first channel owned by this lane
    float4 b0 = __ldg((const float4*)(bias + c0));
    float4 b1 = __ldg((const float4*)(bias + c0 + 4));
    float m[8];
    m[0] = acc[0] * inv + b0.x; m[1] = acc[1] * inv + b0.y;
    m[2] = acc[2] * inv + b0.z; m[3] = acc[3] * inv + b0.w;
    m[4] = acc[4] * inv + b1.x; m[5] = acc[5] * inv + b1.y;
    m[6] = acc[6] * inv + b1.z; m[7] = acc[7] * inv + b1.w;

    // warp-local LayerNorm over 256 channels
    float sum = ((m[0] + m[1]) + (m[2] + m[3])) + ((m[4] + m[5]) + (m[6] + m[7]));
    #pragma unroll
    for (int off = 16; off > 0; off >>= 1) sum += __shfl_xor_sync(0xffffffff, sum, off);
    float mu = sum * (1.0f / 256.0f);
    float d[8];
    float q = 0.f;
    #pragma unroll
    for (int j = 0; j < 8; j++) { d[j] = m[j] - mu; q = fmaf(d[j], d[j], q); }
    #pragma unroll
    for (int off = 16; off > 0; off >>= 1) q += __shfl_xor_sync(0xffffffff, q, off);
    float invs = rsqrtf(q * (1.0f / 256.0f) + 1e-5f);

    float4 g0 = __ldg((const float4*)(gamma + c0));
    float4 g1 = __ldg((const float4*)(gamma + c0 + 4));
    float4 t0 = __ldg((const float4*)(beta + c0));
    float4 t1 = __ldg((const float4*)(beta + c0 + 4));
    float y[8];
    y[0] = fmaxf(d[0] * invs * g0.x + t0.x, 0.f);
    y[1] = fmaxf(d[1] * invs * g0.y + t0.y, 0.f);
    y[2] = fmaxf(d[2] * invs * g0.z + t0.z, 0.f);
    y[3] = fmaxf(d[3] * invs * g0.w + t0.w, 0.f);
    y[4] = fmaxf(d[4] * invs * g1.x + t1.x, 0.f);
    y[5] = fmaxf(d[5] * invs * g1.y + t1.y, 0.f);
    y[6] = fmaxf(d[6] * invs * g1.z + t1.z, 0.f);
    y[7] = fmaxf(d[7] * invs * g1.w + t1.w, 0.f);

    if (outf) {
        float* ob = outf + (size_t)n * DD + c0;
        *(float4*)(ob)     = make_float4(y[0], y[1], y[2], y[3]);
        *(float4*)(ob + 4) = make_float4(y[4], y[5], y[6], y[7]);
    }
    if (ohi) {
        __nv_bfloat162 p0 = __floats2bfloat162_rn(y[0], y[1]);
        __nv_bfloat162 p1 = __floats2bfloat162_rn(y[2], y[3]);
        __nv_bfloat162 p2 = __floats2bfloat162_rn(y[4], y[5]);
        __nv_bfloat162 p3 = __floats2bfloat162_rn(y[6], y[7]);
        int4 packed;
        packed.x = *(const int*)&p0; packed.y = *(const int*)&p1;
        packed.z = *(const int*)&p2; packed.w = *(const int*)&p3;
        ((int4*)ohi)[(size_t)n * 32 + lane] = packed;
    }
}

// ---------------- global mean pool (float2) ----------------
__global__ void k_pool(const float* __restrict__ h) {
    int g = blockIdx.x;
    int col2 = threadIdx.x;
    int s = g_gstart[g], e = g_gstart[g + 1];
    float sum0 = 0.f, sum1 = 0.f;
    const float2* p = (const float2*)h + col2;
    for (int i = s; i < e; i++) {
        float2 v = __ldg(p + (size_t)i * 128);
        sum0 += v.x; sum1 += v.y;
    }
    float invc = 1.0f / (float)max(e - s, 1);
    g_pooled[g * DD + 2 * col2]     = sum0 * invc;
    g_pooled[g * DD + 2 * col2 + 1] = sum1 * invc;
}

// ---------------- final MLP ----------------
__global__ void k_mlp(const float* __restrict__ lw1, const float* __restrict__ lb1,
                      const float* __restrict__ lw2, const float* __restrict__ lb2,
                      float* __restrict__ out) {
    __shared__ float p[DD];
    __shared__ float hid[HIDC];
    int g = blockIdx.x, tid = threadIdx.x;
    for (int i = tid; i < DD; i += 64) p[i] = g_pooled[g * DD + i];
    __syncthreads();
    float s = lb1[tid];
    #pragma unroll 8
    for (int k = 0; k < DD; k++) s = fmaf(p[k], lw1[k * HIDC + tid], s);
    hid[tid] = fmaxf(s, 0.f);
    __syncthreads();
    if (tid < 2) {
        float o = lb2[tid];
        #pragma unroll
        for (int k = 0; k < HIDC; k++) o = fmaf(hid[k], lw2[k * 2 + tid], o);
        out[g * 2 + tid] = o;
    }
}

// ---------------- host launcher ----------------
extern "C" void kernel_launch(void* const* d_in, const int* in_sizes, int n_in,
                              void* d_out, int out_size) {
    const float* x   = (const float*)d_in[0];
    const int*   ei  = (const int*)d_in[1];
    const int*   bat = (const int*)d_in[2];
    const float* W1  = (const float*)d_in[3];
    const float* as1 = (const float*)d_in[4];
    const float* ad1 = (const float*)d_in[5];
    const float* b1  = (const float*)d_in[6];
    const float* g1  = (const float*)d_in[7];
    const float* be1 = (const float*)d_in[8];
    const float* W2  = (const float*)d_in[9];
    const float* as2 = (const float*)d_in[10];
    const float* ad2 = (const float*)d_in[11];
    const float* b2  = (const float*)d_in[12];
    const float* g2  = (const float*)d_in[13];
    const float* be2 = (const float*)d_in[14];
    const float* lw1 = (const float*)d_in[15];
    const float* lb1 = (const float*)d_in[16];
    const float* lw2 = (const float*)d_in[17];
    const float* lb2 = (const float*)d_in[18];
    float* out = (float*)d_out;

    cudaFuncSetAttribute(k_gemm_att, cudaFuncAttributeMaxDynamicSharedMemorySize, SMEM_TOT);

    float *bo;
    __nv_bfloat162 *hb;
    __nv_bfloat16 *ahi, *w1h, *w1l, *w2h, *w2l;
    cudaGetSymbolAddress((void**)&hb, g_hb);
    cudaGetSymbolAddress((void**)&bo, g_o);
    cudaGetSymbolAddress((void**)&ahi, g_ahi);
    cudaGetSymbolAddress((void**)&w1h, g_w1hi);
    cudaGetSymbolAddress((void**)&w1l, g_w1lo);
    cudaGetSymbolAddress((void**)&w2h, g_w2hi);
    cudaGetSymbolAddress((void**)&w2l, g_w2lo);

    int gemm_blocks = (NN + 127) / 128;
    int agg_blocks = (NN + 7) / 8;

    // independent prework first so k_gemm_att lands at the ncu capture slot
    k_split_x<<<NN * DD / 256, 256>>>(x, ahi);                      // 1
    k_split_w<<<2 * DD * DD / 256, 256>>>(W1, W2);                  // 2
    k_gbounds<<<(NN + 255) / 256, 256>>>(bat);                      // 3
    k_gemm_att<<<gemm_blocks, 256, SMEM_TOT>>>(ahi, w1h, w1l, hb, as1, ad1, NN);  // 4

    // CSR build (must finish before agg1)
    k_zero_deg<<<(NN + 255) / 256, 256>>>();                        // 5
    k_hist_edges<<<(ETOT + 255) / 256, 256>>>(ei);                  // 6
    k_scan_part<<<SNB, 512>>>();                                    // 7
    k_scan_boff<<<1, 128>>>();                                      // 8
    k_scan_add<<<(NN + 255) / 256, 256>>>();                        // 9
    k_scatter_edges<<<(ETOT + 255) / 256, 256>>>(ei);               // 10

    // ---- layer 1 agg ----
    k_agg_ln<<<agg_blocks, 256>>>(hb, b1, g1, be1, nullptr, (__nv_bfloat162*)ahi);

    // ---- layer 2 ----
    k_gemm_att<<<gemm_blocks, 256, SMEM_TOT>>>(ahi, w2h, w2l, hb, as2, ad2, NN);
    k_agg_ln<<<agg_blocks, 256>>>(hb, b2, g2, be2, bo, nullptr);

    // ---- pool + MLP ----
    k_pool<<<GG, 128>>>(bo);
    k_mlp<<<GG, 64>>>(lw1, lb1, lw2, lb2, out);
}

// round 11
// speedup vs baseline: 1.4052x; 1.0381x over previous
#include <cuda_runtime.h>
#include <cuda_bf16.h>
#include <cstdint>
#include <math.h>

#define NN 50000
#define EE 400000
#define ETOT (EE + NN)
#define DD 256
#define HEADS 4
#define HIDC 64
#define GG 64
#define NEG_SLOPE 0.2f

// ---------------- static device scratch ----------------
__device__ __nv_bfloat162 g_hb[NN * 128];
__device__ float g_o[NN * DD];
__device__ __nv_bfloat16 g_ahi[NN * DD];
__device__ __nv_bfloat16 g_w1hi[DD * DD], g_w1lo[DD * DD];
__device__ __nv_bfloat16 g_w2hi[DD * DD], g_w2lo[DD * DD];
__device__ float g_asrc[NN * HEADS];
__device__ float g_adst[NN * HEADS];
__device__ int   g_deg[NN];
__device__ int   g_rowptr[NN + 1];
__device__ int   g_cursor[NN];
__device__ int   g_csrsrc[ETOT];
__device__ int   g_gstart[GG + 1];
__device__ float g_pooled[GG * DD];
#define SNB 98
__device__ int   g_bsum[SNB];
__device__ int   g_boff[SNB];

// ---------------- helpers ----------------
__device__ __forceinline__ uint32_t su32(const void* p) {
    uint32_t a;
    asm("{ .reg .u64 t; cvta.to.shared.u64 t, %1; cvt.u32.u64 %0, t; }" : "=r"(a) : "l"(p));
    return a;
}
__device__ __forceinline__ uint32_t swz(uint32_t off) {
    return off ^ ((off >> 3) & 0x70);
}
__device__ __forceinline__ void ldsm_x4(uint32_t* r, uint32_t addr) {
    asm volatile("ldmatrix.sync.aligned.m8n8.x4.shared.b16 {%0,%1,%2,%3}, [%4];"
                 : "=r"(r[0]), "=r"(r[1]), "=r"(r[2]), "=r"(r[3]) : "r"(addr));
}
__device__ __forceinline__ void mma_bf16(float* c, const uint32_t* a, const uint32_t* b) {
    asm volatile("mma.sync.aligned.m16n8k16.row.col.f32.bf16.bf16.f32 "
                 "{%0,%1,%2,%3}, {%4,%5,%6,%7}, {%8,%9}, {%0,%1,%2,%3};"
                 : "+f"(c[0]), "+f"(c[1]), "+f"(c[2]), "+f"(c[3])
                 : "r"(a[0]), "r"(a[1]), "r"(a[2]), "r"(a[3]), "r"(b[0]), "r"(b[1]));
}
__device__ __forceinline__ void cp16(uint32_t dst, const void* src, uint32_t sz) {
    asm volatile("cp.async.cg.shared.global [%0], [%1], 16, %2;" :: "r"(dst), "l"(src), "r"(sz));
}
__device__ __forceinline__ void cp16f(uint32_t dst, const void* src) {
    asm volatile("cp.async.cg.shared.global [%0], [%1], 16;" :: "r"(dst), "l"(src));
}
#define CP_COMMIT() asm volatile("cp.async.commit_group;" ::: "memory")
#define CP_WAIT(n)  asm volatile("cp.async.wait_group %0;" :: "n"(n) : "memory")

// ---------------- CSR build ----------------
__global__ void k_zero_deg() {
    int i = blockIdx.x * blockDim.x + threadIdx.x;
    if (i < NN) g_deg[i] = 0;
}
__global__ void k_hist_edges(const int* __restrict__ ei) {
    int i = blockIdx.x * blockDim.x + threadIdx.x;
    if (i < EE) atomicAdd(&g_deg[ei[EE + i]], 1);
    else if (i < ETOT) atomicAdd(&g_deg[i - EE], 1);
}
__global__ void k_scan_part() {
    __shared__ int sh[512];
    int i = blockIdx.x * 512 + threadIdx.x;
    int v = (i < NN) ? g_deg[i] : 0;
    sh[threadIdx.x] = v;
    __syncthreads();
    #pragma unroll
    for (int off = 1; off < 512; off <<= 1) {
        int t = (threadIdx.x >= off) ? sh[threadIdx.x - off] : 0;
        __syncthreads();
        sh[threadIdx.x] += t;
        __syncthreads();
    }
    if (i < NN) g_rowptr[i] = sh[threadIdx.x] - v;
    if (threadIdx.x == 511) g_bsum[blockIdx.x] = sh[511];
}
__global__ void k_scan_boff() {
    __shared__ int sh[128];
    int i = threadIdx.x;
    int v = (i < SNB) ? g_bsum[i] : 0;
    sh[i] = v;
    __syncthreads();
    #pragma unroll
    for (int off = 1; off < 128; off <<= 1) {
        int t = (i >= off) ? sh[i - off] : 0;
        __syncthreads();
        sh[i] += t;
        __syncthreads();
    }
    if (i < SNB) g_boff[i] = sh[i] - v;
}
__global__ void k_scan_add() {
    int i = blockIdx.x * blockDim.x + threadIdx.x;
    if (i < NN) {
        int val = g_rowptr[i] + g_boff[i >> 9];
        g_rowptr[i] = val;
        g_cursor[i] = val;
    }
    if (i == 0) g_rowptr[NN] = ETOT;
}
__global__ void k_scatter_edges(const int* __restrict__ ei) {
    int i = blockIdx.x * blockDim.x + threadIdx.x;
    int src, dst;
    if (i < EE)        { src = ei[i]; dst = ei[EE + i]; }
    else if (i < ETOT) { src = i - EE; dst = i - EE; }
    else return;
    int pos = atomicAdd(&g_cursor[dst], 1);
    g_csrsrc[pos] = src;
}
__global__ void k_gbounds(const int* __restrict__ batch) {
    int i = blockIdx.x * blockDim.x + threadIdx.x;
    if (i >= NN) return;
    int b = batch[i];
    int prev = (i == 0) ? -1 : batch[i - 1];
    for (int g = prev + 1; g <= b; g++) g_gstart[g] = i;
    if (i == NN - 1)
        for (int g = b + 1; g <= GG; g++) g_gstart[g] = NN;
}

// ---------------- fp32 -> bf16 ----------------
__global__ void k_split_x(const float4* __restrict__ x4, __nv_bfloat162* __restrict__ hi2) {
    int i = blockIdx.x * 256 + threadIdx.x;   // NN*DD/4 elements
    float4 v = x4[i];
    hi2[2 * i]     = __floats2bfloat162_rn(v.x, v.y);
    hi2[2 * i + 1] = __floats2bfloat162_rn(v.z, v.w);
}
__global__ void k_split_w(const float* __restrict__ W1, const float* __restrict__ W2) {
    int i = blockIdx.x * 256 + threadIdx.x;
    int which = i >> 16;
    int j = i & 65535;
    int n = j >> 8, k = j & 255;
    const float* W = which ? W2 : W1;
    float v = W[k * 256 + n];
    __nv_bfloat16 h = __float2bfloat16(v);
    float r = v - __bfloat162float(h);
    if (which) { g_w2hi[j] = h; g_w2lo[j] = __float2bfloat16(r); }
    else       { g_w1hi[j] = h; g_w1lo[j] = __float2bfloat16(r); }
}

// ---------------- GEMM (512 thr, 16 warps, warp=32x64): h = A(bf16) @ [Whi+Wlo]^T ----------------
#define STG   81920
#define OA_HI 0
#define OB_HI 16384
#define OB_LO 49152
#define SMEM_TOT (2 * STG)

__global__ void __launch_bounds__(512) k_gemm_att(
    const __nv_bfloat16* __restrict__ Ahi,
    const __nv_bfloat16* __restrict__ Bhi, const __nv_bfloat16* __restrict__ Blo,
    __nv_bfloat162* __restrict__ Hout,
    const float* __restrict__ as, const float* __restrict__ ad,
    int M)
{
    extern __shared__ char smem[];
    uint32_t sb = su32(smem);
    const int tid = threadIdx.x, wid = tid >> 5, lane = tid & 31;
    const int row0 = blockIdx.x * 128;
    const int wm = wid & 3;        // 4 row groups of 32
    const int wn = wid >> 2;       // 4 col groups of 64

    float acc[2][8][4];
    #pragma unroll
    for (int a = 0; a < 2; a++)
        #pragma unroll
        for (int b = 0; b < 8; b++)
            #pragma unroll
            for (int q = 0; q < 4; q++) acc[a][b][q] = 0.f;

    auto load_chunk = [&](int c, int stage) {
        uint32_t base = sb + stage * STG;
        #pragma unroll
        for (int it = 0; it < 2; it++) {          // A: 1024 16B slots / 512 thr
            int u = tid + it * 512;
            int r = u >> 3, j = u & 7;
            uint32_t sw = swz(r * 128 + j * 16);
            int m = row0 + r;
            int mc = m < M ? m : (M - 1);
            uint32_t sz = (m < M) ? 16u : 0u;
            size_t gi = (size_t)mc * 256 + c * 64 + j * 8;
            cp16(base + OA_HI + sw, Ahi + gi, sz);
        }
        #pragma unroll
        for (int it = 0; it < 4; it++) {          // B: 2048 16B slots / 512 thr
            int u = tid + it * 512;
            int r = u >> 3, j = u & 7;
            uint32_t sw = swz(r * 128 + j * 16);
            size_t gi = (size_t)r * 256 + c * 64 + j * 8;
            cp16f(base + OB_HI + sw, Bhi + gi);
            cp16f(base + OB_LO + sw, Blo + gi);
        }
    };

    load_chunk(0, 0);
    CP_COMMIT();

    const int lrow = lane & 15;
    const int lcol = (lane >> 4) * 8;
    const int cb = wn * 64;

    for (int c = 0; c < 4; c++) {
        int stage = c & 1;
        if (c < 3) { load_chunk(c + 1, stage ^ 1); CP_COMMIT(); CP_WAIT(1); }
        else       { CP_WAIT(0); }
        __syncthreads();
        uint32_t base = sb + stage * STG;

        #pragma unroll
        for (int kk = 0; kk < 4; kk++) {
            uint32_t ah[2][4];
            #pragma unroll
            for (int mt = 0; mt < 2; mt++) {
                uint32_t off = swz((wm * 32 + mt * 16 + lrow) * 128 + (kk * 16 + lcol) * 2);
                ldsm_x4(ah[mt], base + OA_HI + off);
            }
            #pragma unroll
            for (int ntp = 0; ntp < 4; ntp++) {
                int q = lane >> 3;
                int nrow = cb + ntp * 16 + (q >> 1) * 8 + (lane & 7);
                int kcol = kk * 16 + (q & 1) * 8;
                uint32_t boff = swz(nrow * 128 + kcol * 2);
                uint32_t bh[4], bl[4];
                ldsm_x4(bh, base + OB_HI + boff);
                ldsm_x4(bl, base + OB_LO + boff);
                #pragma unroll
                for (int sub = 0; sub < 2; sub++) {
                    int nt = ntp * 2 + sub;
                    #pragma unroll
                    for (int mt = 0; mt < 2; mt++) {
                        mma_bf16(acc[mt][nt], ah[mt], bh + sub * 2);
                        mma_bf16(acc[mt][nt], ah[mt], bl + sub * 2);
                    }
                }
            }
        }
        __syncthreads();
    }

    // ---- epilogue: attention coefficients (head = wn) + bf16 h store ----
    float sa[4], sd[4];    // [mt*2 + rhalf]
    #pragma unroll
    for (int i = 0; i < 4; i++) { sa[i] = 0.f; sd[i] = 0.f; }

    #pragma unroll
    for (int nt = 0; nt < 8; nt++) {
        int c0 = cb + nt * 8 + (lane & 3) * 2;
        float w0 = __ldg(as + c0), w1 = __ldg(as + c0 + 1);
        float v0 = __ldg(ad + c0), v1 = __ldg(ad + c0 + 1);
        #pragma unroll
        for (int mt = 0; mt < 2; mt++) {
            sa[mt * 2 + 0] += acc[mt][nt][0] * w0 + acc[mt][nt][1] * w1;
            sa[mt * 2 + 1] += acc[mt][nt][2] * w0 + acc[mt][nt][3] * w1;
            sd[mt * 2 + 0] += acc[mt][nt][0] * v0 + acc[mt][nt][1] * v1;
            sd[mt * 2 + 1] += acc[mt][nt][2] * v0 + acc[mt][nt][3] * v1;
        }
    }
    #pragma unroll
    for (int i = 0; i < 4; i++) {
        sa[i] += __shfl_xor_sync(0xffffffff, sa[i], 1);
        sa[i] += __shfl_xor_sync(0xffffffff, sa[i], 2);
        sd[i] += __shfl_xor_sync(0xffffffff, sd[i], 1);
        sd[i] += __shfl_xor_sync(0xffffffff, sd[i], 2);
    }
    if ((lane & 3) == 0) {
        #pragma unroll
        for (int mt = 0; mt < 2; mt++)
            #pragma unroll
            for (int rh = 0; rh < 2; rh++) {
                int r = row0 + wm * 32 + mt * 16 + (lane >> 2) + rh * 8;
                if (r < M) {
                    g_asrc[r * 4 + wn] = sa[mt * 2 + rh];
                    g_adst[r * 4 + wn] = sd[mt * 2 + rh];
                }
            }
    }

    #pragma unroll
    for (int mt = 0; mt < 2; mt++) {
        int r0 = row0 + wm * 32 + mt * 16 + (lane >> 2);
        int r1 = r0 + 8;
        #pragma unroll
        for (int nt = 0; nt < 8; nt++) {
            int cc2 = (cb >> 1) + nt * 4 + (lane & 3);
            if (r0 < M) Hout[(size_t)r0 * 128 + cc2] = __floats2bfloat162_rn(acc[mt][nt][0], acc[mt][nt][1]);
            if (r1 < M) Hout[(size_t)r1 * 128 + cc2] = __floats2bfloat162_rn(acc[mt][nt][2], acc[mt][nt][3]);
        }
    }
}

// ---------------- warp-per-node GAT aggregation: 2-deep pipeline ----------------
__global__ void __launch_bounds__(256) k_agg_ln(
    const __nv_bfloat162* __restrict__ hb, const float* __restrict__ bias,
    const float* __restrict__ gamma, const float* __restrict__ beta,
    float* __restrict__ outf, __nv_bfloat162* __restrict__ ohi)
{
    int wid = threadIdx.x >> 5, lane = threadIdx.x & 31;
    int n = blockIdx.x * 8 + wid;
    if (n >= NN) return;
    int beg = g_rowptr[n], end = g_rowptr[n + 1];
    int head = lane >> 3;
    float adh = __ldg(g_adst + 4 * n + head);

    float acc[8];
    #pragma unroll
    for (int j = 0; j < 8; j++) acc[j] = 0.f;
    float den = 0.f;

    const int4* hrow = (const int4*)hb;

    // software pipeline: indices 2 ahead, data 1 ahead
    int s_cur = __ldg(g_csrsrc + beg);
    int s_nxt = (beg + 1 < end) ? __ldg(g_csrsrc + beg + 1) : 0;
    float av = __ldg(g_asrc + 4 * s_cur + head);
    int4  v  = __ldg(hrow + (size_t)s_cur * 32 + lane);

    for (int k = beg; k < end; k++) {
        float av_n; int4 v_n;
        if (k + 1 < end) {
            av_n = __ldg(g_asrc + 4 * s_nxt + head);
            v_n  = __ldg(hrow + (size_t)s_nxt * 32 + lane);
        }
        int s_n2 = (k + 2 < end) ? __ldg(g_csrsrc + k + 2) : 0;

        float e = av + adh;
        e = (e > 0.f) ? e : NEG_SLOPE * e;
        float w = __expf(e);
        den += w;
        const __nv_bfloat162* pv = (const __nv_bfloat162*)&v;
        #pragma unroll
        for (int j = 0; j < 4; j++) {
            float2 f = __bfloat1622float2(pv[j]);
            acc[2 * j]     = fmaf(w, f.x, acc[2 * j]);
            acc[2 * j + 1] = fmaf(w, f.y, acc[2 * j + 1]);
        }
        av = av_n; v = v_n; s_nxt = s_n2;
    }

    float inv = 1.0f / den;
    int c0 = lane * 8;
    float4 b0 = __ldg((const float4*)(bias + c0));
    float4 b1 = __ldg((const float4*)(bias + c0 + 4));
    float m[8];
    m[0] = acc[0] * inv + b0.x; m[1] = acc[1] * inv + b0.y;
    m[2] = acc[2] * inv + b0.z; m[3] = acc[3] * inv + b0.w;
    m[4] = acc[4] * inv + b1.x; m[5] = acc[5] * inv + b1.y;
    m[6] = acc[6] * inv + b1.z; m[7] = acc[7] * inv + b1.w;

    float sum = ((m[0] + m[1]) + (m[2] + m[3])) + ((m[4] + m[5]) + (m[6] + m[7]));
    #pragma unroll
    for (int off = 16; off > 0; off >>= 1) sum += __shfl_xor_sync(0xffffffff, sum, off);
    float mu = sum * (1.0f / 256.0f);
    float d[8];
    float q = 0.f;
    #pragma unroll
    for (int j = 0; j < 8; j++) { d[j] = m[j] - mu; q = fmaf(d[j], d[j], q); }
    #pragma unroll
    for (int off = 16; off > 0; off >>= 1) q += __shfl_xor_sync(0xffffffff, q, off);
    float invs = rsqrtf(q * (1.0f / 256.0f) + 1e-5f);

    float4 g0 = __ldg((const float4*)(gamma + c0));
    float4 g1 = __ldg((const float4*)(gamma + c0 + 4));
    float4 t0 = __ldg((const float4*)(beta + c0));
    float4 t1 = __ldg((const float4*)(beta + c0 + 4));
    float y[8];
    y[0] = fmaxf(d[0] * invs * g0.x + t0.x, 0.f);
    y[1] = fmaxf(d[1] * invs * g0.y + t0.y, 0.f);
    y[2] = fmaxf(d[2] * invs * g0.z + t0.z, 0.f);
    y[3] = fmaxf(d[3] * invs * g0.w + t0.w, 0.f);
    y[4] = fmaxf(d[4] * invs * g1.x + t1.x, 0.f);
    y[5] = fmaxf(d[5] * invs * g1.y + t1.y, 0.f);
    y[6] = fmaxf(d[6] * invs * g1.z + t1.z, 0.f);
    y[7] = fmaxf(d[7] * invs * g1.w + t1.w, 0.f);

    if (outf) {
        float* ob = outf + (size_t)n * DD + c0;
        *(float4*)(ob)     = make_float4(y[0], y[1], y[2], y[3]);
        *(float4*)(ob + 4) = make_float4(y[4], y[5], y[6], y[7]);
    }
    if (ohi) {
        __nv_bfloat162 p0 = __floats2bfloat162_rn(y[0], y[1]);
        __nv_bfloat162 p1 = __floats2bfloat162_rn(y[2], y[3]);
        __nv_bfloat162 p2 = __floats2bfloat162_rn(y[4], y[5]);
        __nv_bfloat162 p3 = __floats2bfloat162_rn(y[6], y[7]);
        int4 packed;
        packed.x = *(const int*)&p0; packed.y = *(const int*)&p1;
        packed.z = *(const int*)&p2; packed.w = *(const int*)&p3;
        ((int4*)ohi)[(size_t)n * 32 + lane] = packed;
    }
}

// ---------------- global mean pool (float2) ----------------
__global__ void k_pool(const float* __restrict__ h) {
    int g = blockIdx.x;
    int col2 = threadIdx.x;
    int s = g_gstart[g], e = g_gstart[g + 1];
    float sum0 = 0.f, sum1 = 0.f;
    const float2* p = (const float2*)h + col2;
    for (int i = s; i < e; i++) {
        float2 v = __ldg(p + (size_t)i * 128);
        sum0 += v.x; sum1 += v.y;
    }
    float invc = 1.0f / (float)max(e - s, 1);
    g_pooled[g * DD + 2 * col2]     = sum0 * invc;
    g_pooled[g * DD + 2 * col2 + 1] = sum1 * invc;
}

// ---------------- final MLP ----------------
__global__ void k_mlp(const float* __restrict__ lw1, const float* __restrict__ lb1,
                      const float* __restrict__ lw2, const float* __restrict__ lb2,
                      float* __restrict__ out) {
    __shared__ float p[DD];
    __shared__ float hid[HIDC];
    int g = blockIdx.x, tid = threadIdx.x;
    for (int i = tid; i < DD; i += 64) p[i] = g_pooled[g * DD + i];
    __syncthreads();
    float s = lb1[tid];
    #pragma unroll 8
    for (int k = 0; k < DD; k++) s = fmaf(p[k], lw1[k * HIDC + tid], s);
    hid[tid] = fmaxf(s, 0.f);
    __syncthreads();
    if (tid < 2) {
        float o = lb2[tid];
        #pragma unroll
        for (int k = 0; k < HIDC; k++) o = fmaf(hid[k], lw2[k * 2 + tid], o);
        out[g * 2 + tid] = o;
    }
}

// ---------------- host launcher ----------------
extern "C" void kernel_launch(void* const* d_in, const int* in_sizes, int n_in,
                              void* d_out, int out_size) {
    const float* x   = (const float*)d_in[0];
    const int*   ei  = (const int*)d_in[1];
    const int*   bat = (const int*)d_in[2];
    const float* W1  = (const float*)d_in[3];
    const float* as1 = (const float*)d_in[4];
    const float* ad1 = (const float*)d_in[5];
    const float* b1  = (const float*)d_in[6];
    const float* g1  = (const float*)d_in[7];
    const float* be1 = (const float*)d_in[8];
    const float* W2  = (const float*)d_in[9];
    const float* as2 = (const float*)d_in[10];
    const float* ad2 = (const float*)d_in[11];
    const float* b2  = (const float*)d_in[12];
    const float* g2  = (const float*)d_in[13];
    const float* be2 = (const float*)d_in[14];
    const float* lw1 = (const float*)d_in[15];
    const float* lb1 = (const float*)d_in[16];
    const float* lw2 = (const float*)d_in[17];
    const float* lb2 = (const float*)d_in[18];
    float* out = (float*)d_out;

    cudaFuncSetAttribute(k_gemm_att, cudaFuncAttributeMaxDynamicSharedMemorySize, SMEM_TOT);

    float *bo;
    __nv_bfloat162 *hb;
    __nv_bfloat16 *ahi, *w1h, *w1l, *w2h, *w2l;
    cudaGetSymbolAddress((void**)&hb, g_hb);
    cudaGetSymbolAddress((void**)&bo, g_o);
    cudaGetSymbolAddress((void**)&ahi, g_ahi);
    cudaGetSymbolAddress((void**)&w1h, g_w1hi);
    cudaGetSymbolAddress((void**)&w1l, g_w1lo);
    cudaGetSymbolAddress((void**)&w2h, g_w2hi);
    cudaGetSymbolAddress((void**)&w2l, g_w2lo);

    int gemm_blocks = (NN + 127) / 128;
    int agg_blocks = (NN + 7) / 8;

    // independent prework first so k_gemm_att lands at the ncu capture slot
    k_split_x<<<NN * DD / 1024, 256>>>((const float4*)x, (__nv_bfloat162*)ahi);  // 1
    k_split_w<<<2 * DD * DD / 256, 256>>>(W1, W2);                  // 2
    k_gbounds<<<(NN + 255) / 256, 256>>>(bat);                      // 3
    k_gemm_att<<<gemm_blocks, 512, SMEM_TOT>>>(ahi, w1h, w1l, hb, as1, ad1, NN);  // 4

    // CSR build (must finish before agg1)
    k_zero_deg<<<(NN + 255) / 256, 256>>>();                        // 5
    k_hist_edges<<<(ETOT + 255) / 256, 256>>>(ei);                  // 6
    k_scan_part<<<SNB, 512>>>();                                    // 7
    k_scan_boff<<<1, 128>>>();                                      // 8
    k_scan_add<<<(NN + 255) / 256, 256>>>();                        // 9
    k_scatter_edges<<<(ETOT + 255) / 256, 256>>>(ei);               // 10

    // ---- layer 1 agg ----
    k_agg_ln<<<agg_blocks, 256>>>(hb, b1, g1, be1, nullptr, (__nv_bfloat162*)ahi);

    // ---- layer 2 ----
    k_gemm_att<<<gemm_blocks, 512, SMEM_TOT>>>(ahi, w2h, w2l, hb, as2, ad2, NN);
    k_agg_ln<<<agg_blocks, 256>>>(hb, b2, g2, be2, bo, nullptr);

    // ---- pool + MLP ----
    k_pool<<<GG, 128>>>(bo);
    k_mlp<<<GG, 64>>>(lw1, lb1, lw2, lb2, out);
}

// round 13
// speedup vs baseline: 1.8348x; 1.3058x over previous
#include <cuda_runtime.h>
#include <cuda_bf16.h>
#include <cstdint>
#include <math.h>

#define NN 50000
#define EE 400000
#define ETOT (EE + NN)
#define DD 256
#define HEADS 4
#define HIDC 64
#define GG 64
#define NEG_SLOPE 0.2f

// ---------------- static device scratch ----------------
__device__ __nv_bfloat162 g_hb[NN * 128];   // GEMM output h (bf16)
__device__ __nv_bfloat16 g_ahi[NN * DD];    // layer input (bf16); reused as agg output
__device__ __nv_bfloat16 g_w1hi[DD * DD], g_w1lo[DD * DD];
__device__ __nv_bfloat16 g_w2hi[DD * DD], g_w2lo[DD * DD];
__device__ float g_asrc[NN * HEADS];
__device__ float g_adst[NN * HEADS];
__device__ int   g_deg[NN];
__device__ int   g_rowptr[NN + 1];
__device__ int   g_cursor[NN];
__device__ int   g_csrsrc[ETOT];
__device__ int   g_gstart[GG + 1];
__device__ float g_pooled[GG * DD];
#define SNB 98
__device__ int   g_bsum[SNB];
__device__ int   g_boff[SNB];

// ---------------- helpers ----------------
__device__ __forceinline__ uint32_t su32(const void* p) {
    uint32_t a;
    asm("{ .reg .u64 t; cvta.to.shared.u64 t, %1; cvt.u32.u64 %0, t; }" : "=r"(a) : "l"(p));
    return a;
}
__device__ __forceinline__ uint32_t swz(uint32_t off) {
    return off ^ ((off >> 3) & 0x70);
}
__device__ __forceinline__ void ldsm_x4(uint32_t* r, uint32_t addr) {
    asm volatile("ldmatrix.sync.aligned.m8n8.x4.shared.b16 {%0,%1,%2,%3}, [%4];"
                 : "=r"(r[0]), "=r"(r[1]), "=r"(r[2]), "=r"(r[3]) : "r"(addr));
}
__device__ __forceinline__ void mma_bf16(float* c, const uint32_t* a, const uint32_t* b) {
    asm volatile("mma.sync.aligned.m16n8k16.row.col.f32.bf16.bf16.f32 "
                 "{%0,%1,%2,%3}, {%4,%5,%6,%7}, {%8,%9}, {%0,%1,%2,%3};"
                 : "+f"(c[0]), "+f"(c[1]), "+f"(c[2]), "+f"(c[3])
                 : "r"(a[0]), "r"(a[1]), "r"(a[2]), "r"(a[3]), "r"(b[0]), "r"(b[1]));
}
__device__ __forceinline__ void cp16(uint32_t dst, const void* src, uint32_t sz) {
    asm volatile("cp.async.cg.shared.global [%0], [%1], 16, %2;" :: "r"(dst), "l"(src), "r"(sz));
}
__device__ __forceinline__ void cp16f(uint32_t dst, const void* src) {
    asm volatile("cp.async.cg.shared.global [%0], [%1], 16;" :: "r"(dst), "l"(src));
}
#define CP_COMMIT() asm volatile("cp.async.commit_group;" ::: "memory")
#define CP_WAIT(n)  asm volatile("cp.async.wait_group %0;" :: "n"(n) : "memory")

// ---------------- CSR build ----------------
__global__ void k_zero_deg() {
    int i = blockIdx.x * blockDim.x + threadIdx.x;
    if (i < NN) g_deg[i] = 0;
    if (i < GG * DD) g_pooled[i] = 0.f;
}
__global__ void k_hist_edges(const int* __restrict__ ei) {
    int i = blockIdx.x * blockDim.x + threadIdx.x;
    if (i < EE) atomicAdd(&g_deg[ei[EE + i]], 1);
    else if (i < ETOT) atomicAdd(&g_deg[i - EE], 1);
}
__global__ void k_scan_part() {
    __shared__ int sh[512];
    int i = blockIdx.x * 512 + threadIdx.x;
    int v = (i < NN) ? g_deg[i] : 0;
    sh[threadIdx.x] = v;
    __syncthreads();
    #pragma unroll
    for (int off = 1; off < 512; off <<= 1) {
        int t = (threadIdx.x >= off) ? sh[threadIdx.x - off] : 0;
        __syncthreads();
        sh[threadIdx.x] += t;
        __syncthreads();
    }
    if (i < NN) g_rowptr[i] = sh[threadIdx.x] - v;
    if (threadIdx.x == 511) g_bsum[blockIdx.x] = sh[511];
}
__global__ void k_scan_boff() {
    __shared__ int sh[128];
    int i = threadIdx.x;
    int v = (i < SNB) ? g_bsum[i] : 0;
    sh[i] = v;
    __syncthreads();
    #pragma unroll
    for (int off = 1; off < 128; off <<= 1) {
        int t = (i >= off) ? sh[i - off] : 0;
        __syncthreads();
        sh[i] += t;
        __syncthreads();
    }
    if (i < SNB) g_boff[i] = sh[i] - v;
}
__global__ void k_scan_add() {
    int i = blockIdx.x * blockDim.x + threadIdx.x;
    if (i < NN) {
        int val = g_rowptr[i] + g_boff[i >> 9];
        g_rowptr[i] = val;
        g_cursor[i] = val;
    }
    if (i == 0) g_rowptr[NN] = ETOT;
}
__global__ void k_scatter_edges(const int* __restrict__ ei) {
    int i = blockIdx.x * blockDim.x + threadIdx.x;
    int src, dst;
    if (i < EE)        { src = ei[i]; dst = ei[EE + i]; }
    else if (i < ETOT) { src = i - EE; dst = i - EE; }
    else return;
    int pos = atomicAdd(&g_cursor[dst], 1);
    g_csrsrc[pos] = src;
}
__global__ void k_gbounds(const int* __restrict__ batch) {
    int i = blockIdx.x * blockDim.x + threadIdx.x;
    if (i >= NN) return;
    int b = batch[i];
    int prev = (i == 0) ? -1 : batch[i - 1];
    for (int g = prev + 1; g <= b; g++) g_gstart[g] = i;
    if (i == NN - 1)
        for (int g = b + 1; g <= GG; g++) g_gstart[g] = NN;
}

// ---------------- fp32 -> bf16 ----------------
__global__ void k_split_x(const float4* __restrict__ x4, __nv_bfloat162* __restrict__ hi2) {
    int i = blockIdx.x * 256 + threadIdx.x;
    float4 v = x4[i];
    hi2[2 * i]     = __floats2bfloat162_rn(v.x, v.y);
    hi2[2 * i + 1] = __floats2bfloat162_rn(v.z, v.w);
}
__global__ void k_split_w(const float* __restrict__ W1, const float* __restrict__ W2) {
    int i = blockIdx.x * 256 + threadIdx.x;
    int which = i >> 16;
    int j = i & 65535;
    int n = j >> 8, k = j & 255;
    const float* W = which ? W2 : W1;
    float v = W[k * 256 + n];
    __nv_bfloat16 h = __float2bfloat16(v);
    float r = v - __bfloat162float(h);
    if (which) { g_w2hi[j] = h; g_w2lo[j] = __float2bfloat16(r); }
    else       { g_w1hi[j] = h; g_w1lo[j] = __float2bfloat16(r); }
}

// ---------------- GEMM (512 thr, A bf16, W hi+lo 2-pass) + fused att epilogue ----------------
#define STG   81920
#define OA_HI 0
#define OB_HI 16384
#define OB_LO 49152
#define SMEM_TOT (2 * STG)

__global__ void __launch_bounds__(512) k_gemm_att(
    const __nv_bfloat16* __restrict__ Ahi,
    const __nv_bfloat16* __restrict__ Bhi, const __nv_bfloat16* __restrict__ Blo,
    __nv_bfloat162* __restrict__ Hout,
    const float* __restrict__ as, const float* __restrict__ ad,
    int M)
{
    extern __shared__ char smem[];
    uint32_t sb = su32(smem);
    const int tid = threadIdx.x, wid = tid >> 5, lane = tid & 31;
    const int row0 = blockIdx.x * 128;
    const int wm = wid & 3;        // 4 row groups of 32
    const int wn = wid >> 2;       // 4 col groups of 64

    float acc[2][8][4];
    #pragma unroll
    for (int a = 0; a < 2; a++)
        #pragma unroll
        for (int b = 0; b < 8; b++)
            #pragma unroll
            for (int q = 0; q < 4; q++) acc[a][b][q] = 0.f;

    auto load_chunk = [&](int c, int stage) {
        uint32_t base = sb + stage * STG;
        #pragma unroll
        for (int it = 0; it < 2; it++) {
            int u = tid + it * 512;
            int r = u >> 3, j = u & 7;
            uint32_t sw = swz(r * 128 + j * 16);
            int m = row0 + r;
            int mc = m < M ? m : (M - 1);
            uint32_t sz = (m < M) ? 16u : 0u;
            size_t gi = (size_t)mc * 256 + c * 64 + j * 8;
            cp16(base + OA_HI + sw, Ahi + gi, sz);
        }
        #pragma unroll
        for (int it = 0; it < 4; it++) {
            int u = tid + it * 512;
            int r = u >> 3, j = u & 7;
            uint32_t sw = swz(r * 128 + j * 16);
            size_t gi = (size_t)r * 256 + c * 64 + j * 8;
            cp16f(base + OB_HI + sw, Bhi + gi);
            cp16f(base + OB_LO + sw, Blo + gi);
        }
    };

    load_chunk(0, 0);
    CP_COMMIT();

    const int lrow = lane & 15;
    const int lcol = (lane >> 4) * 8;
    const int cb = wn * 64;

    for (int c = 0; c < 4; c++) {
        int stage = c & 1;
        if (c < 3) { load_chunk(c + 1, stage ^ 1); CP_COMMIT(); CP_WAIT(1); }
        else       { CP_WAIT(0); }
        __syncthreads();
        uint32_t base = sb + stage * STG;

        #pragma unroll
        for (int kk = 0; kk < 4; kk++) {
            uint32_t ah[2][4];
            #pragma unroll
            for (int mt = 0; mt < 2; mt++) {
                uint32_t off = swz((wm * 32 + mt * 16 + lrow) * 128 + (kk * 16 + lcol) * 2);
                ldsm_x4(ah[mt], base + OA_HI + off);
            }
            #pragma unroll
            for (int ntp = 0; ntp < 4; ntp++) {
                int q = lane >> 3;
                int nrow = cb + ntp * 16 + (q >> 1) * 8 + (lane & 7);
                int kcol = kk * 16 + (q & 1) * 8;
                uint32_t boff = swz(nrow * 128 + kcol * 2);
                uint32_t bh[4], bl[4];
                ldsm_x4(bh, base + OB_HI + boff);
                ldsm_x4(bl, base + OB_LO + boff);
                #pragma unroll
                for (int sub = 0; sub < 2; sub++) {
                    int nt = ntp * 2 + sub;
                    #pragma unroll
                    for (int mt = 0; mt < 2; mt++) {
                        mma_bf16(acc[mt][nt], ah[mt], bh + sub * 2);
                        mma_bf16(acc[mt][nt], ah[mt], bl + sub * 2);
                    }
                }
            }
        }
        __syncthreads();
    }

    // ---- epilogue: attention coefficients (head = wn) + bf16 h store ----
    float sa[4], sd[4];
    #pragma unroll
    for (int i = 0; i < 4; i++) { sa[i] = 0.f; sd[i] = 0.f; }

    #pragma unroll
    for (int nt = 0; nt < 8; nt++) {
        int c0 = cb + nt * 8 + (lane & 3) * 2;
        float w0 = __ldg(as + c0), w1 = __ldg(as + c0 + 1);
        float v0 = __ldg(ad + c0), v1 = __ldg(ad + c0 + 1);
        #pragma unroll
        for (int mt = 0; mt < 2; mt++) {
            sa[mt * 2 + 0] += acc[mt][nt][0] * w0 + acc[mt][nt][1] * w1;
            sa[mt * 2 + 1] += acc[mt][nt][2] * w0 + acc[mt][nt][3] * w1;
            sd[mt * 2 + 0] += acc[mt][nt][0] * v0 + acc[mt][nt][1] * v1;
            sd[mt * 2 + 1] += acc[mt][nt][2] * v0 + acc[mt][nt][3] * v1;
        }
    }
    #pragma unroll
    for (int i = 0; i < 4; i++) {
        sa[i] += __shfl_xor_sync(0xffffffff, sa[i], 1);
        sa[i] += __shfl_xor_sync(0xffffffff, sa[i], 2);
        sd[i] += __shfl_xor_sync(0xffffffff, sd[i], 1);
        sd[i] += __shfl_xor_sync(0xffffffff, sd[i], 2);
    }
    if ((lane & 3) == 0) {
        #pragma unroll
        for (int mt = 0; mt < 2; mt++)
            #pragma unroll
            for (int rh = 0; rh < 2; rh++) {
                int r = row0 + wm * 32 + mt * 16 + (lane >> 2) + rh * 8;
                if (r < M) {
                    g_asrc[r * 4 + wn] = sa[mt * 2 + rh];
                    g_adst[r * 4 + wn] = sd[mt * 2 + rh];
                }
            }
    }

    #pragma unroll
    for (int mt = 0; mt < 2; mt++) {
        int r0 = row0 + wm * 32 + mt * 16 + (lane >> 2);
        int r1 = r0 + 8;
        #pragma unroll
        for (int nt = 0; nt < 8; nt++) {
            int cc2 = (cb >> 1) + nt * 4 + (lane & 3);
            if (r0 < M) Hout[(size_t)r0 * 128 + cc2] = __floats2bfloat162_rn(acc[mt][nt][0], acc[mt][nt][1]);
            if (r1 < M) Hout[(size_t)r1 * 128 + cc2] = __floats2bfloat162_rn(acc[mt][nt][2], acc[mt][nt][3]);
        }
    }
}

// ---------------- warp-per-node GAT aggregation (2-deep pipeline) + bias + warp LN + ReLU ----------------
__global__ void __launch_bounds__(256) k_agg_ln(
    const __nv_bfloat162* __restrict__ hb, const float* __restrict__ bias,
    const float* __restrict__ gamma, const float* __restrict__ beta,
    __nv_bfloat162* __restrict__ ohi)
{
    int wid = threadIdx.x >> 5, lane = threadIdx.x & 31;
    int n = blockIdx.x * 8 + wid;
    if (n >= NN) return;
    int beg = g_rowptr[n], end = g_rowptr[n + 1];
    int head = lane >> 3;
    float adh = __ldg(g_adst + 4 * n + head);

    float acc[8];
    #pragma unroll
    for (int j = 0; j < 8; j++) acc[j] = 0.f;
    float den = 0.f;

    const int4* hrow = (const int4*)hb;

    int s_cur = __ldg(g_csrsrc + beg);
    int s_nxt = (beg + 1 < end) ? __ldg(g_csrsrc + beg + 1) : 0;
    float av = __ldg(g_asrc + 4 * s_cur + head);
    int4  v  = __ldg(hrow + (size_t)s_cur * 32 + lane);

    for (int k = beg; k < end; k++) {
        float av_n; int4 v_n;
        if (k + 1 < end) {
            av_n = __ldg(g_asrc + 4 * s_nxt + head);
            v_n  = __ldg(hrow + (size_t)s_nxt * 32 + lane);
        }
        int s_n2 = (k + 2 < end) ? __ldg(g_csrsrc + k + 2) : 0;

        float e = av + adh;
        e = (e > 0.f) ? e : NEG_SLOPE * e;
        float w = __expf(e);
        den += w;
        const __nv_bfloat162* pv = (const __nv_bfloat162*)&v;
        #pragma unroll
        for (int j = 0; j < 4; j++) {
            float2 f = __bfloat1622float2(pv[j]);
            acc[2 * j]     = fmaf(w, f.x, acc[2 * j]);
            acc[2 * j + 1] = fmaf(w, f.y, acc[2 * j + 1]);
        }
        av = av_n; v = v_n; s_nxt = s_n2;
    }

    float inv = 1.0f / den;
    int c0 = lane * 8;
    float4 b0 = __ldg((const float4*)(bias + c0));
    float4 b1 = __ldg((const float4*)(bias + c0 + 4));
    float m[8];
    m[0] = acc[0] * inv + b0.x; m[1] = acc[1] * inv + b0.y;
    m[2] = acc[2] * inv + b0.z; m[3] = acc[3] * inv + b0.w;
    m[4] = acc[4] * inv + b1.x; m[5] = acc[5] * inv + b1.y;
    m[6] = acc[6] * inv + b1.z; m[7] = acc[7] * inv + b1.w;

    float sum = ((m[0] + m[1]) + (m[2] + m[3])) + ((m[4] + m[5]) + (m[6] + m[7]));
    #pragma unroll
    for (int off = 16; off > 0; off >>= 1) sum += __shfl_xor_sync(0xffffffff, sum, off);
    float mu = sum * (1.0f / 256.0f);
    float d[8];
    float q = 0.f;
    #pragma unroll
    for (int j = 0; j < 8; j++) { d[j] = m[j] - mu; q = fmaf(d[j], d[j], q); }
    #pragma unroll
    for (int off = 16; off > 0; off >>= 1) q += __shfl_xor_sync(0xffffffff, q, off);
    float invs = rsqrtf(q * (1.0f / 256.0f) + 1e-5f);

    float4 g0 = __ldg((const float4*)(gamma + c0));
    float4 g1 = __ldg((const float4*)(gamma + c0 + 4));
    float4 t0 = __ldg((const float4*)(beta + c0));
    float4 t1 = __ldg((const float4*)(beta + c0 + 4));
    float y[8];
    y[0] = fmaxf(d[0] * invs * g0.x + t0.x, 0.f);
    y[1] = fmaxf(d[1] * invs * g0.y + t0.y, 0.f);
    y[2] = fmaxf(d[2] * invs * g0.z + t0.z, 0.f);
    y[3] = fmaxf(d[3] * invs * g0.w + t0.w, 0.f);
    y[4] = fmaxf(d[4] * invs * g1.x + t1.x, 0.f);
    y[5] = fmaxf(d[5] * invs * g1.y + t1.y, 0.f);
    y[6] = fmaxf(d[6] * invs * g1.z + t1.z, 0.f);
    y[7] = fmaxf(d[7] * invs * g1.w + t1.w, 0.f);

    __nv_bfloat162 p0 = __floats2bfloat162_rn(y[0], y[1]);
    __nv_bfloat162 p1 = __floats2bfloat162_rn(y[2], y[3]);
    __nv_bfloat162 p2 = __floats2bfloat162_rn(y[4], y[5]);
    __nv_bfloat162 p3 = __floats2bfloat162_rn(y[6], y[7]);
    int4 packed;
    packed.x = *(const int*)&p0; packed.y = *(const int*)&p1;
    packed.z = *(const int*)&p2; packed.w = *(const int*)&p3;
    ((int4*)ohi)[(size_t)n * 32 + lane] = packed;
}

// ---------------- global mean pool: parallel partial sums (bf16 in, atomic fp32 out) ----------------
__global__ void k_pool(const __nv_bfloat162* __restrict__ h) {
    int g = blockIdx.x;
    int chunk = blockIdx.y;                 // 0..7
    int c2 = threadIdx.x;                   // bf16x2 pair 0..127
    int s = g_gstart[g], e = g_gstart[g + 1];
    int len = e - s;
    int cs = s + (len * chunk) / 8;
    int ce = s + (len * (chunk + 1)) / 8;
    float sum0 = 0.f, sum1 = 0.f;
    const __nv_bfloat162* p = h + c2;
    for (int i = cs; i < ce; i++) {
        float2 f = __bfloat1622float2(__ldg(p + (size_t)i * 128));
        sum0 += f.x; sum1 += f.y;
    }
    if (cs < ce) {
        atomicAdd(&g_pooled[g * DD + 2 * c2], sum0);
        atomicAdd(&g_pooled[g * DD + 2 * c2 + 1], sum1);
    }
}

// ---------------- final MLP (normalization folded in) ----------------
__global__ void k_mlp(const float* __restrict__ lw1, const float* __restrict__ lb1,
                      const float* __restrict__ lw2, const float* __restrict__ lb2,
                      float* __restrict__ out) {
    __shared__ float p[DD];
    __shared__ float hid[HIDC];
    int g = blockIdx.x, tid = threadIdx.x;
    int cnt = g_gstart[g + 1] - g_gstart[g];
    float invc = 1.0f / (float)max(cnt, 1);
    for (int i = tid; i < DD; i += 64) p[i] = g_pooled[g * DD + i] * invc;
    __syncthreads();
    float s = lb1[tid];
    #pragma unroll 8
    for (int k = 0; k < DD; k++) s = fmaf(p[k], lw1[k * HIDC + tid], s);
    hid[tid] = fmaxf(s, 0.f);
    __syncthreads();
    if (tid < 2) {
        float o = lb2[tid];
        #pragma unroll
        for (int k = 0; k < HIDC; k++) o = fmaf(hid[k], lw2[k * 2 + tid], o);
        out[g * 2 + tid] = o;
    }
}

// ---------------- host launcher ----------------
extern "C" void kernel_launch(void* const* d_in, const int* in_sizes, int n_in,
                              void* d_out, int out_size) {
    const float* x   = (const float*)d_in[0];
    const int*   ei  = (const int*)d_in[1];
    const int*   bat = (const int*)d_in[2];
    const float* W1  = (const float*)d_in[3];
    const float* as1 = (const float*)d_in[4];
    const float* ad1 = (const float*)d_in[5];
    const float* b1  = (const float*)d_in[6];
    const float* g1  = (const float*)d_in[7];
    const float* be1 = (const float*)d_in[8];
    const float* W2  = (const float*)d_in[9];
    const float* as2 = (const float*)d_in[10];
    const float* ad2 = (const float*)d_in[11];
    const float* b2  = (const float*)d_in[12];
    const float* g2  = (const float*)d_in[13];
    const float* be2 = (const float*)d_in[14];
    const float* lw1 = (const float*)d_in[15];
    const float* lb1 = (const float*)d_in[16];
    const float* lw2 = (const float*)d_in[17];
    const float* lb2 = (const float*)d_in[18];
    float* out = (float*)d_out;

    cudaFuncSetAttribute(k_gemm_att, cudaFuncAttributeMaxDynamicSharedMemorySize, SMEM_TOT);

    __nv_bfloat162 *hb;
    __nv_bfloat16 *ahi, *w1h, *w1l, *w2h, *w2l;
    cudaGetSymbolAddress((void**)&hb, g_hb);
    cudaGetSymbolAddress((void**)&ahi, g_ahi);
    cudaGetSymbolAddress((void**)&w1h, g_w1hi);
    cudaGetSymbolAddress((void**)&w1l, g_w1lo);
    cudaGetSymbolAddress((void**)&w2h, g_w2hi);
    cudaGetSymbolAddress((void**)&w2l, g_w2lo);

    int gemm_blocks = (NN + 127) / 128;
    int agg_blocks = (NN + 7) / 8;

    // independent prework first so k_gemm_att lands at the ncu capture slot
    k_split_x<<<NN * DD / 1024, 256>>>((const float4*)x, (__nv_bfloat162*)ahi);  // 1
    k_split_w<<<2 * DD * DD / 256, 256>>>(W1, W2);                  // 2
    k_gbounds<<<(NN + 255) / 256, 256>>>(bat);                      // 3
    k_gemm_att<<<gemm_blocks, 512, SMEM_TOT>>>(ahi, w1h, w1l, hb, as1, ad1, NN);  // 4

    // CSR build (must finish before agg1); also zeroes g_pooled
    k_zero_deg<<<(NN + 255) / 256, 256>>>();                        // 5
    k_hist_edges<<<(ETOT + 255) / 256, 256>>>(ei);                  // 6
    k_scan_part<<<SNB, 512>>>();                                    // 7
    k_scan_boff<<<1, 128>>>();                                      // 8
    k_scan_add<<<(NN + 255) / 256, 256>>>();                        // 9
    k_scatter_edges<<<(ETOT + 255) / 256, 256>>>(ei);               // 10

    // ---- layer 1 agg (writes bf16 into g_ahi) ----
    k_agg_ln<<<agg_blocks, 256>>>(hb, b1, g1, be1, (__nv_bfloat162*)ahi);

    // ---- layer 2 ----
    k_gemm_att<<<gemm_blocks, 512, SMEM_TOT>>>(ahi, w2h, w2l, hb, as2, ad2, NN);
    k_agg_ln<<<agg_blocks, 256>>>(hb, b2, g2, be2, (__nv_bfloat162*)ahi);

    // ---- pool + MLP ----
    k_pool<<<dim3(GG, 8), 128>>>((const __nv_bfloat162*)ahi);
    k_mlp<<<GG, 64>>>(lw1, lb1, lw2, lb2, out);
}

// round 14
// speedup vs baseline: 1.8966x; 1.0336x over previous
#include <cuda_runtime.h>
#include <cuda_bf16.h>
#include <cstdint>
#include <math.h>

#define NN 50000
#define EE 400000
#define ETOT (EE + NN)
#define DD 256
#define HEADS 4
#define HIDC 64
#define GG 64
#define NEG_SLOPE 0.2f

// ---------------- static device scratch ----------------
__device__ __nv_bfloat162 g_hb[NN * 128];   // GEMM output h (bf16)
__device__ __nv_bfloat16 g_ahi[NN * DD];    // layer input (bf16); reused as agg output
__device__ __nv_bfloat16 g_w1hi[DD * DD], g_w1lo[DD * DD];
__device__ __nv_bfloat16 g_w2hi[DD * DD], g_w2lo[DD * DD];
__device__ float g_asrc[NN * HEADS];
__device__ float g_adst[NN * HEADS];
__device__ int   g_deg[NN];
__device__ int   g_rowptr[NN + 1];
__device__ int   g_cursor[NN];
__device__ int   g_csrsrc[ETOT];
__device__ int   g_gstart[GG + 1];
__device__ float g_pooled[GG * DD];
#define SNB 98
__device__ int   g_bsum[SNB];
__device__ int   g_boff[SNB];

// ---------------- helpers ----------------
__device__ __forceinline__ uint32_t su32(const void* p) {
    uint32_t a;
    asm("{ .reg .u64 t; cvta.to.shared.u64 t, %1; cvt.u32.u64 %0, t; }" : "=r"(a) : "l"(p));
    return a;
}
__device__ __forceinline__ uint32_t swz(uint32_t off) {
    return off ^ ((off >> 3) & 0x70);
}
__device__ __forceinline__ void ldsm_x4(uint32_t* r, uint32_t addr) {
    asm volatile("ldmatrix.sync.aligned.m8n8.x4.shared.b16 {%0,%1,%2,%3}, [%4];"
                 : "=r"(r[0]), "=r"(r[1]), "=r"(r[2]), "=r"(r[3]) : "r"(addr));
}
__device__ __forceinline__ void mma_bf16(float* c, const uint32_t* a, const uint32_t* b) {
    asm volatile("mma.sync.aligned.m16n8k16.row.col.f32.bf16.bf16.f32 "
                 "{%0,%1,%2,%3}, {%4,%5,%6,%7}, {%8,%9}, {%0,%1,%2,%3};"
                 : "+f"(c[0]), "+f"(c[1]), "+f"(c[2]), "+f"(c[3])
                 : "r"(a[0]), "r"(a[1]), "r"(a[2]), "r"(a[3]), "r"(b[0]), "r"(b[1]));
}
__device__ __forceinline__ void cp16(uint32_t dst, const void* src, uint32_t sz) {
    asm volatile("cp.async.cg.shared.global [%0], [%1], 16, %2;" :: "r"(dst), "l"(src), "r"(sz));
}
__device__ __forceinline__ void cp16f(uint32_t dst, const void* src) {
    asm volatile("cp.async.cg.shared.global [%0], [%1], 16;" :: "r"(dst), "l"(src));
}
#define CP_COMMIT() asm volatile("cp.async.commit_group;" ::: "memory")
#define CP_WAIT(n)  asm volatile("cp.async.wait_group %0;" :: "n"(n) : "memory")

// ---------------- fused prep: zero deg/pooled + graph bounds + W split ----------------
__global__ void k_prep(const int* __restrict__ batch,
                       const float* __restrict__ W1, const float* __restrict__ W2) {
    int i = blockIdx.x * blockDim.x + threadIdx.x;   // 131072 threads
    if (i < NN) {
        g_deg[i] = 0;
        int b = batch[i];
        int prev = (i == 0) ? -1 : batch[i - 1];
        for (int g = prev + 1; g <= b; g++) g_gstart[g] = i;
        if (i == NN - 1)
            for (int g = b + 1; g <= GG; g++) g_gstart[g] = NN;
    }
    if (i < GG * DD) g_pooled[i] = 0.f;
    {
        int which = i >> 16;
        int j = i & 65535;
        int n = j >> 8, k = j & 255;
        const float* W = which ? W2 : W1;
        float v = W[k * 256 + n];
        __nv_bfloat16 h = __float2bfloat16(v);
        float r = v - __bfloat162float(h);
        if (which) { g_w2hi[j] = h; g_w2lo[j] = __float2bfloat16(r); }
        else       { g_w1hi[j] = h; g_w1lo[j] = __float2bfloat16(r); }
    }
}

__global__ void k_hist_edges(const int* __restrict__ ei) {
    int i = blockIdx.x * blockDim.x + threadIdx.x;
    if (i < EE) atomicAdd(&g_deg[ei[EE + i]], 1);
    else if (i < ETOT) atomicAdd(&g_deg[i - EE], 1);
}
__global__ void k_scan_part() {
    __shared__ int sh[512];
    int i = blockIdx.x * 512 + threadIdx.x;
    int v = (i < NN) ? g_deg[i] : 0;
    sh[threadIdx.x] = v;
    __syncthreads();
    #pragma unroll
    for (int off = 1; off < 512; off <<= 1) {
        int t = (threadIdx.x >= off) ? sh[threadIdx.x - off] : 0;
        __syncthreads();
        sh[threadIdx.x] += t;
        __syncthreads();
    }
    if (i < NN) g_rowptr[i] = sh[threadIdx.x] - v;
    if (threadIdx.x == 511) g_bsum[blockIdx.x] = sh[511];
}
__global__ void k_scan_boff() {
    __shared__ int sh[128];
    int i = threadIdx.x;
    int v = (i < SNB) ? g_bsum[i] : 0;
    sh[i] = v;
    __syncthreads();
    #pragma unroll
    for (int off = 1; off < 128; off <<= 1) {
        int t = (i >= off) ? sh[i - off] : 0;
        __syncthreads();
        sh[i] += t;
        __syncthreads();
    }
    if (i < SNB) g_boff[i] = sh[i] - v;
}
__global__ void k_scan_add() {
    int i = blockIdx.x * blockDim.x + threadIdx.x;
    if (i < NN) {
        int val = g_rowptr[i] + g_boff[i >> 9];
        g_rowptr[i] = val;
        g_cursor[i] = val;
    }
    if (i == 0) g_rowptr[NN] = ETOT;
}
__global__ void k_scatter_edges(const int* __restrict__ ei) {
    int i = blockIdx.x * blockDim.x + threadIdx.x;
    int src, dst;
    if (i < EE)        { src = ei[i]; dst = ei[EE + i]; }
    else if (i < ETOT) { src = i - EE; dst = i - EE; }
    else return;
    int pos = atomicAdd(&g_cursor[dst], 1);
    g_csrsrc[pos] = src;
}

// ---------------- fp32 -> bf16 ----------------
__global__ void k_split_x(const float4* __restrict__ x4, __nv_bfloat162* __restrict__ hi2) {
    int i = blockIdx.x * 256 + threadIdx.x;
    float4 v = x4[i];
    hi2[2 * i]     = __floats2bfloat162_rn(v.x, v.y);
    hi2[2 * i + 1] = __floats2bfloat162_rn(v.z, v.w);
}

// ---------------- GEMM (256 thr, CTA 128x128, 2 CTA/SM): h = A @ [Whi+Wlo]^T ----------------
#define STG   49152
#define OA_HI 0
#define OB_HI 16384
#define OB_LO 32768
#define SMEM_TOT (2 * STG)

__global__ void __launch_bounds__(256, 2) k_gemm_att(
    const __nv_bfloat16* __restrict__ Ahi,
    const __nv_bfloat16* __restrict__ Bhi, const __nv_bfloat16* __restrict__ Blo,
    __nv_bfloat162* __restrict__ Hout,
    const float* __restrict__ as, const float* __restrict__ ad,
    int M)
{
    extern __shared__ char smem[];
    uint32_t sb = su32(smem);
    const int tid = threadIdx.x, wid = tid >> 5, lane = tid & 31;
    const int row0 = blockIdx.x * 128;
    const int col0 = blockIdx.y * 128;
    const int wm = wid & 3;        // 4 row groups of 32
    const int wn = wid >> 2;       // 2 col groups of 64 (local)

    float acc[2][8][4];
    #pragma unroll
    for (int a = 0; a < 2; a++)
        #pragma unroll
        for (int b = 0; b < 8; b++)
            #pragma unroll
            for (int q = 0; q < 4; q++) acc[a][b][q] = 0.f;

    auto load_chunk = [&](int c, int stage) {
        uint32_t base = sb + stage * STG;
        #pragma unroll
        for (int it = 0; it < 4; it++) {          // A: 1024 16B slots / 256 thr
            int u = tid + it * 256;
            int r = u >> 3, j = u & 7;
            uint32_t sw = swz(r * 128 + j * 16);
            int m = row0 + r;
            int mc = m < M ? m : (M - 1);
            uint32_t sz = (m < M) ? 16u : 0u;
            size_t gi = (size_t)mc * 256 + c * 64 + j * 8;
            cp16(base + OA_HI + sw, Ahi + gi, sz);
        }
        #pragma unroll
        for (int it = 0; it < 4; it++) {          // B: 1024 16B slots each (128 rows)
            int u = tid + it * 256;
            int r = u >> 3, j = u & 7;
            uint32_t sw = swz(r * 128 + j * 16);
            size_t gi = (size_t)(col0 + r) * 256 + c * 64 + j * 8;
            cp16f(base + OB_HI + sw, Bhi + gi);
            cp16f(base + OB_LO + sw, Blo + gi);
        }
    };

    load_chunk(0, 0);
    CP_COMMIT();

    const int lrow = lane & 15;
    const int lcol = (lane >> 4) * 8;
    const int cb = wn * 64;        // local col base in smem

    for (int c = 0; c < 4; c++) {
        int stage = c & 1;
        if (c < 3) { load_chunk(c + 1, stage ^ 1); CP_COMMIT(); CP_WAIT(1); }
        else       { CP_WAIT(0); }
        __syncthreads();
        uint32_t base = sb + stage * STG;

        #pragma unroll
        for (int kk = 0; kk < 4; kk++) {
            uint32_t ah[2][4];
            #pragma unroll
            for (int mt = 0; mt < 2; mt++) {
                uint32_t off = swz((wm * 32 + mt * 16 + lrow) * 128 + (kk * 16 + lcol) * 2);
                ldsm_x4(ah[mt], base + OA_HI + off);
            }
            #pragma unroll
            for (int ntp = 0; ntp < 4; ntp++) {
                int q = lane >> 3;
                int nrow = cb + ntp * 16 + (q >> 1) * 8 + (lane & 7);
                int kcol = kk * 16 + (q & 1) * 8;
                uint32_t boff = swz(nrow * 128 + kcol * 2);
                uint32_t bh[4], bl[4];
                ldsm_x4(bh, base + OB_HI + boff);
                ldsm_x4(bl, base + OB_LO + boff);
                #pragma unroll
                for (int sub = 0; sub < 2; sub++) {
                    int nt = ntp * 2 + sub;
                    #pragma unroll
                    for (int mt = 0; mt < 2; mt++) {
                        mma_bf16(acc[mt][nt], ah[mt], bh + sub * 2);
                        mma_bf16(acc[mt][nt], ah[mt], bl + sub * 2);
                    }
                }
            }
        }
        __syncthreads();
    }

    // ---- epilogue: attention coefficients (head = blockIdx.y*2 + wn) + bf16 h store ----
    const int head = blockIdx.y * 2 + wn;
    float sa[4], sd[4];
    #pragma unroll
    for (int i = 0; i < 4; i++) { sa[i] = 0.f; sd[i] = 0.f; }

    #pragma unroll
    for (int nt = 0; nt < 8; nt++) {
        int c0 = col0 + cb + nt * 8 + (lane & 3) * 2;
        float w0 = __ldg(as + c0), w1 = __ldg(as + c0 + 1);
        float v0 = __ldg(ad + c0), v1 = __ldg(ad + c0 + 1);
        #pragma unroll
        for (int mt = 0; mt < 2; mt++) {
            sa[mt * 2 + 0] += acc[mt][nt][0] * w0 + acc[mt][nt][1] * w1;
            sa[mt * 2 + 1] += acc[mt][nt][2] * w0 + acc[mt][nt][3] * w1;
            sd[mt * 2 + 0] += acc[mt][nt][0] * v0 + acc[mt][nt][1] * v1;
            sd[mt * 2 + 1] += acc[mt][nt][2] * v0 + acc[mt][nt][3] * v1;
        }
    }
    #pragma unroll
    for (int i = 0; i < 4; i++) {
        sa[i] += __shfl_xor_sync(0xffffffff, sa[i], 1);
        sa[i] += __shfl_xor_sync(0xffffffff, sa[i], 2);
        sd[i] += __shfl_xor_sync(0xffffffff, sd[i], 1);
        sd[i] += __shfl_xor_sync(0xffffffff, sd[i], 2);
    }
    if ((lane & 3) == 0) {
        #pragma unroll
        for (int mt = 0; mt < 2; mt++)
            #pragma unroll
            for (int rh = 0; rh < 2; rh++) {
                int r = row0 + wm * 32 + mt * 16 + (lane >> 2) + rh * 8;
                if (r < M) {
                    g_asrc[r * 4 + head] = sa[mt * 2 + rh];
                    g_adst[r * 4 + head] = sd[mt * 2 + rh];
                }
            }
    }

    #pragma unroll
    for (int mt = 0; mt < 2; mt++) {
        int r0 = row0 + wm * 32 + mt * 16 + (lane >> 2);
        int r1 = r0 + 8;
        #pragma unroll
        for (int nt = 0; nt < 8; nt++) {
            int cc2 = (col0 >> 1) + (cb >> 1) + nt * 4 + (lane & 3);
            if (r0 < M) Hout[(size_t)r0 * 128 + cc2] = __floats2bfloat162_rn(acc[mt][nt][0], acc[mt][nt][1]);
            if (r1 < M) Hout[(size_t)r1 * 128 + cc2] = __floats2bfloat162_rn(acc[mt][nt][2], acc[mt][nt][3]);
        }
    }
}

// ---------------- warp-per-node GAT aggregation (3-deep pipeline) + bias + warp LN + ReLU ----------------
__global__ void __launch_bounds__(256) k_agg_ln(
    const __nv_bfloat162* __restrict__ hb, const float* __restrict__ bias,
    const float* __restrict__ gamma, const float* __restrict__ beta,
    __nv_bfloat162* __restrict__ ohi)
{
    int wid = threadIdx.x >> 5, lane = threadIdx.x & 31;
    int n = blockIdx.x * 8 + wid;
    if (n >= NN) return;
    int beg = g_rowptr[n], end = g_rowptr[n + 1];
    int head = lane >> 3;
    float adh = __ldg(g_adst + 4 * n + head);

    float acc[8];
    #pragma unroll
    for (int j = 0; j < 8; j++) acc[j] = 0.f;
    float den = 0.f;

    const int4* hrow = (const int4*)hb;

    // depth-3 pipeline: index 3 ahead, data 2 ahead
    int sC;
    float avA, avB;
    int4 vA, vB;
    {
        int s0 = __ldg(g_csrsrc + beg);
        avA = __ldg(g_asrc + 4 * s0 + head);
        vA  = __ldg(hrow + (size_t)s0 * 32 + lane);
        if (beg + 1 < end) {
            int s1 = __ldg(g_csrsrc + beg + 1);
            avB = __ldg(g_asrc + 4 * s1 + head);
            vB  = __ldg(hrow + (size_t)s1 * 32 + lane);
        }
        sC = (beg + 2 < end) ? __ldg(g_csrsrc + beg + 2) : 0;
    }

    for (int k = beg; k < end; k++) {
        float avC; int4 vC;
        if (k + 2 < end) {
            avC = __ldg(g_asrc + 4 * sC + head);
            vC  = __ldg(hrow + (size_t)sC * 32 + lane);
        }
        int sD = (k + 3 < end) ? __ldg(g_csrsrc + k + 3) : 0;

        float e = avA + adh;
        e = (e > 0.f) ? e : NEG_SLOPE * e;
        float w = __expf(e);
        den += w;
        const __nv_bfloat162* pv = (const __nv_bfloat162*)&vA;
        #pragma unroll
        for (int j = 0; j < 4; j++) {
            float2 f = __bfloat1622float2(pv[j]);
            acc[2 * j]     = fmaf(w, f.x, acc[2 * j]);
            acc[2 * j + 1] = fmaf(w, f.y, acc[2 * j + 1]);
        }
        avA = avB; vA = vB;
        avB = avC; vB = vC;
        sC = sD;
    }

    float inv = 1.0f / den;
    int c0 = lane * 8;
    float4 b0 = __ldg((const float4*)(bias + c0));
    float4 b1 = __ldg((const float4*)(bias + c0 + 4));
    float m[8];
    m[0] = acc[0] * inv + b0.x; m[1] = acc[1] * inv + b0.y;
    m[2] = acc[2] * inv + b0.z; m[3] = acc[3] * inv + b0.w;
    m[4] = acc[4] * inv + b1.x; m[5] = acc[5] * inv + b1.y;
    m[6] = acc[6] * inv + b1.z; m[7] = acc[7] * inv + b1.w;

    float sum = ((m[0] + m[1]) + (m[2] + m[3])) + ((m[4] + m[5]) + (m[6] + m[7]));
    #pragma unroll
    for (int off = 16; off > 0; off >>= 1) sum += __shfl_xor_sync(0xffffffff, sum, off);
    float mu = sum * (1.0f / 256.0f);
    float d[8];
    float q = 0.f;
    #pragma unroll
    for (int j = 0; j < 8; j++) { d[j] = m[j] - mu; q = fmaf(d[j], d[j], q); }
    #pragma unroll
    for (int off = 16; off > 0; off >>= 1) q += __shfl_xor_sync(0xffffffff, q, off);
    float invs = rsqrtf(q * (1.0f / 256.0f) + 1e-5f);

    float4 g0 = __ldg((const float4*)(gamma + c0));
    float4 g1 = __ldg((const float4*)(gamma + c0 + 4));
    float4 t0 = __ldg((const float4*)(beta + c0));
    float4 t1 = __ldg((const float4*)(beta + c0 + 4));
    float y[8];
    y[0] = fmaxf(d[0] * invs * g0.x + t0.x, 0.f);
    y[1] = fmaxf(d[1] * invs * g0.y + t0.y, 0.f);
    y[2] = fmaxf(d[2] * invs * g0.z + t0.z, 0.f);
    y[3] = fmaxf(d[3] * invs * g0.w + t0.w, 0.f);
    y[4] = fmaxf(d[4] * invs * g1.x + t1.x, 0.f);
    y[5] = fmaxf(d[5] * invs * g1.y + t1.y, 0.f);
    y[6] = fmaxf(d[6] * invs * g1.z + t1.z, 0.f);
    y[7] = fmaxf(d[7] * invs * g1.w + t1.w, 0.f);

    __nv_bfloat162 p0 = __floats2bfloat162_rn(y[0], y[1]);
    __nv_bfloat162 p1 = __floats2bfloat162_rn(y[2], y[3]);
    __nv_bfloat162 p2 = __floats2bfloat162_rn(y[4], y[5]);
    __nv_bfloat162 p3 = __floats2bfloat162_rn(y[6], y[7]);
    int4 packed;
    packed.x = *(const int*)&p0; packed.y = *(const int*)&p1;
    packed.z = *(const int*)&p2; packed.w = *(const int*)&p3;
    ((int4*)ohi)[(size_t)n * 32 + lane] = packed;
}

// ---------------- global mean pool: parallel partial sums ----------------
__global__ void k_pool(const __nv_bfloat162* __restrict__ h) {
    int g = blockIdx.x;
    int chunk = blockIdx.y;
    int c2 = threadIdx.x;
    int s = g_gstart[g], e = g_gstart[g + 1];
    int len = e - s;
    int cs = s + (len * chunk) / 8;
    int ce = s + (len * (chunk + 1)) / 8;
    float sum0 = 0.f, sum1 = 0.f;
    const __nv_bfloat162* p = h + c2;
    for (int i = cs; i < ce; i++) {
        float2 f = __bfloat1622float2(__ldg(p + (size_t)i * 128));
        sum0 += f.x; sum1 += f.y;
    }
    if (cs < ce) {
        atomicAdd(&g_pooled[g * DD + 2 * c2], sum0);
        atomicAdd(&g_pooled[g * DD + 2 * c2 + 1], sum1);
    }
}

// ---------------- final MLP (normalization folded in) ----------------
__global__ void k_mlp(const float* __restrict__ lw1, const float* __restrict__ lb1,
                      const float* __restrict__ lw2, const float* __restrict__ lb2,
                      float* __restrict__ out) {
    __shared__ float p[DD];
    __shared__ float hid[HIDC];
    int g = blockIdx.x, tid = threadIdx.x;
    int cnt = g_gstart[g + 1] - g_gstart[g];
    float invc = 1.0f / (float)max(cnt, 1);
    for (int i = tid; i < DD; i += 64) p[i] = g_pooled[g * DD + i] * invc;
    __syncthreads();
    float s = lb1[tid];
    #pragma unroll 8
    for (int k = 0; k < DD; k++) s = fmaf(p[k], lw1[k * HIDC + tid], s);
    hid[tid] = fmaxf(s, 0.f);
    __syncthreads();
    if (tid < 2) {
        float o = lb2[tid];
        #pragma unroll
        for (int k = 0; k < HIDC; k++) o = fmaf(hid[k], lw2[k * 2 + tid], o);
        out[g * 2 + tid] = o;
    }
}

// ---------------- host launcher ----------------
extern "C" void kernel_launch(void* const* d_in, const int* in_sizes, int n_in,
                              void* d_out, int out_size) {
    const float* x   = (const float*)d_in[0];
    const int*   ei  = (const int*)d_in[1];
    const int*   bat = (const int*)d_in[2];
    const float* W1  = (const float*)d_in[3];
    const float* as1 = (const float*)d_in[4];
    const float* ad1 = (const float*)d_in[5];
    const float* b1  = (const float*)d_in[6];
    const float* g1  = (const float*)d_in[7];
    const float* be1 = (const float*)d_in[8];
    const float* W2  = (const float*)d_in[9];
    const float* as2 = (const float*)d_in[10];
    const float* ad2 = (const float*)d_in[11];
    const float* b2  = (const float*)d_in[12];
    const float* g2  = (const float*)d_in[13];
    const float* be2 = (const float*)d_in[14];
    const float* lw1 = (const float*)d_in[15];
    const float* lb1 = (const float*)d_in[16];
    const float* lw2 = (const float*)d_in[17];
    const float* lb2 = (const float*)d_in[18];
    float* out = (float*)d_out;

    cudaFuncSetAttribute(k_gemm_att, cudaFuncAttributeMaxDynamicSharedMemorySize, SMEM_TOT);

    __nv_bfloat162 *hb;
    __nv_bfloat16 *ahi, *w1h, *w1l, *w2h, *w2l;
    cudaGetSymbolAddress((void**)&hb, g_hb);
    cudaGetSymbolAddress((void**)&ahi, g_ahi);
    cudaGetSymbolAddress((void**)&w1h, g_w1hi);
    cudaGetSymbolAddress((void**)&w1l, g_w1lo);
    cudaGetSymbolAddress((void**)&w2h, g_w2hi);
    cudaGetSymbolAddress((void**)&w2l, g_w2lo);

    dim3 gemm_grid((NN + 127) / 128, 2);
    int agg_blocks = (NN + 7) / 8;

    k_split_x<<<NN * DD / 1024, 256>>>((const float4*)x, (__nv_bfloat162*)ahi);  // 1
    k_prep<<<512, 256>>>(bat, W1, W2);                              // 2
    k_hist_edges<<<(ETOT + 255) / 256, 256>>>(ei);                  // 3
    k_gemm_att<<<gemm_grid, 256, SMEM_TOT>>>(ahi, w1h, w1l, hb, as1, ad1, NN);  // 4 (ncu slot)

    k_scan_part<<<SNB, 512>>>();                                    // 5
    k_scan_boff<<<1, 128>>>();                                      // 6
    k_scan_add<<<(NN + 255) / 256, 256>>>();                        // 7
    k_scatter_edges<<<(ETOT + 255) / 256, 256>>>(ei);               // 8

    // ---- layer 1 agg ----
    k_agg_ln<<<agg_blocks, 256>>>(hb, b1, g1, be1, (__nv_bfloat162*)ahi);

    // ---- layer 2 ----
    k_gemm_att<<<gemm_grid, 256, SMEM_TOT>>>(ahi, w2h, w2l, hb, as2, ad2, NN);
    k_agg_ln<<<agg_blocks, 256>>>(hb, b2, g2, be2, (__nv_bfloat162*)ahi);

    // ---- pool + MLP ----
    k_pool<<<dim3(GG, 8), 128>>>((const __nv_bfloat162*)ahi);
    k_mlp<<<GG, 64>>>(lw1, lb1, lw2, lb2, out);
}

// round 15
// speedup vs baseline: 1.9647x; 1.0360x over previous
#include <cuda_runtime.h>
#include <cuda_bf16.h>
#include <cstdint>
#include <math.h>

#define NN 50000
#define EE 400000
#define ETOT (EE + NN)
#define DD 256
#define HEADS 4
#define HIDC 64
#define GG 64
#define NEG_SLOPE 0.2f

// ---------------- static device scratch ----------------
__device__ __nv_bfloat162 g_hb[NN * 128];
__device__ __nv_bfloat16 g_ahi[NN * DD];
__device__ __nv_bfloat16 g_w1hi[DD * DD], g_w1lo[DD * DD];
__device__ __nv_bfloat16 g_w2hi[DD * DD], g_w2lo[DD * DD];
__device__ float g_asrc[NN * HEADS];
__device__ float g_adst[NN * HEADS];
__device__ int   g_deg[NN];
__device__ int   g_rowptr[NN + 1];
__device__ int   g_cursor[NN];
__device__ int   g_csrsrc[ETOT];
__device__ int   g_gstart[GG + 1];
__device__ float g_pooled[GG * DD];
#define SNB 98
__device__ int   g_bsum[SNB];
__device__ int   g_boff[SNB];

// ---------------- helpers ----------------
__device__ __forceinline__ uint32_t su32(const void* p) {
    uint32_t a;
    asm("{ .reg .u64 t; cvta.to.shared.u64 t, %1; cvt.u32.u64 %0, t; }" : "=r"(a) : "l"(p));
    return a;
}
__device__ __forceinline__ uint32_t swz(uint32_t off) {
    return off ^ ((off >> 3) & 0x70);
}
__device__ __forceinline__ void ldsm_x4(uint32_t* r, uint32_t addr) {
    asm volatile("ldmatrix.sync.aligned.m8n8.x4.shared.b16 {%0,%1,%2,%3}, [%4];"
                 : "=r"(r[0]), "=r"(r[1]), "=r"(r[2]), "=r"(r[3]) : "r"(addr));
}
__device__ __forceinline__ void mma_bf16(float* c, const uint32_t* a, const uint32_t* b) {
    asm volatile("mma.sync.aligned.m16n8k16.row.col.f32.bf16.bf16.f32 "
                 "{%0,%1,%2,%3}, {%4,%5,%6,%7}, {%8,%9}, {%0,%1,%2,%3};"
                 : "+f"(c[0]), "+f"(c[1]), "+f"(c[2]), "+f"(c[3])
                 : "r"(a[0]), "r"(a[1]), "r"(a[2]), "r"(a[3]), "r"(b[0]), "r"(b[1]));
}
__device__ __forceinline__ void cp16(uint32_t dst, const void* src, uint32_t sz) {
    asm volatile("cp.async.cg.shared.global [%0], [%1], 16, %2;" :: "r"(dst), "l"(src), "r"(sz));
}
__device__ __forceinline__ void cp16f(uint32_t dst, const void* src) {
    asm volatile("cp.async.cg.shared.global [%0], [%1], 16;" :: "r"(dst), "l"(src));
}
#define CP_COMMIT() asm volatile("cp.async.commit_group;" ::: "memory")
#define CP_WAIT(n)  asm volatile("cp.async.wait_group %0;" :: "n"(n) : "memory")

// ---------------- fused prep: zero deg/pooled + graph bounds + W split ----------------
__global__ void k_prep(const int* __restrict__ batch,
                       const float* __restrict__ W1, const float* __restrict__ W2) {
    int i = blockIdx.x * blockDim.x + threadIdx.x;
    if (i < NN) {
        g_deg[i] = 0;
        int b = batch[i];
        int prev = (i == 0) ? -1 : batch[i - 1];
        for (int g = prev + 1; g <= b; g++) g_gstart[g] = i;
        if (i == NN - 1)
            for (int g = b + 1; g <= GG; g++) g_gstart[g] = NN;
    }
    if (i < GG * DD) g_pooled[i] = 0.f;
    {
        int which = i >> 16;
        int j = i & 65535;
        int n = j >> 8, k = j & 255;
        const float* W = which ? W2 : W1;
        float v = W[k * 256 + n];
        __nv_bfloat16 h = __float2bfloat16(v);
        float r = v - __bfloat162float(h);
        if (which) { g_w2hi[j] = h; g_w2lo[j] = __float2bfloat16(r); }
        else       { g_w1hi[j] = h; g_w1lo[j] = __float2bfloat16(r); }
    }
}

__global__ void k_hist_edges(const int* __restrict__ ei) {
    int i = blockIdx.x * blockDim.x + threadIdx.x;
    if (i < EE) atomicAdd(&g_deg[ei[EE + i]], 1);
    else if (i < ETOT) atomicAdd(&g_deg[i - EE], 1);
}
__global__ void k_scan_part() {
    __shared__ int sh[512];
    int i = blockIdx.x * 512 + threadIdx.x;
    int v = (i < NN) ? g_deg[i] : 0;
    sh[threadIdx.x] = v;
    __syncthreads();
    #pragma unroll
    for (int off = 1; off < 512; off <<= 1) {
        int t = (threadIdx.x >= off) ? sh[threadIdx.x - off] : 0;
        __syncthreads();
        sh[threadIdx.x] += t;
        __syncthreads();
    }
    if (i < NN) g_rowptr[i] = sh[threadIdx.x] - v;
    if (threadIdx.x == 511) g_bsum[blockIdx.x] = sh[511];
}
__global__ void k_scan_boff() {
    __shared__ int sh[128];
    int i = threadIdx.x;
    int v = (i < SNB) ? g_bsum[i] : 0;
    sh[i] = v;
    __syncthreads();
    #pragma unroll
    for (int off = 1; off < 128; off <<= 1) {
        int t = (i >= off) ? sh[i - off] : 0;
        __syncthreads();
        sh[i] += t;
        __syncthreads();
    }
    if (i < SNB) g_boff[i] = sh[i] - v;
}
__global__ void k_scan_add() {
    int i = blockIdx.x * blockDim.x + threadIdx.x;
    if (i < NN) {
        int val = g_rowptr[i] + g_boff[i >> 9];
        g_rowptr[i] = val;
        g_cursor[i] = val;
    }
    if (i == 0) g_rowptr[NN] = ETOT;
}
__global__ void k_scatter_edges(const int* __restrict__ ei) {
    int i = blockIdx.x * blockDim.x + threadIdx.x;
    int src, dst;
    if (i < EE)        { src = ei[i]; dst = ei[EE + i]; }
    else if (i < ETOT) { src = i - EE; dst = i - EE; }
    else return;
    int pos = atomicAdd(&g_cursor[dst], 1);
    g_csrsrc[pos] = src;
}

// ---------------- fp32 -> bf16 ----------------
__global__ void k_split_x(const float4* __restrict__ x4, __nv_bfloat162* __restrict__ hi2) {
    int i = blockIdx.x * 256 + threadIdx.x;
    float4 v = x4[i];
    hi2[2 * i]     = __floats2bfloat162_rn(v.x, v.y);
    hi2[2 * i + 1] = __floats2bfloat162_rn(v.z, v.w);
}

// ---------------- GEMM (256 thr, CTA 128x128, 2 CTA/SM): h = A @ [Whi+Wlo]^T ----------------
#define STG   49152
#define OA_HI 0
#define OB_HI 16384
#define OB_LO 32768
#define SMEM_TOT (2 * STG)

__global__ void __launch_bounds__(256, 2) k_gemm_att(
    const __nv_bfloat16* __restrict__ Ahi,
    const __nv_bfloat16* __restrict__ Bhi, const __nv_bfloat16* __restrict__ Blo,
    __nv_bfloat162* __restrict__ Hout,
    const float* __restrict__ as, const float* __restrict__ ad,
    int M)
{
    extern __shared__ char smem[];
    uint32_t sb = su32(smem);
    const int tid = threadIdx.x, wid = tid >> 5, lane = tid & 31;
    const int row0 = blockIdx.x * 128;
    const int col0 = blockIdx.y * 128;
    const int wm = wid & 3;
    const int wn = wid >> 2;

    float acc[2][8][4];
    #pragma unroll
    for (int a = 0; a < 2; a++)
        #pragma unroll
        for (int b = 0; b < 8; b++)
            #pragma unroll
            for (int q = 0; q < 4; q++) acc[a][b][q] = 0.f;

    auto load_chunk = [&](int c, int stage) {
        uint32_t base = sb + stage * STG;
        #pragma unroll
        for (int it = 0; it < 4; it++) {
            int u = tid + it * 256;
            int r = u >> 3, j = u & 7;
            uint32_t sw = swz(r * 128 + j * 16);
            int m = row0 + r;
            int mc = m < M ? m : (M - 1);
            uint32_t sz = (m < M) ? 16u : 0u;
            size_t gi = (size_t)mc * 256 + c * 64 + j * 8;
            cp16(base + OA_HI + sw, Ahi + gi, sz);
        }
        #pragma unroll
        for (int it = 0; it < 4; it++) {
            int u = tid + it * 256;
            int r = u >> 3, j = u & 7;
            uint32_t sw = swz(r * 128 + j * 16);
            size_t gi = (size_t)(col0 + r) * 256 + c * 64 + j * 8;
            cp16f(base + OB_HI + sw, Bhi + gi);
            cp16f(base + OB_LO + sw, Blo + gi);
        }
    };

    load_chunk(0, 0);
    CP_COMMIT();

    const int lrow = lane & 15;
    const int lcol = (lane >> 4) * 8;
    const int cb = wn * 64;

    for (int c = 0; c < 4; c++) {
        int stage = c & 1;
        if (c < 3) { load_chunk(c + 1, stage ^ 1); CP_COMMIT(); CP_WAIT(1); }
        else       { CP_WAIT(0); }
        __syncthreads();
        uint32_t base = sb + stage * STG;

        #pragma unroll
        for (int kk = 0; kk < 4; kk++) {
            uint32_t ah[2][4];
            #pragma unroll
            for (int mt = 0; mt < 2; mt++) {
                uint32_t off = swz((wm * 32 + mt * 16 + lrow) * 128 + (kk * 16 + lcol) * 2);
                ldsm_x4(ah[mt], base + OA_HI + off);
            }
            #pragma unroll
            for (int ntp = 0; ntp < 4; ntp++) {
                int q = lane >> 3;
                int nrow = cb + ntp * 16 + (q >> 1) * 8 + (lane & 7);
                int kcol = kk * 16 + (q & 1) * 8;
                uint32_t boff = swz(nrow * 128 + kcol * 2);
                uint32_t bh[4], bl[4];
                ldsm_x4(bh, base + OB_HI + boff);
                ldsm_x4(bl, base + OB_LO + boff);
                #pragma unroll
                for (int sub = 0; sub < 2; sub++) {
                    int nt = ntp * 2 + sub;
                    #pragma unroll
                    for (int mt = 0; mt < 2; mt++) {
                        mma_bf16(acc[mt][nt], ah[mt], bh + sub * 2);
                        mma_bf16(acc[mt][nt], ah[mt], bl + sub * 2);
                    }
                }
            }
        }
        __syncthreads();
    }

    const int head = blockIdx.y * 2 + wn;
    float sa[4], sd[4];
    #pragma unroll
    for (int i = 0; i < 4; i++) { sa[i] = 0.f; sd[i] = 0.f; }

    #pragma unroll
    for (int nt = 0; nt < 8; nt++) {
        int c0 = col0 + cb + nt * 8 + (lane & 3) * 2;
        float w0 = __ldg(as + c0), w1 = __ldg(as + c0 + 1);
        float v0 = __ldg(ad + c0), v1 = __ldg(ad + c0 + 1);
        #pragma unroll
        for (int mt = 0; mt < 2; mt++) {
            sa[mt * 2 + 0] += acc[mt][nt][0] * w0 + acc[mt][nt][1] * w1;
            sa[mt * 2 + 1] += acc[mt][nt][2] * w0 + acc[mt][nt][3] * w1;
            sd[mt * 2 + 0] += acc[mt][nt][0] * v0 + acc[mt][nt][1] * v1;
            sd[mt * 2 + 1] += acc[mt][nt][2] * v0 + acc[mt][nt][3] * v1;
        }
    }
    #pragma unroll
    for (int i = 0; i < 4; i++) {
        sa[i] += __shfl_xor_sync(0xffffffff, sa[i], 1);
        sa[i] += __shfl_xor_sync(0xffffffff, sa[i], 2);
        sd[i] += __shfl_xor_sync(0xffffffff, sd[i], 1);
        sd[i] += __shfl_xor_sync(0xffffffff, sd[i], 2);
    }
    if ((lane & 3) == 0) {
        #pragma unroll
        for (int mt = 0; mt < 2; mt++)
            #pragma unroll
            for (int rh = 0; rh < 2; rh++) {
                int r = row0 + wm * 32 + mt * 16 + (lane >> 2) + rh * 8;
                if (r < M) {
                    g_asrc[r * 4 + head] = sa[mt * 2 + rh];
                    g_adst[r * 4 + head] = sd[mt * 2 + rh];
                }
            }
    }

    #pragma unroll
    for (int mt = 0; mt < 2; mt++) {
        int r0 = row0 + wm * 32 + mt * 16 + (lane >> 2);
        int r1 = r0 + 8;
        #pragma unroll
        for (int nt = 0; nt < 8; nt++) {
            int cc2 = (col0 >> 1) + (cb >> 1) + nt * 4 + (lane & 3);
            if (r0 < M) Hout[(size_t)r0 * 128 + cc2] = __floats2bfloat162_rn(acc[mt][nt][0], acc[mt][nt][1]);
            if (r1 < M) Hout[(size_t)r1 * 128 + cc2] = __floats2bfloat162_rn(acc[mt][nt][2], acc[mt][nt][3]);
        }
    }
}

// ---------------- warp-per-node GAT aggregation (3-deep pipeline) + bias + warp LN + ReLU ----------------
__global__ void __launch_bounds__(256) k_agg_ln(
    const __nv_bfloat162* __restrict__ hb, const float* __restrict__ bias,
    const float* __restrict__ gamma, const float* __restrict__ beta,
    __nv_bfloat162* __restrict__ ohi)
{
    int wid = threadIdx.x >> 5, lane = threadIdx.x & 31;
    int n = blockIdx.x * 8 + wid;
    if (n >= NN) return;
    int beg = g_rowptr[n], end = g_rowptr[n + 1];
    int head = lane >> 3;
    float adh = __ldg(g_adst + 4 * n + head);

    float acc[8];
    #pragma unroll
    for (int j = 0; j < 8; j++) acc[j] = 0.f;
    float den = 0.f;

    const int4* hrow = (const int4*)hb;

    int sC;
    float avA, avB;
    int4 vA, vB;
    {
        int s0 = __ldg(g_csrsrc + beg);
        avA = __ldg(g_asrc + 4 * s0 + head);
        vA  = __ldg(hrow + (size_t)s0 * 32 + lane);
        if (beg + 1 < end) {
            int s1 = __ldg(g_csrsrc + beg + 1);
            avB = __ldg(g_asrc + 4 * s1 + head);
            vB  = __ldg(hrow + (size_t)s1 * 32 + lane);
        }
        sC = (beg + 2 < end) ? __ldg(g_csrsrc + beg + 2) : 0;
    }

    for (int k = beg; k < end; k++) {
        float avC; int4 vC;
        if (k + 2 < end) {
            avC = __ldg(g_asrc + 4 * sC + head);
            vC  = __ldg(hrow + (size_t)sC * 32 + lane);
        }
        int sD = (k + 3 < end) ? __ldg(g_csrsrc + k + 3) : 0;

        float e = avA + adh;
        e = (e > 0.f) ? e : NEG_SLOPE * e;
        float w = __expf(e);
        den += w;
        const __nv_bfloat162* pv = (const __nv_bfloat162*)&vA;
        #pragma unroll
        for (int j = 0; j < 4; j++) {
            float2 f = __bfloat1622float2(pv[j]);
            acc[2 * j]     = fmaf(w, f.x, acc[2 * j]);
            acc[2 * j + 1] = fmaf(w, f.y, acc[2 * j + 1]);
        }
        avA = avB; vA = vB;
        avB = avC; vB = vC;
        sC = sD;
    }

    float inv = 1.0f / den;
    int c0 = lane * 8;
    float4 b0 = __ldg((const float4*)(bias + c0));
    float4 b1 = __ldg((const float4*)(bias + c0 + 4));
    float m[8];
    m[0] = acc[0] * inv + b0.x; m[1] = acc[1] * inv + b0.y;
    m[2] = acc[2] * inv + b0.z; m[3] = acc[3] * inv + b0.w;
    m[4] = acc[4] * inv + b1.x; m[5] = acc[5] * inv + b1.y;
    m[6] = acc[6] * inv + b1.z; m[7] = acc[7] * inv + b1.w;

    float sum = ((m[0] + m[1]) + (m[2] + m[3])) + ((m[4] + m[5]) + (m[6] + m[7]));
    #pragma unroll
    for (int off = 16; off > 0; off >>= 1) sum += __shfl_xor_sync(0xffffffff, sum, off);
    float mu = sum * (1.0f / 256.0f);
    float d[8];
    float q = 0.f;
    #pragma unroll
    for (int j = 0; j < 8; j++) { d[j] = m[j] - mu; q = fmaf(d[j], d[j], q); }
    #pragma unroll
    for (int off = 16; off > 0; off >>= 1) q += __shfl_xor_sync(0xffffffff, q, off);
    float invs = rsqrtf(q * (1.0f / 256.0f) + 1e-5f);

    float4 g0 = __ldg((const float4*)(gamma + c0));
    float4 g1 = __ldg((const float4*)(gamma + c0 + 4));
    float4 t0 = __ldg((const float4*)(beta + c0));
    float4 t1 = __ldg((const float4*)(beta + c0 + 4));
    float y[8];
    y[0] = fmaxf(d[0] * invs * g0.x + t0.x, 0.f);
    y[1] = fmaxf(d[1] * invs * g0.y + t0.y, 0.f);
    y[2] = fmaxf(d[2] * invs * g0.z + t0.z, 0.f);
    y[3] = fmaxf(d[3] * invs * g0.w + t0.w, 0.f);
    y[4] = fmaxf(d[4] * invs * g1.x + t1.x, 0.f);
    y[5] = fmaxf(d[5] * invs * g1.y + t1.y, 0.f);
    y[6] = fmaxf(d[6] * invs * g1.z + t1.z, 0.f);
    y[7] = fmaxf(d[7] * invs * g1.w + t1.w, 0.f);

    __nv_bfloat162 p0 = __floats2bfloat162_rn(y[0], y[1]);
    __nv_bfloat162 p1 = __floats2bfloat162_rn(y[2], y[3]);
    __nv_bfloat162 p2 = __floats2bfloat162_rn(y[4], y[5]);
    __nv_bfloat162 p3 = __floats2bfloat162_rn(y[6], y[7]);
    int4 packed;
    packed.x = *(const int*)&p0; packed.y = *(const int*)&p1;
    packed.z = *(const int*)&p2; packed.w = *(const int*)&p3;
    ((int4*)ohi)[(size_t)n * 32 + lane] = packed;
}

// ---------------- global mean pool: parallel partial sums ----------------
__global__ void k_pool(const __nv_bfloat162* __restrict__ h) {
    int g = blockIdx.x;
    int chunk = blockIdx.y;
    int c2 = threadIdx.x;
    int s = g_gstart[g], e = g_gstart[g + 1];
    int len = e - s;
    int cs = s + (len * chunk) / 8;
    int ce = s + (len * (chunk + 1)) / 8;
    float sum0 = 0.f, sum1 = 0.f;
    const __nv_bfloat162* p = h + c2;
    for (int i = cs; i < ce; i++) {
        float2 f = __bfloat1622float2(__ldg(p + (size_t)i * 128));
        sum0 += f.x; sum1 += f.y;
    }
    if (cs < ce) {
        atomicAdd(&g_pooled[g * DD + 2 * c2], sum0);
        atomicAdd(&g_pooled[g * DD + 2 * c2 + 1], sum1);
    }
}

// ---------------- final MLP (normalization folded in) ----------------
__global__ void k_mlp(const float* __restrict__ lw1, const float* __restrict__ lb1,
                      const float* __restrict__ lw2, const float* __restrict__ lb2,
                      float* __restrict__ out) {
    __shared__ float p[DD];
    __shared__ float hid[HIDC];
    int g = blockIdx.x, tid = threadIdx.x;
    int cnt = g_gstart[g + 1] - g_gstart[g];
    float invc = 1.0f / (float)max(cnt, 1);
    for (int i = tid; i < DD; i += 64) p[i] = g_pooled[g * DD + i] * invc;
    __syncthreads();
    float s = lb1[tid];
    #pragma unroll 8
    for (int k = 0; k < DD; k++) s = fmaf(p[k], lw1[k * HIDC + tid], s);
    hid[tid] = fmaxf(s, 0.f);
    __syncthreads();
    if (tid < 2) {
        float o = lb2[tid];
        #pragma unroll
        for (int k = 0; k < HIDC; k++) o = fmaf(hid[k], lw2[k * 2 + tid], o);
        out[g * 2 + tid] = o;
    }
}

// ---------------- host launcher (dual-stream: CSR build overlaps GEMM1) ----------------
extern "C" void kernel_launch(void* const* d_in, const int* in_sizes, int n_in,
                              void* d_out, int out_size) {
    const float* x   = (const float*)d_in[0];
    const int*   ei  = (const int*)d_in[1];
    const int*   bat = (const int*)d_in[2];
    const float* W1  = (const float*)d_in[3];
    const float* as1 = (const float*)d_in[4];
    const float* ad1 = (const float*)d_in[5];
    const float* b1  = (const float*)d_in[6];
    const float* g1  = (const float*)d_in[7];
    const float* be1 = (const float*)d_in[8];
    const float* W2  = (const float*)d_in[9];
    const float* as2 = (const float*)d_in[10];
    const float* ad2 = (const float*)d_in[11];
    const float* b2  = (const float*)d_in[12];
    const float* g2  = (const float*)d_in[13];
    const float* be2 = (const float*)d_in[14];
    const float* lw1 = (const float*)d_in[15];
    const float* lb1 = (const float*)d_in[16];
    const float* lw2 = (const float*)d_in[17];
    const float* lb2 = (const float*)d_in[18];
    float* out = (float*)d_out;

    // lazy one-time resources (no device memory; created on the uncaptured
    // correctness call, reused during graph capture)
    static bool inited = false;
    static cudaStream_t s2;
    static cudaEvent_t ev_prep, ev_csr;
    if (!inited) {
        cudaStreamCreateWithFlags(&s2, cudaStreamNonBlocking);
        cudaEventCreateWithFlags(&ev_prep, cudaEventDisableTiming);
        cudaEventCreateWithFlags(&ev_csr, cudaEventDisableTiming);
        cudaFuncSetAttribute(k_gemm_att, cudaFuncAttributeMaxDynamicSharedMemorySize, SMEM_TOT);
        inited = true;
    }

    __nv_bfloat162 *hb;
    __nv_bfloat16 *ahi, *w1h, *w1l, *w2h, *w2l;
    cudaGetSymbolAddress((void**)&hb, g_hb);
    cudaGetSymbolAddress((void**)&ahi, g_ahi);
    cudaGetSymbolAddress((void**)&w1h, g_w1hi);
    cudaGetSymbolAddress((void**)&w1l, g_w1lo);
    cudaGetSymbolAddress((void**)&w2h, g_w2hi);
    cudaGetSymbolAddress((void**)&w2l, g_w2lo);

    dim3 gemm_grid((NN + 127) / 128, 2);
    int agg_blocks = (NN + 7) / 8;

    // main stream: splits + prep, then GEMM1
    k_split_x<<<NN * DD / 1024, 256>>>((const float4*)x, (__nv_bfloat162*)ahi);
    k_prep<<<512, 256>>>(bat, W1, W2);
    cudaEventRecord(ev_prep, 0);

    // side stream: CSR build (needs g_deg zeroed by prep)
    cudaStreamWaitEvent(s2, ev_prep, 0);
    k_hist_edges<<<(ETOT + 255) / 256, 256, 0, s2>>>(ei);
    k_scan_part<<<SNB, 512, 0, s2>>>();
    k_scan_boff<<<1, 128, 0, s2>>>();
    k_scan_add<<<(NN + 255) / 256, 256, 0, s2>>>();
    k_scatter_edges<<<(ETOT + 255) / 256, 256, 0, s2>>>(ei);
    cudaEventRecord(ev_csr, s2);

    // main stream: GEMM1 runs concurrently with the CSR chain
    k_gemm_att<<<gemm_grid, 256, SMEM_TOT>>>(ahi, w1h, w1l, hb, as1, ad1, NN);

    // rejoin: agg1 needs both GEMM1 (main) and CSR (side)
    cudaStreamWaitEvent(0, ev_csr, 0);
    k_agg_ln<<<agg_blocks, 256>>>(hb, b1, g1, be1, (__nv_bfloat162*)ahi);

    // ---- layer 2 ----
    k_gemm_att<<<gemm_grid, 256, SMEM_TOT>>>(ahi, w2h, w2l, hb, as2, ad2, NN);
    k_agg_ln<<<agg_blocks, 256>>>(hb, b2, g2, be2, (__nv_bfloat162*)ahi);

    // ---- pool + MLP ----
    k_pool<<<dim3(GG, 8), 128>>>((const __nv_bfloat162*)ahi);
    k_mlp<<<GG, 64>>>(lw1, lb1, lw2, lb2, out);
}

// round 17
// speedup vs baseline: 2.0183x; 1.0273x over previous
#include <cuda_runtime.h>
#include <cuda_bf16.h>
#include <cstdint>
#include <math.h>

#define NN 50000
#define EE 400000
#define ETOT (EE + NN)
#define DD 256
#define HEADS 4
#define HIDC 64
#define GG 64
#define NEG_SLOPE 0.2f

// ---------------- static device scratch ----------------
__device__ __nv_bfloat162 g_hb[NN * 128];
__device__ __nv_bfloat16 g_ahi[NN * DD];
__device__ __nv_bfloat16 g_w1hi[DD * DD], g_w1lo[DD * DD];
__device__ __nv_bfloat16 g_w2hi[DD * DD], g_w2lo[DD * DD];
__device__ float g_asrc[NN * HEADS];
__device__ float g_adst[NN * HEADS];
__device__ int   g_deg[NN];
__device__ int   g_rowptr[NN + 1];
__device__ int   g_cursor[NN];
__device__ int   g_csrsrc[ETOT];
__device__ int   g_gstart[GG + 1];
__device__ float g_pooled[GG * DD];
#define SNB 98
__device__ int   g_bsum[SNB];
__device__ int   g_boff[SNB];

// ---------------- helpers ----------------
__device__ __forceinline__ uint32_t su32(const void* p) {
    uint32_t a;
    asm("{ .reg .u64 t; cvta.to.shared.u64 t, %1; cvt.u32.u64 %0, t; }" : "=r"(a) : "l"(p));
    return a;
}
__device__ __forceinline__ uint32_t swz(uint32_t off) {
    return off ^ ((off >> 3) & 0x70);
}
__device__ __forceinline__ void ldsm_x4(uint32_t* r, uint32_t addr) {
    asm volatile("ldmatrix.sync.aligned.m8n8.x4.shared.b16 {%0,%1,%2,%3}, [%4];"
                 : "=r"(r[0]), "=r"(r[1]), "=r"(r[2]), "=r"(r[3]) : "r"(addr));
}
__device__ __forceinline__ void mma_bf16(float* c, const uint32_t* a, const uint32_t* b) {
    asm volatile("mma.sync.aligned.m16n8k16.row.col.f32.bf16.bf16.f32 "
                 "{%0,%1,%2,%3}, {%4,%5,%6,%7}, {%8,%9}, {%0,%1,%2,%3};"
                 : "+f"(c[0]), "+f"(c[1]), "+f"(c[2]), "+f"(c[3])
                 : "r"(a[0]), "r"(a[1]), "r"(a[2]), "r"(a[3]), "r"(b[0]), "r"(b[1]));
}
__device__ __forceinline__ void cp16(uint32_t dst, const void* src, uint32_t sz) {
    asm volatile("cp.async.cg.shared.global [%0], [%1], 16, %2;" :: "r"(dst), "l"(src), "r"(sz));
}
__device__ __forceinline__ void cp16f(uint32_t dst, const void* src) {
    asm volatile("cp.async.cg.shared.global [%0], [%1], 16;" :: "r"(dst), "l"(src));
}
#define CP_COMMIT() asm volatile("cp.async.commit_group;" ::: "memory")
#define CP_WAIT(n)  asm volatile("cp.async.wait_group %0;" :: "n"(n) : "memory")

// ---------------- tiny fork kernel (gives s2 a captured dependency source) ----------------
__global__ void k_fork() {}

// ---------------- fused prep: zero deg/pooled + graph bounds + W split ----------------
__global__ void k_prep(const int* __restrict__ batch,
                       const float* __restrict__ W1, const float* __restrict__ W2) {
    int i = blockIdx.x * blockDim.x + threadIdx.x;
    if (i < NN) {
        g_deg[i] = 0;
        int b = batch[i];
        int prev = (i == 0) ? -1 : batch[i - 1];
        for (int g = prev + 1; g <= b; g++) g_gstart[g] = i;
        if (i == NN - 1)
            for (int g = b + 1; g <= GG; g++) g_gstart[g] = NN;
    }
    if (i < GG * DD) g_pooled[i] = 0.f;
    {
        int which = i >> 16;
        int j = i & 65535;
        int n = j >> 8, k = j & 255;
        const float* W = which ? W2 : W1;
        float v = W[k * 256 + n];
        __nv_bfloat16 h = __float2bfloat16(v);
        float r = v - __bfloat162float(h);
        if (which) { g_w2hi[j] = h; g_w2lo[j] = __float2bfloat16(r); }
        else       { g_w1hi[j] = h; g_w1lo[j] = __float2bfloat16(r); }
    }
}

__global__ void k_hist_edges(const int* __restrict__ ei) {
    int i = blockIdx.x * blockDim.x + threadIdx.x;
    if (i < EE) atomicAdd(&g_deg[ei[EE + i]], 1);
    else if (i < ETOT) atomicAdd(&g_deg[i - EE], 1);
}
__global__ void k_scan_part() {
    __shared__ int sh[512];
    int i = blockIdx.x * 512 + threadIdx.x;
    int v = (i < NN) ? g_deg[i] : 0;
    sh[threadIdx.x] = v;
    __syncthreads();
    #pragma unroll
    for (int off = 1; off < 512; off <<= 1) {
        int t = (threadIdx.x >= off) ? sh[threadIdx.x - off] : 0;
        __syncthreads();
        sh[threadIdx.x] += t;
        __syncthreads();
    }
    if (i < NN) g_rowptr[i] = sh[threadIdx.x] - v;
    if (threadIdx.x == 511) g_bsum[blockIdx.x] = sh[511];
}
__global__ void k_scan_boff() {
    __shared__ int sh[128];
    int i = threadIdx.x;
    int v = (i < SNB) ? g_bsum[i] : 0;
    sh[i] = v;
    __syncthreads();
    #pragma unroll
    for (int off = 1; off < 128; off <<= 1) {
        int t = (i >= off) ? sh[i - off] : 0;
        __syncthreads();
        sh[i] += t;
        __syncthreads();
    }
    if (i < SNB) g_boff[i] = sh[i] - v;
}
__global__ void k_scan_add() {
    int i = blockIdx.x * blockDim.x + threadIdx.x;
    if (i < NN) {
        int val = g_rowptr[i] + g_boff[i >> 9];
        g_rowptr[i] = val;
        g_cursor[i] = val;
    }
    if (i == 0) g_rowptr[NN] = ETOT;
}
__global__ void k_scatter_edges(const int* __restrict__ ei) {
    int i = blockIdx.x * blockDim.x + threadIdx.x;
    int src, dst;
    if (i < EE)        { src = ei[i]; dst = ei[EE + i]; }
    else if (i < ETOT) { src = i - EE; dst = i - EE; }
    else return;
    int pos = atomicAdd(&g_cursor[dst], 1);
    g_csrsrc[pos] = src;
}

// ---------------- fp32 -> bf16 ----------------
__global__ void k_split_x(const float4* __restrict__ x4, __nv_bfloat162* __restrict__ hi2) {
    int i = blockIdx.x * 256 + threadIdx.x;
    float4 v = x4[i];
    hi2[2 * i]     = __floats2bfloat162_rn(v.x, v.y);
    hi2[2 * i + 1] = __floats2bfloat162_rn(v.z, v.w);
}

// ---------------- GEMM (256 thr, CTA 128x128, 2 CTA/SM): h = A @ [Whi+Wlo]^T ----------------
#define STG   49152
#define OA_HI 0
#define OB_HI 16384
#define OB_LO 32768
#define SMEM_TOT (2 * STG)

__global__ void __launch_bounds__(256, 2) k_gemm_att(
    const __nv_bfloat16* __restrict__ Ahi,
    const __nv_bfloat16* __restrict__ Bhi, const __nv_bfloat16* __restrict__ Blo,
    __nv_bfloat162* __restrict__ Hout,
    const float* __restrict__ as, const float* __restrict__ ad,
    int M)
{
    extern __shared__ char smem[];
    uint32_t sb = su32(smem);
    const int tid = threadIdx.x, wid = tid >> 5, lane = tid & 31;
    const int row0 = blockIdx.x * 128;
    const int col0 = blockIdx.y * 128;
    const int wm = wid & 3;
    const int wn = wid >> 2;

    float acc[2][8][4];
    #pragma unroll
    for (int a = 0; a < 2; a++)
        #pragma unroll
        for (int b = 0; b < 8; b++)
            #pragma unroll
            for (int q = 0; q < 4; q++) acc[a][b][q] = 0.f;

    auto load_chunk = [&](int c, int stage) {
        uint32_t base = sb + stage * STG;
        #pragma unroll
        for (int it = 0; it < 4; it++) {
            int u = tid + it * 256;
            int r = u >> 3, j = u & 7;
            uint32_t sw = swz(r * 128 + j * 16);
            int m = row0 + r;
            int mc = m < M ? m : (M - 1);
            uint32_t sz = (m < M) ? 16u : 0u;
            size_t gi = (size_t)mc * 256 + c * 64 + j * 8;
            cp16(base + OA_HI + sw, Ahi + gi, sz);
        }
        #pragma unroll
        for (int it = 0; it < 4; it++) {
            int u = tid + it * 256;
            int r = u >> 3, j = u & 7;
            uint32_t sw = swz(r * 128 + j * 16);
            size_t gi = (size_t)(col0 + r) * 256 + c * 64 + j * 8;
            cp16f(base + OB_HI + sw, Bhi + gi);
            cp16f(base + OB_LO + sw, Blo + gi);
        }
    };

    load_chunk(0, 0);
    CP_COMMIT();

    const int lrow = lane & 15;
    const int lcol = (lane >> 4) * 8;
    const int cb = wn * 64;

    for (int c = 0; c < 4; c++) {
        int stage = c & 1;
        if (c < 3) { load_chunk(c + 1, stage ^ 1); CP_COMMIT(); CP_WAIT(1); }
        else       { CP_WAIT(0); }
        __syncthreads();
        uint32_t base = sb + stage * STG;

        #pragma unroll
        for (int kk = 0; kk < 4; kk++) {
            uint32_t ah[2][4];
            #pragma unroll
            for (int mt = 0; mt < 2; mt++) {
                uint32_t off = swz((wm * 32 + mt * 16 + lrow) * 128 + (kk * 16 + lcol) * 2);
                ldsm_x4(ah[mt], base + OA_HI + off);
            }
            #pragma unroll
            for (int ntp = 0; ntp < 4; ntp++) {
                int q = lane >> 3;
                int nrow = cb + ntp * 16 + (q >> 1) * 8 + (lane & 7);
                int kcol = kk * 16 + (q & 1) * 8;
                uint32_t boff = swz(nrow * 128 + kcol * 2);
                uint32_t bh[4], bl[4];
                ldsm_x4(bh, base + OB_HI + boff);
                ldsm_x4(bl, base + OB_LO + boff);
                #pragma unroll
                for (int sub = 0; sub < 2; sub++) {
                    int nt = ntp * 2 + sub;
                    #pragma unroll
                    for (int mt = 0; mt < 2; mt++) {
                        mma_bf16(acc[mt][nt], ah[mt], bh + sub * 2);
                        mma_bf16(acc[mt][nt], ah[mt], bl + sub * 2);
                    }
                }
            }
        }
        __syncthreads();
    }

    const int head = blockIdx.y * 2 + wn;
    float sa[4], sd[4];
    #pragma unroll
    for (int i = 0; i < 4; i++) { sa[i] = 0.f; sd[i] = 0.f; }

    #pragma unroll
    for (int nt = 0; nt < 8; nt++) {
        int c0 = col0 + cb + nt * 8 + (lane & 3) * 2;
        float w0 = __ldg(as + c0), w1 = __ldg(as + c0 + 1);
        float v0 = __ldg(ad + c0), v1 = __ldg(ad + c0 + 1);
        #pragma unroll
        for (int mt = 0; mt < 2; mt++) {
            sa[mt * 2 + 0] += acc[mt][nt][0] * w0 + acc[mt][nt][1] * w1;
            sa[mt * 2 + 1] += acc[mt][nt][2] * w0 + acc[mt][nt][3] * w1;
            sd[mt * 2 + 0] += acc[mt][nt][0] * v0 + acc[mt][nt][1] * v1;
            sd[mt * 2 + 1] += acc[mt][nt][2] * v0 + acc[mt][nt][3] * v1;
        }
    }
    #pragma unroll
    for (int i = 0; i < 4; i++) {
        sa[i] += __shfl_xor_sync(0xffffffff, sa[i], 1);
        sa[i] += __shfl_xor_sync(0xffffffff, sa[i], 2);
        sd[i] += __shfl_xor_sync(0xffffffff, sd[i], 1);
        sd[i] += __shfl_xor_sync(0xffffffff, sd[i], 2);
    }
    if ((lane & 3) == 0) {
        #pragma unroll
        for (int mt = 0; mt < 2; mt++)
            #pragma unroll
            for (int rh = 0; rh < 2; rh++) {
                int r = row0 + wm * 32 + mt * 16 + (lane >> 2) + rh * 8;
                if (r < M) {
                    g_asrc[r * 4 + head] = sa[mt * 2 + rh];
                    g_adst[r * 4 + head] = sd[mt * 2 + rh];
                }
            }
    }

    #pragma unroll
    for (int mt = 0; mt < 2; mt++) {
        int r0 = row0 + wm * 32 + mt * 16 + (lane >> 2);
        int r1 = r0 + 8;
        #pragma unroll
        for (int nt = 0; nt < 8; nt++) {
            int cc2 = (col0 >> 1) + (cb >> 1) + nt * 4 + (lane & 3);
            if (r0 < M) Hout[(size_t)r0 * 128 + cc2] = __floats2bfloat162_rn(acc[mt][nt][0], acc[mt][nt][1]);
            if (r1 < M) Hout[(size_t)r1 * 128 + cc2] = __floats2bfloat162_rn(acc[mt][nt][2], acc[mt][nt][3]);
        }
    }
}

// ---------------- warp-per-node GAT aggregation + bias + warp LN + ReLU ----------------
// ohi != nullptr : write bf16 features (layer 1)
// ohi == nullptr : accumulate mean-pool partials into g_pooled (layer 2, fused pool)
__global__ void __launch_bounds__(256) k_agg_ln(
    const __nv_bfloat162* __restrict__ hb, const float* __restrict__ bias,
    const float* __restrict__ gamma, const float* __restrict__ beta,
    __nv_bfloat162* __restrict__ ohi, const int* __restrict__ batch)
{
    __shared__ float sp[8][DD];
    int wid = threadIdx.x >> 5, lane = threadIdx.x & 31;
    int n = blockIdx.x * 8 + wid;     // grid*8 == NN exactly
    int beg = g_rowptr[n], end = g_rowptr[n + 1];
    int head = lane >> 3;
    float adh = __ldg(g_adst + 4 * n + head);

    float acc[8];
    #pragma unroll
    for (int j = 0; j < 8; j++) acc[j] = 0.f;
    float den = 0.f;

    const int4* hrow = (const int4*)hb;

    int sC;
    float avA, avB;
    int4 vA, vB;
    {
        int s0 = __ldg(g_csrsrc + beg);
        avA = __ldg(g_asrc + 4 * s0 + head);
        vA  = __ldg(hrow + (size_t)s0 * 32 + lane);
        if (beg + 1 < end) {
            int s1 = __ldg(g_csrsrc + beg + 1);
            avB = __ldg(g_asrc + 4 * s1 + head);
            vB  = __ldg(hrow + (size_t)s1 * 32 + lane);
        }
        sC = (beg + 2 < end) ? __ldg(g_csrsrc + beg + 2) : 0;
    }

    for (int k = beg; k < end; k++) {
        float avC; int4 vC;
        if (k + 2 < end) {
            avC = __ldg(g_asrc + 4 * sC + head);
            vC  = __ldg(hrow + (size_t)sC * 32 + lane);
        }
        int sD = (k + 3 < end) ? __ldg(g_csrsrc + k + 3) : 0;

        float e = avA + adh;
        e = (e > 0.f) ? e : NEG_SLOPE * e;
        float w = __expf(e);
        den += w;
        const __nv_bfloat162* pv = (const __nv_bfloat162*)&vA;
        #pragma unroll
        for (int j = 0; j < 4; j++) {
            float2 f = __bfloat1622float2(pv[j]);
            acc[2 * j]     = fmaf(w, f.x, acc[2 * j]);
            acc[2 * j + 1] = fmaf(w, f.y, acc[2 * j + 1]);
        }
        avA = avB; vA = vB;
        avB = avC; vB = vC;
        sC = sD;
    }

    float inv = 1.0f / den;
    int c0 = lane * 8;
    float4 b0 = __ldg((const float4*)(bias + c0));
    float4 b1 = __ldg((const float4*)(bias + c0 + 4));
    float m[8];
    m[0] = acc[0] * inv + b0.x; m[1] = acc[1] * inv + b0.y;
    m[2] = acc[2] * inv + b0.z; m[3] = acc[3] * inv + b0.w;
    m[4] = acc[4] * inv + b1.x; m[5] = acc[5] * inv + b1.y;
    m[6] = acc[6] * inv + b1.z; m[7] = acc[7] * inv + b1.w;

    float sum = ((m[0] + m[1]) + (m[2] + m[3])) + ((m[4] + m[5]) + (m[6] + m[7]));
    #pragma unroll
    for (int off = 16; off > 0; off >>= 1) sum += __shfl_xor_sync(0xffffffff, sum, off);
    float mu = sum * (1.0f / 256.0f);
    float d[8];
    float q = 0.f;
    #pragma unroll
    for (int j = 0; j < 8; j++) { d[j] = m[j] - mu; q = fmaf(d[j], d[j], q); }
    #pragma unroll
    for (int off = 16; off > 0; off >>= 1) q += __shfl_xor_sync(0xffffffff, q, off);
    float invs = rsqrtf(q * (1.0f / 256.0f) + 1e-5f);

    float4 g0 = __ldg((const float4*)(gamma + c0));
    float4 g1 = __ldg((const float4*)(gamma + c0 + 4));
    float4 t0 = __ldg((const float4*)(beta + c0));
    float4 t1 = __ldg((const float4*)(beta + c0 + 4));
    float y[8];
    y[0] = fmaxf(d[0] * invs * g0.x + t0.x, 0.f);
    y[1] = fmaxf(d[1] * invs * g0.y + t0.y, 0.f);
    y[2] = fmaxf(d[2] * invs * g0.z + t0.z, 0.f);
    y[3] = fmaxf(d[3] * invs * g0.w + t0.w, 0.f);
    y[4] = fmaxf(d[4] * invs * g1.x + t1.x, 0.f);
    y[5] = fmaxf(d[5] * invs * g1.y + t1.y, 0.f);
    y[6] = fmaxf(d[6] * invs * g1.z + t1.z, 0.f);
    y[7] = fmaxf(d[7] * invs * g1.w + t1.w, 0.f);

    if (ohi) {
        __nv_bfloat162 p0 = __floats2bfloat162_rn(y[0], y[1]);
        __nv_bfloat162 p1 = __floats2bfloat162_rn(y[2], y[3]);
        __nv_bfloat162 p2 = __floats2bfloat162_rn(y[4], y[5]);
        __nv_bfloat162 p3 = __floats2bfloat162_rn(y[6], y[7]);
        int4 packed;
        packed.x = *(const int*)&p0; packed.y = *(const int*)&p1;
        packed.z = *(const int*)&p2; packed.w = *(const int*)&p3;
        ((int4*)ohi)[(size_t)n * 32 + lane] = packed;
        return;
    }

    // ---- fused mean-pool accumulation ----
    int gFirst = __ldg(batch + blockIdx.x * 8);
    int gLast  = __ldg(batch + blockIdx.x * 8 + 7);
    if (gFirst == gLast) {
        #pragma unroll
        for (int j = 0; j < 8; j++) sp[wid][c0 + j] = y[j];
        __syncthreads();
        int t = threadIdx.x;
        float s = ((sp[0][t] + sp[1][t]) + (sp[2][t] + sp[3][t]))
                + ((sp[4][t] + sp[5][t]) + (sp[6][t] + sp[7][t]));
        atomicAdd(&g_pooled[gFirst * DD + t], s);
    } else {
        int g = __ldg(batch + n);
        #pragma unroll
        for (int j = 0; j < 8; j++)
            atomicAdd(&g_pooled[g * DD + c0 + j], y[j]);
    }
}

// ---------------- final MLP (normalization folded in) ----------------
__global__ void k_mlp(const float* __restrict__ lw1, const float* __restrict__ lb1,
                      const float* __restrict__ lw2, const float* __restrict__ lb2,
                      float* __restrict__ out) {
    __shared__ float p[DD];
    __shared__ float hid[HIDC];
    int g = blockIdx.x, tid = threadIdx.x;
    int cnt = g_gstart[g + 1] - g_gstart[g];
    float invc = 1.0f / (float)max(cnt, 1);
    for (int i = tid; i < DD; i += 64) p[i] = g_pooled[g * DD + i] * invc;
    __syncthreads();
    float s = lb1[tid];
    #pragma unroll 8
    for (int k = 0; k < DD; k++) s = fmaf(p[k], lw1[k * HIDC + tid], s);
    hid[tid] = fmaxf(s, 0.f);
    __syncthreads();
    if (tid < 2) {
        float o = lb2[tid];
        #pragma unroll
        for (int k = 0; k < HIDC; k++) o = fmaf(hid[k], lw2[k * 2 + tid], o);
        out[g * 2 + tid] = o;
    }
}

// ---------------- host launcher (dual-stream, capture-safe fork) ----------------
extern "C" void kernel_launch(void* const* d_in, const int* in_sizes, int n_in,
                              void* d_out, int out_size) {
    const float* x   = (const float*)d_in[0];
    const int*   ei  = (const int*)d_in[1];
    const int*   bat = (const int*)d_in[2];
    const float* W1  = (const float*)d_in[3];
    const float* as1 = (const float*)d_in[4];
    const float* ad1 = (const float*)d_in[5];
    const float* b1  = (const float*)d_in[6];
    const float* g1  = (const float*)d_in[7];
    const float* be1 = (const float*)d_in[8];
    const float* W2  = (const float*)d_in[9];
    const float* as2 = (const float*)d_in[10];
    const float* ad2 = (const float*)d_in[11];
    const float* b2  = (const float*)d_in[12];
    const float* g2  = (const float*)d_in[13];
    const float* be2 = (const float*)d_in[14];
    const float* lw1 = (const float*)d_in[15];
    const float* lb1 = (const float*)d_in[16];
    const float* lw2 = (const float*)d_in[17];
    const float* lb2 = (const float*)d_in[18];
    float* out = (float*)d_out;

    static bool inited = false;
    static cudaStream_t s2;
    static cudaEvent_t ev_fork, ev_prep, ev_csr, ev_sx;
    if (!inited) {
        cudaStreamCreateWithFlags(&s2, cudaStreamNonBlocking);
        cudaEventCreateWithFlags(&ev_fork, cudaEventDisableTiming);
        cudaEventCreateWithFlags(&ev_prep, cudaEventDisableTiming);
        cudaEventCreateWithFlags(&ev_csr, cudaEventDisableTiming);
        cudaEventCreateWithFlags(&ev_sx, cudaEventDisableTiming);
        cudaFuncSetAttribute(k_gemm_att, cudaFuncAttributeMaxDynamicSharedMemorySize, SMEM_TOT);
        inited = true;
    }

    __nv_bfloat162 *hb;
    __nv_bfloat16 *ahi, *w1h, *w1l, *w2h, *w2l;
    cudaGetSymbolAddress((void**)&hb, g_hb);
    cudaGetSymbolAddress((void**)&ahi, g_ahi);
    cudaGetSymbolAddress((void**)&w1h, g_w1hi);
    cudaGetSymbolAddress((void**)&w1l, g_w1lo);
    cudaGetSymbolAddress((void**)&w2h, g_w2hi);
    cudaGetSymbolAddress((void**)&w2l, g_w2lo);

    dim3 gemm_grid((NN + 127) / 128, 2);
    int agg_blocks = NN / 8;

    // fork point on the origin stream (captured), then s2 joins the capture
    k_fork<<<1, 32>>>();
    cudaEventRecord(ev_fork, 0);
    cudaStreamWaitEvent(s2, ev_fork, 0);

    // side stream: split_x (independent of prep)
    k_split_x<<<NN * DD / 1024, 256, 0, s2>>>((const float4*)x, (__nv_bfloat162*)ahi);
    cudaEventRecord(ev_sx, s2);

    // main stream: prep
    k_prep<<<512, 256>>>(bat, W1, W2);
    cudaEventRecord(ev_prep, 0);

    // side stream: CSR build (needs g_deg zeroed by prep)
    cudaStreamWaitEvent(s2, ev_prep, 0);
    k_hist_edges<<<(ETOT + 255) / 256, 256, 0, s2>>>(ei);
    k_scan_part<<<SNB, 512, 0, s2>>>();
    k_scan_boff<<<1, 128, 0, s2>>>();
    k_scan_add<<<(NN + 255) / 256, 256, 0, s2>>>();
    k_scatter_edges<<<(ETOT + 255) / 256, 256, 0, s2>>>(ei);
    cudaEventRecord(ev_csr, s2);

    // main stream: GEMM1 (needs split_x + prep), concurrent with CSR chain
    cudaStreamWaitEvent(0, ev_sx, 0);
    k_gemm_att<<<gemm_grid, 256, SMEM_TOT>>>(ahi, w1h, w1l, hb, as1, ad1, NN);

    // rejoin: agg1 needs GEMM1 (main) + CSR (side)
    cudaStreamWaitEvent(0, ev_csr, 0);
    k_agg_ln<<<agg_blocks, 256>>>(hb, b1, g1, be1, (__nv_bfloat162*)ahi, bat);

    // ---- layer 2 (agg2 fuses mean-pool accumulation) ----
    k_gemm_att<<<gemm_grid, 256, SMEM_TOT>>>(ahi, w2h, w2l, hb, as2, ad2, NN);
    k_agg_ln<<<agg_blocks, 256>>>(hb, b2, g2, be2, nullptr, bat);

    // ---- MLP ----
    k_mlp<<<GG, 64>>>(lw1, lb1, lw2, lb2, out);
}